// round 3
// baseline (speedup 1.0000x reference)
#include <cuda_runtime.h>
#include <math.h>

// Problem constants
// B=16, C=512, NH=8, DK=64, H=W=32, N=H*W=1024

// ---------------------------------------------------------------------------
// Device scratch (allocation-free rule: __device__ globals)
// q,k,v stored d-major: [b][h][d][n]  (n contiguous)
// att stored [b][c][n] with c = h*64 + d (matches the reference's head-outer
// channel order feeding w_o)
// lh/lw: [b][h][n][64] (r = 0..62 valid, slot 63 unused padding)
// ---------------------------------------------------------------------------
__device__ float g_q  [16 * 8 * 64 * 1024];
__device__ float g_k  [16 * 8 * 64 * 1024];
__device__ float g_v  [16 * 8 * 64 * 1024];
__device__ float g_att[16 * 512 * 1024];
__device__ float g_lh [16 * 8 * 1024 * 64];
__device__ float g_lw [16 * 8 * 1024 * 64];

// ---------------------------------------------------------------------------
// SGEMM: out(512 x 1024) = A(512x512) @ X_b(512x1024) per batch.
// BM=BN=128, BK=16, 256 threads, 8x8 micro-tile, float4 smem paths.
// MODE 0: scatter into d-major qkv layout  out[((b*8+h)*64+d)*1024+n], h=o&7, d=o>>3
// MODE 1: plain [b][o][n] + bias (final output projection)
// ---------------------------------------------------------------------------
template <int MODE>
__global__ __launch_bounds__(256)
void gemm512_kernel(const float* __restrict__ A, const float* __restrict__ X,
                    float* __restrict__ out, const float* __restrict__ bias)
{
    const int b  = blockIdx.z;
    const int bm = blockIdx.y * 128;
    const int bn = blockIdx.x * 128;
    const float* __restrict__ Xb = X + b * 512 * 1024;

    __shared__ float As[16][132];   // [c][o], padded: 2-way max on store, bcast-free read
    __shared__ float Bs[16][128];   // [c][n]

    const int tid = threadIdx.x;
    const int tr  = tid >> 4;       // 0..15 -> rows tr*8
    const int tc  = tid & 15;       // 0..15 -> cols tc*8

    float acc[8][8];
#pragma unroll
    for (int i = 0; i < 8; i++)
#pragma unroll
        for (int j = 0; j < 8; j++) acc[i][j] = 0.f;

    for (int k0 = 0; k0 < 512; k0 += 16) {
        // A tile 128x16, transpose into smem
#pragma unroll
        for (int l = 0; l < 2; l++) {
            int flat = tid + l * 256;          // float4 id 0..511
            int row  = flat >> 2;              // 0..127 (o)
            int c4   = (flat & 3) * 4;         // 0,4,8,12 (c)
            float4 av = *reinterpret_cast<const float4*>(&A[(bm + row) * 512 + k0 + c4]);
            As[c4 + 0][row] = av.x;
            As[c4 + 1][row] = av.y;
            As[c4 + 2][row] = av.z;
            As[c4 + 3][row] = av.w;
        }
        // B tile 16x128, direct
#pragma unroll
        for (int l = 0; l < 2; l++) {
            int flat = tid + l * 256;
            int row  = flat >> 5;              // 0..15 (c)
            int col  = (flat & 31) * 4;        // 0..124 (n)
            *reinterpret_cast<float4*>(&Bs[row][col]) =
                *reinterpret_cast<const float4*>(&Xb[(k0 + row) * 1024 + bn + col]);
        }
        __syncthreads();

#pragma unroll
        for (int kk = 0; kk < 16; kk++) {
            float a[8], bb[8];
            *reinterpret_cast<float4*>(&a[0]) = *reinterpret_cast<float4*>(&As[kk][tr * 8]);
            *reinterpret_cast<float4*>(&a[4]) = *reinterpret_cast<float4*>(&As[kk][tr * 8 + 4]);
            *reinterpret_cast<float4*>(&bb[0]) = *reinterpret_cast<float4*>(&Bs[kk][tc * 8]);
            *reinterpret_cast<float4*>(&bb[4]) = *reinterpret_cast<float4*>(&Bs[kk][tc * 8 + 4]);
#pragma unroll
            for (int i = 0; i < 8; i++)
#pragma unroll
                for (int j = 0; j < 8; j++)
                    acc[i][j] += a[i] * bb[j];
        }
        __syncthreads();
    }

    if (MODE == 0) {
        // d-major scatter: 8 consecutive o = one d, all 8 heads -> per-(i) the
        // half-warp writes 128 consecutive n floats: coalesced.
#pragma unroll
        for (int i = 0; i < 8; i++) {
            int o = bm + tr * 8 + i;
            int h = o & 7, d = o >> 3;
            float* dst = out + (((b * 8 + h) * 64 + d) * 1024 + bn + tc * 8);
#pragma unroll
            for (int j = 0; j < 8; j++) dst[j] = acc[i][j];
        }
    } else {
#pragma unroll
        for (int i = 0; i < 8; i++) {
            int o = bm + tr * 8 + i;
            float bo = bias[o];
            float* dst = out + ((b * 512 + o) * 1024 + bn + tc * 8);
#pragma unroll
            for (int j = 0; j < 8; j++) dst[j] = acc[i][j] + bo;
        }
    }
}

// ---------------------------------------------------------------------------
// Per-query rel-pos tables: lh[n][r] = sum_d q[n][d]*rel_h[r][d] (r<63), same lw.
// One block = one (b,h) x 64-query chunk. 256 threads: i = tid%64, r-group = tid/64.
// ---------------------------------------------------------------------------
__global__ __launch_bounds__(256)
void bias_tables_kernel(const float* __restrict__ q,
                        const float* __restrict__ rel_h, const float* __restrict__ rel_w,
                        float* __restrict__ lh, float* __restrict__ lw)
{
    const int blk = blockIdx.x;          // 0..2047
    const int bh  = blk >> 4;            // 0..127
    const int n0  = (blk & 15) * 64;
    const float* __restrict__ qb = q + bh * 64 * 1024;   // [d][n]

    __shared__ float Qs[64][65];         // [i][d], conflict-free both directions
    __shared__ float Rh[63][64];
    __shared__ float Rw[63][64];

    const int tid = threadIdx.x;

#pragma unroll
    for (int l = 0; l < 16; l++) {       // 4096 scalar elems
        int flat = tid + l * 256;
        int d = flat >> 6, i = flat & 63;
        Qs[i][d] = qb[d * 1024 + n0 + i];
    }
#pragma unroll
    for (int l = 0; l < 16; l++) {
        int flat = tid + l * 256;
        if (flat < 63 * 64) {
            (&Rh[0][0])[flat] = rel_h[flat];
            (&Rw[0][0])[flat] = rel_w[flat];
        }
    }
    __syncthreads();

    const int i  = tid & 63;
    const int r0 = (tid >> 6) * 16;      // 0,16,32,48

    float acch[16], accw[16];
#pragma unroll
    for (int t = 0; t < 16; t++) { acch[t] = 0.f; accw[t] = 0.f; }

    for (int d = 0; d < 64; d++) {
        float qv = Qs[i][d];
#pragma unroll
        for (int t = 0; t < 16; t++) {
            int r = r0 + t;
            if (r < 63) {
                acch[t] += qv * Rh[r][d];
                accw[t] += qv * Rw[r][d];
            }
        }
    }

    const int base = (bh * 1024 + n0 + i) * 64;
#pragma unroll
    for (int t = 0; t < 16; t++) {
        int r = r0 + t;
        if (r < 63) {
            lh[base + r] = acch[t];
            lw[base + r] = accw[t];
        }
    }
}

// ---------------------------------------------------------------------------
// Flash attention with content-aware rel-pos bias.
// Per block: one (b,h), one 64-query tile. 128 threads (ty=tid/16 rows ty*8,
// tx=tid%15 cols tx*4). Online softmax over 16 key tiles of 64.
// s = (q.k + lh[i_k - x + 31] + lw[j_k - y + 31]) / 8
// Output staged through smem so global writes are coalesced rows of att[c][n].
// ---------------------------------------------------------------------------
struct AttnSmem {
    float Qs[64][65];   // [i][d]
    float Ks[64][68];   // [d][j]  (float4 along j)
    float Vs[64][65];   // [j][d]
    float Ps[64][68];   // [r][j]  (float4 writes along j)
    float Lh[64][64];   // [i][r]
    float Lw[64][64];
};

__global__ __launch_bounds__(128)
void attn_kernel(const float* __restrict__ q, const float* __restrict__ k,
                 const float* __restrict__ v,
                 const float* __restrict__ lh, const float* __restrict__ lw,
                 float* __restrict__ att)
{
    extern __shared__ unsigned char smem_raw[];
    AttnSmem& sm = *reinterpret_cast<AttnSmem*>(smem_raw);

    const int bh = blockIdx.y;           // 0..127
    const int b  = bh >> 3, h = bh & 7;
    const int q0 = blockIdx.x * 64;

    const float* __restrict__ qb = q + bh * 64 * 1024;
    const float* __restrict__ kb = k + bh * 64 * 1024;
    const float* __restrict__ vb = v + bh * 64 * 1024;

    const int tid = threadIdx.x;         // 128
    const int ty  = tid >> 4;            // 0..7 -> rows ty*8
    const int tx  = tid & 15;            // 0..15 -> cols tx*4

    // Load Q (transposed to [i][d]) and bias tables
#pragma unroll
    for (int l = 0; l < 32; l++) {
        int flat = tid + l * 128;
        int d = flat >> 6, i = flat & 63;
        sm.Qs[i][d] = qb[d * 1024 + q0 + i];
    }
#pragma unroll
    for (int l = 0; l < 32; l++) {
        int flat = tid + l * 128;
        int i = flat >> 6, r = flat & 63;
        int gidx = (bh * 1024 + q0 + i) * 64 + r;
        sm.Lh[i][r] = lh[gidx];
        sm.Lw[i][r] = lw[gidx];
    }

    float m[8], lsum[8], o[8][4];
#pragma unroll
    for (int rr = 0; rr < 8; rr++) {
        m[rr] = -1e30f; lsum[rr] = 0.f;
#pragma unroll
        for (int cc = 0; cc < 4; cc++) o[rr][cc] = 0.f;
    }

    int xr[8], yr[8];
#pragma unroll
    for (int rr = 0; rr < 8; rr++) {
        int nq = q0 + ty * 8 + rr;
        xr[rr] = nq >> 5;
        yr[rr] = nq & 31;
    }

    __syncthreads();

    for (int kt = 0; kt < 16; kt++) {
        // K tile [d][j]: natural layout, float4
#pragma unroll
        for (int l = 0; l < 8; l++) {
            int flat = tid + l * 128;    // float4 id 0..1023
            int d = flat >> 4, j4 = (flat & 15) * 4;
            *reinterpret_cast<float4*>(&sm.Ks[d][j4]) =
                *reinterpret_cast<const float4*>(&kb[d * 1024 + kt * 64 + j4]);
        }
        // V tile transposed to [j][d] (scalar, conflict-free via 65-pad)
#pragma unroll
        for (int l = 0; l < 32; l++) {
            int flat = tid + l * 128;
            int d = flat >> 6, j = flat & 63;
            sm.Vs[j][d] = vb[d * 1024 + kt * 64 + j];
        }
        __syncthreads();

        // S = Q @ K^T  (8x4 per thread)
        float s[8][4];
#pragma unroll
        for (int rr = 0; rr < 8; rr++)
#pragma unroll
            for (int cc = 0; cc < 4; cc++) s[rr][cc] = 0.f;

#pragma unroll 8
        for (int kk = 0; kk < 64; kk++) {
            float a[8];
#pragma unroll
            for (int rr = 0; rr < 8; rr++) a[rr] = sm.Qs[ty * 8 + rr][kk];
            float4 bv = *reinterpret_cast<float4*>(&sm.Ks[kk][tx * 4]);
#pragma unroll
            for (int rr = 0; rr < 8; rr++) {
                s[rr][0] += a[rr] * bv.x;
                s[rr][1] += a[rr] * bv.y;
                s[rr][2] += a[rr] * bv.z;
                s[rr][3] += a[rr] * bv.w;
            }
        }

        // bias + scale + online softmax
        const int kt2 = kt * 2;
#pragma unroll
        for (int rr = 0; rr < 8; rr++) {
            int row = ty * 8 + rr;
#pragma unroll
            for (int cc = 0; cc < 4; cc++) {
                int jj = tx * 4 + cc;
                float bias = sm.Lh[row][kt2 + (jj >> 5) - xr[rr] + 31]
                           + sm.Lw[row][(jj & 31) - yr[rr] + 31];
                s[rr][cc] = (s[rr][cc] + bias) * 0.125f;
            }
            float mloc = fmaxf(fmaxf(s[rr][0], s[rr][1]), fmaxf(s[rr][2], s[rr][3]));
#pragma unroll
            for (int off = 8; off >= 1; off >>= 1)
                mloc = fmaxf(mloc, __shfl_xor_sync(0xffffffffu, mloc, off));
            float mnew  = fmaxf(m[rr], mloc);
            float alpha = __expf(m[rr] - mnew);
            m[rr] = mnew;
            float rsum = 0.f;
#pragma unroll
            for (int cc = 0; cc < 4; cc++) {
                s[rr][cc] = __expf(s[rr][cc] - mnew);
                rsum += s[rr][cc];
            }
#pragma unroll
            for (int off = 8; off >= 1; off >>= 1)
                rsum += __shfl_xor_sync(0xffffffffu, rsum, off);
            lsum[rr] = lsum[rr] * alpha + rsum;
#pragma unroll
            for (int cc = 0; cc < 4; cc++) o[rr][cc] *= alpha;
            // stage P
            *reinterpret_cast<float4*>(&sm.Ps[row][tx * 4]) =
                make_float4(s[rr][0], s[rr][1], s[rr][2], s[rr][3]);
        }
        __syncthreads();

        // O += P @ V
#pragma unroll 8
        for (int jj = 0; jj < 64; jj++) {
            float a[8];
#pragma unroll
            for (int rr = 0; rr < 8; rr++) a[rr] = sm.Ps[ty * 8 + rr][jj];
            float bv[4];
#pragma unroll
            for (int cc = 0; cc < 4; cc++) bv[cc] = sm.Vs[jj][tx * 4 + cc];
#pragma unroll
            for (int rr = 0; rr < 8; rr++)
#pragma unroll
                for (int cc = 0; cc < 4; cc++)
                    o[rr][cc] += a[rr] * bv[cc];
        }
        __syncthreads();
    }

    // normalize + stage transposed to [d][i] (reuse Ks), then coalesced store
#pragma unroll
    for (int rr = 0; rr < 8; rr++) {
        float inv = 1.0f / lsum[rr];
#pragma unroll
        for (int cc = 0; cc < 4; cc++)
            sm.Ks[tx * 4 + cc][ty * 8 + rr] = o[rr][cc] * inv;
    }
    __syncthreads();

    float* ab = att + (b * 512 + h * 64) * 1024 + q0;
#pragma unroll
    for (int l = 0; l < 32; l++) {
        int flat = tid + l * 128;
        int d = flat >> 6, i = flat & 63;
        ab[d * 1024 + i] = sm.Ks[d][i];
    }
}

// ---------------------------------------------------------------------------
// Launch
// ---------------------------------------------------------------------------
extern "C" void kernel_launch(void* const* d_in, const int* in_sizes, int n_in,
                              void* d_out, int out_size)
{
    const float* x     = (const float*)d_in[0];
    const float* w_q   = (const float*)d_in[1];
    const float* w_k   = (const float*)d_in[2];
    const float* w_v   = (const float*)d_in[3];
    const float* w_o   = (const float*)d_in[4];
    const float* b_o   = (const float*)d_in[5];
    const float* rel_h = (const float*)d_in[6];
    const float* rel_w = (const float*)d_in[7];
    float* out = (float*)d_out;

    float *pq, *pk, *pv, *patt, *plh, *plw;
    cudaGetSymbolAddress((void**)&pq,   g_q);
    cudaGetSymbolAddress((void**)&pk,   g_k);
    cudaGetSymbolAddress((void**)&pv,   g_v);
    cudaGetSymbolAddress((void**)&patt, g_att);
    cudaGetSymbolAddress((void**)&plh,  g_lh);
    cudaGetSymbolAddress((void**)&plw,  g_lw);

    cudaFuncSetAttribute(attn_kernel, cudaFuncAttributeMaxDynamicSharedMemorySize,
                         (int)sizeof(AttnSmem));

    dim3 gp(8, 4, 16);   // n-tiles, m-tiles, batch
    gemm512_kernel<0><<<gp, 256>>>(w_q, x, pq, nullptr);
    gemm512_kernel<0><<<gp, 256>>>(w_k, x, pk, nullptr);
    gemm512_kernel<0><<<gp, 256>>>(w_v, x, pv, nullptr);

    bias_tables_kernel<<<2048, 256>>>(pq, rel_h, rel_w, plh, plw);

    attn_kernel<<<dim3(16, 128), 128, sizeof(AttnSmem)>>>(pq, pk, pv, plh, plw, patt);

    gemm512_kernel<1><<<gp, 256>>>(w_o, patt, out, b_o);
}

// round 7
// speedup vs baseline: 1.2594x; 1.2594x over previous
#include <cuda_runtime.h>
#include <cuda_bf16.h>
#include <math.h>
#include <stdint.h>

// Problem: B=16, C=512, NH=8, DK=64, H=W=32, N=1024
// NOTE: harness toolchain targets compute_103 (no 'a') -> tcgen05/TMA unusable.
// Use legacy mma.sync (HMMA) + ldmatrix + cp.async, all plain sm_80-level PTX.

// ===========================================================================
// PTX helpers
// ===========================================================================
__device__ __forceinline__ uint32_t smem_u32(const void* p) {
    uint32_t a;
    asm("{ .reg .u64 t; cvta.to.shared.u64 t, %1; cvt.u32.u64 %0, t; }"
        : "=r"(a) : "l"(p));
    return a;
}
__device__ __forceinline__ void cp16(uint32_t dst, const void* src) {
    asm volatile("cp.async.cg.shared.global [%0], [%1], 16;" :: "r"(dst), "l"(src));
}
__device__ __forceinline__ void cp_commit() { asm volatile("cp.async.commit_group;"); }
template <int N>
__device__ __forceinline__ void cp_wait() {
    asm volatile("cp.async.wait_group %0;" :: "n"(N) : "memory");
}
__device__ __forceinline__ void ldsm4(uint32_t* r, uint32_t addr) {
    asm volatile("ldmatrix.sync.aligned.m8n8.x4.shared.b16 {%0,%1,%2,%3}, [%4];"
                 : "=r"(r[0]), "=r"(r[1]), "=r"(r[2]), "=r"(r[3]) : "r"(addr));
}
__device__ __forceinline__ void mma_bf16(float* d, const uint32_t* a,
                                         uint32_t b0, uint32_t b1) {
    asm volatile(
        "mma.sync.aligned.m16n8k16.row.col.f32.bf16.bf16.f32 "
        "{%0,%1,%2,%3}, {%4,%5,%6,%7}, {%8,%9}, {%0,%1,%2,%3};"
        : "+f"(d[0]), "+f"(d[1]), "+f"(d[2]), "+f"(d[3])
        : "r"(a[0]), "r"(a[1]), "r"(a[2]), "r"(a[3]), "r"(b0), "r"(b1));
}
__device__ __forceinline__ uint32_t packbf2(float a, float b) {
    __nv_bfloat162 h = __floats2bfloat162_rn(a, b);
    return *reinterpret_cast<uint32_t*>(&h);
}

// ===========================================================================
// Device scratch
// q,k,v: [b][h][d][n] fp32
// xtb/xts: x transposed [b][n][c], bf16 big/small split
// attb/atts: attention output [b][n][c] (c=h*64+d), bf16 split
// wb/ws: weights [4][o][c] bf16 split; order q,k,v,o
// lh/lw: [b][h][n][64] fp32
// ===========================================================================
__device__ float         g_q   [16 * 8 * 64 * 1024];
__device__ float         g_k   [16 * 8 * 64 * 1024];
__device__ float         g_v   [16 * 8 * 64 * 1024];
__device__ __nv_bfloat16 g_xtb [16 * 1024 * 512];
__device__ __nv_bfloat16 g_xts [16 * 1024 * 512];
__device__ __nv_bfloat16 g_attb[16 * 1024 * 512];
__device__ __nv_bfloat16 g_atts[16 * 1024 * 512];
__device__ __nv_bfloat16 g_wb  [4 * 512 * 512];
__device__ __nv_bfloat16 g_ws  [4 * 512 * 512];
__device__ float         g_lh  [16 * 8 * 1024 * 64];
__device__ float         g_lw  [16 * 8 * 1024 * 64];

// ===========================================================================
// Producers: transpose+split x -> [b][n][c] bf16 pair; split weights
// ===========================================================================
__global__ __launch_bounds__(256)
void transpose_split_kernel(const float* __restrict__ x,
                            __nv_bfloat16* __restrict__ xtb,
                            __nv_bfloat16* __restrict__ xts)
{
    __shared__ float t[32][33];
    const int b = blockIdx.z, c0 = blockIdx.y * 32, n0 = blockIdx.x * 32;
    const int lx = threadIdx.x & 31, ly = threadIdx.x >> 5;   // ly: 0..7
    const float* xb = x + ((size_t)b * 512 + c0) * 1024 + n0;
#pragma unroll
    for (int r = 0; r < 4; r++)
        t[ly * 4 + r][lx] = xb[(size_t)(ly * 4 + r) * 1024 + lx];
    __syncthreads();
    __nv_bfloat16* ob = xtb + ((size_t)b * 1024 + n0) * 512 + c0;
    __nv_bfloat16* os = xts + ((size_t)b * 1024 + n0) * 512 + c0;
#pragma unroll
    for (int r = 0; r < 4; r++) {
        float v = t[lx][ly * 4 + r];
        __nv_bfloat16 bg = __float2bfloat16_rn(v);
        __nv_bfloat16 sl = __float2bfloat16_rn(v - __bfloat162float(bg));
        ob[(size_t)(ly * 4 + r) * 512 + lx] = bg;
        os[(size_t)(ly * 4 + r) * 512 + lx] = sl;
    }
}

__global__ __launch_bounds__(256)
void wsplit_kernel(const float* __restrict__ w0, const float* __restrict__ w1,
                   const float* __restrict__ w2, const float* __restrict__ w3,
                   __nv_bfloat16* __restrict__ wb, __nv_bfloat16* __restrict__ ws)
{
    int i = blockIdx.x * 256 + threadIdx.x;          // 0 .. 4*262144-1
    int arr = i >> 18, off = i & 262143;
    const float* src = (arr == 0) ? w0 : (arr == 1) ? w1 : (arr == 2) ? w2 : w3;
    float v = src[off];
    __nv_bfloat16 bg = __float2bfloat16_rn(v);
    wb[i] = bg;
    ws[i] = __float2bfloat16_rn(v - __bfloat162float(bg));
}

// ===========================================================================
// mma.sync bf16x3 GEMM: D[n,o] = A[b][n][c] @ W[o][c], K=512.
// BM=128(n) BN=128(o) BK=32, 256 thr = 8 warps, warp tile 32x64.
// Smem row layout: 16 bf16 (32B payload) per 48B row -> ldmatrix rows hit 8
// distinct 16B phases within 128B -> conflict-free LDSM.
// Stage = A(2 terms x 2 k16 x 128row x 48B = 24KB) + B(24KB) = 48KB, x2 stages.
// MODE 0: scatter fp32 out[((b*8+h)*64+d)*1024+n], h=o&7, d=o>>3
// MODE 1: fp32 out[b][o][n] + bias
// ===========================================================================
static constexpr unsigned GSTAGE = 49152u;
static constexpr unsigned GEMM_SMEM = 2u * GSTAGE;   // 98304

template <int MODE>
__global__ __launch_bounds__(256)
void gemm_mma_kernel(const __nv_bfloat16* __restrict__ Ab_g,
                     const __nv_bfloat16* __restrict__ As_g,
                     const __nv_bfloat16* __restrict__ Bb_g,
                     const __nv_bfloat16* __restrict__ Bs_g,
                     float* __restrict__ out, const float* __restrict__ bias)
{
    extern __shared__ unsigned char smraw[];
    const uint32_t sb = smem_u32(smraw);
    const int tid = threadIdx.x, w = tid >> 5, lane = tid & 31;
    const int b = blockIdx.z, n0 = blockIdx.x * 128, o0 = blockIdx.y * 128;
    const int wm = w & 3, wn = w >> 2;

    const __nv_bfloat16* Ag[2] = { Ab_g + ((size_t)b * 1024 + n0) * 512,
                                   As_g + ((size_t)b * 1024 + n0) * 512 };
    const __nv_bfloat16* Bg[2] = { Bb_g + (size_t)o0 * 512,
                                   Bs_g + (size_t)o0 * 512 };

    float acc[2][8][4];
#pragma unroll
    for (int t = 0; t < 2; t++)
#pragma unroll
        for (int j = 0; j < 8; j++)
#pragma unroll
            for (int e = 0; e < 4; e++) acc[t][j][e] = 0.f;

    auto load_chunk = [&](int c, uint32_t stage) {
#pragma unroll
        for (int l = 0; l < 8; l++) {
            int flat = tid + l * 256;            // 0..2047
            int op   = flat >> 10;               // 0=A, 1=B
            int term = (flat >> 9) & 1;
            int sub  = flat & 511;
            int row  = sub >> 2;
            int kb   = (sub >> 1) & 1;
            int seg  = sub & 1;
            uint32_t dst = stage + (uint32_t)op * 24576u + (uint32_t)term * 12288u
                         + (uint32_t)kb * 6144u + (uint32_t)row * 48u + (uint32_t)seg * 16u;
            const __nv_bfloat16* src = (op ? Bg[term] : Ag[term])
                                     + (size_t)row * 512 + c * 32 + kb * 16 + seg * 8;
            cp16(dst, src);
        }
    };

    const int rl   = (lane & 7) + ((lane >> 3) & 1) * 8;
    const int byt  = ((lane >> 4) & 1) * 16;

    auto compute = [&](uint32_t stage) {
#pragma unroll
        for (int kb = 0; kb < 2; kb++) {
            uint32_t a_f[2][2][4];   // [term][t16]
            uint32_t b_f[2][4][4];   // [term][g16]
#pragma unroll
            for (int term = 0; term < 2; term++) {
#pragma unroll
                for (int t = 0; t < 2; t++)
                    ldsm4(a_f[term][t], stage + (uint32_t)term * 12288u + (uint32_t)kb * 6144u
                                        + (uint32_t)(wm * 32 + t * 16 + rl) * 48u + byt);
#pragma unroll
                for (int g = 0; g < 4; g++)
                    ldsm4(b_f[term][g], stage + 24576u + (uint32_t)term * 12288u + (uint32_t)kb * 6144u
                                        + (uint32_t)(wn * 64 + g * 16 + rl) * 48u + byt);
            }
#pragma unroll
            for (int t = 0; t < 2; t++)
#pragma unroll
                for (int j = 0; j < 8; j++) {
                    int g = j >> 1, jj = j & 1;
                    mma_bf16(acc[t][j], a_f[0][t], b_f[0][g][jj], b_f[0][g][jj + 2]); // big*big
                    mma_bf16(acc[t][j], a_f[0][t], b_f[1][g][jj], b_f[1][g][jj + 2]); // big*small
                    mma_bf16(acc[t][j], a_f[1][t], b_f[0][g][jj], b_f[0][g][jj + 2]); // small*big
                }
        }
    };

    load_chunk(0, sb); cp_commit();
    for (int c = 0; c < 16; c++) {
        if (c < 15) {
            load_chunk(c + 1, sb + (uint32_t)((c + 1) & 1) * GSTAGE);
            cp_commit();
            cp_wait<1>();
        } else {
            cp_wait<0>();
        }
        __syncthreads();
        compute(sb + (uint32_t)(c & 1) * GSTAGE);
        __syncthreads();
    }

    // Epilogue: stage 64 o-rows x 128 n in smem (reuse), two passes
    float* Ds = reinterpret_cast<float*>(smraw);    // [64][132]
    const int grp = lane >> 2, tig = lane & 3;
#pragma unroll
    for (int p = 0; p < 2; p++) {
        if (wn == p) {
#pragma unroll
            for (int t = 0; t < 2; t++)
#pragma unroll
                for (int j = 0; j < 8; j++) {
                    int oc = j * 8 + 2 * tig;
                    int mb = wm * 32 + t * 16 + grp;
                    Ds[oc * 132 + mb]           = acc[t][j][0];
                    Ds[(oc + 1) * 132 + mb]     = acc[t][j][1];
                    Ds[oc * 132 + mb + 8]       = acc[t][j][2];
                    Ds[(oc + 1) * 132 + mb + 8] = acc[t][j][3];
                }
        }
        __syncthreads();
#pragma unroll
        for (int l = 0; l < 8; l++) {
            int idx  = tid + l * 256;            // 2048 float4
            int row  = idx >> 5;                 // 0..63 (o within half)
            int col4 = (idx & 31) * 4;           // 0..124 (n)
            float4 v = *reinterpret_cast<float4*>(&Ds[row * 132 + col4]);
            int o = o0 + p * 64 + row;
            if (MODE == 0) {
                int h = o & 7, d = o >> 3;
                *reinterpret_cast<float4*>(
                    &out[(size_t)((b * 8 + h) * 64 + d) * 1024 + n0 + col4]) = v;
            } else {
                float bo = __ldg(&bias[o]);
                v.x += bo; v.y += bo; v.z += bo; v.w += bo;
                *reinterpret_cast<float4*>(
                    &out[(size_t)(b * 512 + o) * 1024 + n0 + col4]) = v;
            }
        }
        __syncthreads();
    }
}

// ===========================================================================
// Rel-pos tables, register-blocked: lh/lw[n][r] = sum_d q[n][d]*rel[r][d]
// ===========================================================================
__global__ __launch_bounds__(256)
void bias_tables_kernel(const float* __restrict__ q,
                        const float* __restrict__ rel_h, const float* __restrict__ rel_w,
                        float* __restrict__ lh, float* __restrict__ lw)
{
    extern __shared__ float bsm[];
    float (*Qs2)[64] = reinterpret_cast<float (*)[64]>(bsm);          // [d][i] 16KB
    float (*Rs)[128] = reinterpret_cast<float (*)[128]>(bsm + 4096);  // [d][col] 32KB

    const int blk = blockIdx.x;          // 2048
    const int bh  = blk >> 4;
    const int n0  = (blk & 15) * 64;
    const float* __restrict__ qb = q + (size_t)bh * 64 * 1024;   // [d][n]
    const int tid = threadIdx.x;

#pragma unroll
    for (int l = 0; l < 16; l++) {
        int flat = tid + l * 256;
        int d = flat >> 6, i = flat & 63;
        Qs2[d][i] = qb[(size_t)d * 1024 + n0 + i];
    }
#pragma unroll
    for (int l = 0; l < 32; l++) {
        int flat = tid + l * 256;
        int d = flat >> 7, col = flat & 127;
        float v = 0.f;
        if (col < 63)                    v = rel_h[col * 64 + d];
        else if (col >= 64 && col < 127) v = rel_w[(col - 64) * 64 + d];
        Rs[d][col] = v;
    }
    __syncthreads();

    const int warp = tid >> 5, lane = tid & 31;
    const int i0 = warp * 8, c0 = lane * 4;

    float acc[8][4];
#pragma unroll
    for (int rr = 0; rr < 8; rr++)
#pragma unroll
        for (int cc = 0; cc < 4; cc++) acc[rr][cc] = 0.f;

#pragma unroll 4
    for (int d = 0; d < 64; d++) {
        float a[8];
        *reinterpret_cast<float4*>(&a[0]) = *reinterpret_cast<float4*>(&Qs2[d][i0]);
        *reinterpret_cast<float4*>(&a[4]) = *reinterpret_cast<float4*>(&Qs2[d][i0 + 4]);
        float4 bv = *reinterpret_cast<float4*>(&Rs[d][c0]);
#pragma unroll
        for (int rr = 0; rr < 8; rr++) {
            acc[rr][0] += a[rr] * bv.x;
            acc[rr][1] += a[rr] * bv.y;
            acc[rr][2] += a[rr] * bv.z;
            acc[rr][3] += a[rr] * bv.w;
        }
    }

#pragma unroll
    for (int rr = 0; rr < 8; rr++) {
        size_t base = ((size_t)bh * 1024 + n0 + i0 + rr) * 64;
#pragma unroll
        for (int cc = 0; cc < 4; cc++) {
            int col = c0 + cc;
            if (col < 63)                    lh[base + col] = acc[rr][cc];
            else if (col >= 64 && col < 127) lw[base + col - 64] = acc[rr][cc];
        }
    }
}

// ===========================================================================
// Flash attention with rel-pos bias (fp32 core, known-correct); epilogue
// writes att[b][n][c] bf16 big/small for the tensor out-projection.
// ===========================================================================
struct AttnSmem {
    float Qs[64][65];
    float Ks[64][68];
    float Vs[64][65];
    float Ps[64][68];
    float Lh[64][64];
    float Lw[64][64];
};

__global__ __launch_bounds__(128)
void attn_kernel(const float* __restrict__ q, const float* __restrict__ k,
                 const float* __restrict__ v,
                 const float* __restrict__ lh, const float* __restrict__ lw,
                 __nv_bfloat16* __restrict__ attb, __nv_bfloat16* __restrict__ atts)
{
    extern __shared__ unsigned char smem_raw[];
    AttnSmem& sm = *reinterpret_cast<AttnSmem*>(smem_raw);

    const int bh = blockIdx.y;
    const int b  = bh >> 3, h = bh & 7;
    const int q0 = blockIdx.x * 64;

    const float* __restrict__ qb = q + (size_t)bh * 64 * 1024;
    const float* __restrict__ kb = k + (size_t)bh * 64 * 1024;
    const float* __restrict__ vb = v + (size_t)bh * 64 * 1024;

    const int tid = threadIdx.x;
    const int ty  = tid >> 4;
    const int tx  = tid & 15;

#pragma unroll
    for (int l = 0; l < 32; l++) {
        int flat = tid + l * 128;
        int d = flat >> 6, i = flat & 63;
        sm.Qs[i][d] = qb[(size_t)d * 1024 + q0 + i];
    }
#pragma unroll
    for (int l = 0; l < 32; l++) {
        int flat = tid + l * 128;
        int i = flat >> 6, r = flat & 63;
        size_t gidx = ((size_t)bh * 1024 + q0 + i) * 64 + r;
        sm.Lh[i][r] = lh[gidx];
        sm.Lw[i][r] = lw[gidx];
    }

    float m[8], lsum[8], o[8][4];
#pragma unroll
    for (int rr = 0; rr < 8; rr++) {
        m[rr] = -1e30f; lsum[rr] = 0.f;
#pragma unroll
        for (int cc = 0; cc < 4; cc++) o[rr][cc] = 0.f;
    }

    int xr[8], yr[8];
#pragma unroll
    for (int rr = 0; rr < 8; rr++) {
        int nq = q0 + ty * 8 + rr;
        xr[rr] = nq >> 5;
        yr[rr] = nq & 31;
    }

    __syncthreads();

    for (int kt = 0; kt < 16; kt++) {
#pragma unroll
        for (int l = 0; l < 8; l++) {
            int flat = tid + l * 128;
            int d = flat >> 4, j4 = (flat & 15) * 4;
            *reinterpret_cast<float4*>(&sm.Ks[d][j4]) =
                *reinterpret_cast<const float4*>(&kb[(size_t)d * 1024 + kt * 64 + j4]);
        }
#pragma unroll
        for (int l = 0; l < 32; l++) {
            int flat = tid + l * 128;
            int d = flat >> 6, j = flat & 63;
            sm.Vs[j][d] = vb[(size_t)d * 1024 + kt * 64 + j];
        }
        __syncthreads();

        float s[8][4];
#pragma unroll
        for (int rr = 0; rr < 8; rr++)
#pragma unroll
            for (int cc = 0; cc < 4; cc++) s[rr][cc] = 0.f;

#pragma unroll 8
        for (int kk = 0; kk < 64; kk++) {
            float a[8];
#pragma unroll
            for (int rr = 0; rr < 8; rr++) a[rr] = sm.Qs[ty * 8 + rr][kk];
            float4 bv = *reinterpret_cast<float4*>(&sm.Ks[kk][tx * 4]);
#pragma unroll
            for (int rr = 0; rr < 8; rr++) {
                s[rr][0] += a[rr] * bv.x;
                s[rr][1] += a[rr] * bv.y;
                s[rr][2] += a[rr] * bv.z;
                s[rr][3] += a[rr] * bv.w;
            }
        }

        const int kt2 = kt * 2;
#pragma unroll
        for (int rr = 0; rr < 8; rr++) {
            int row = ty * 8 + rr;
#pragma unroll
            for (int cc = 0; cc < 4; cc++) {
                int jj = tx * 4 + cc;
                float bias = sm.Lh[row][kt2 + (jj >> 5) - xr[rr] + 31]
                           + sm.Lw[row][(jj & 31) - yr[rr] + 31];
                s[rr][cc] = (s[rr][cc] + bias) * 0.125f;
            }
            float mloc = fmaxf(fmaxf(s[rr][0], s[rr][1]), fmaxf(s[rr][2], s[rr][3]));
#pragma unroll
            for (int off = 8; off >= 1; off >>= 1)
                mloc = fmaxf(mloc, __shfl_xor_sync(0xffffffffu, mloc, off));
            float mnew  = fmaxf(m[rr], mloc);
            float alpha = __expf(m[rr] - mnew);
            m[rr] = mnew;
            float rsum = 0.f;
#pragma unroll
            for (int cc = 0; cc < 4; cc++) {
                s[rr][cc] = __expf(s[rr][cc] - mnew);
                rsum += s[rr][cc];
            }
#pragma unroll
            for (int off = 8; off >= 1; off >>= 1)
                rsum += __shfl_xor_sync(0xffffffffu, rsum, off);
            lsum[rr] = lsum[rr] * alpha + rsum;
#pragma unroll
            for (int cc = 0; cc < 4; cc++) o[rr][cc] *= alpha;
            *reinterpret_cast<float4*>(&sm.Ps[row][tx * 4]) =
                make_float4(s[rr][0], s[rr][1], s[rr][2], s[rr][3]);
        }
        __syncthreads();

#pragma unroll 8
        for (int jj = 0; jj < 64; jj++) {
            float a[8];
#pragma unroll
            for (int rr = 0; rr < 8; rr++) a[rr] = sm.Ps[ty * 8 + rr][jj];
            float bv[4];
#pragma unroll
            for (int cc = 0; cc < 4; cc++) bv[cc] = sm.Vs[jj][tx * 4 + cc];
#pragma unroll
            for (int rr = 0; rr < 8; rr++)
#pragma unroll
                for (int cc = 0; cc < 4; cc++)
                    o[rr][cc] += a[rr] * bv[cc];
        }
        __syncthreads();
    }

    // Epilogue: att[b][n][c] bf16 big/small, c = h*64 + d
#pragma unroll
    for (int rr = 0; rr < 8; rr++) {
        float inv = 1.0f / lsum[rr];
        float vv[4], bgf[4], slf[4];
#pragma unroll
        for (int cc = 0; cc < 4; cc++) {
            vv[cc]  = o[rr][cc] * inv;
            bgf[cc] = __bfloat162float(__float2bfloat16_rn(vv[cc]));
            slf[cc] = vv[cc] - bgf[cc];
        }
        size_t base = ((size_t)(b * 1024 + q0 + ty * 8 + rr)) * 512 + h * 64 + tx * 4;
        uint2 pb = make_uint2(packbf2(bgf[0], bgf[1]), packbf2(bgf[2], bgf[3]));
        uint2 ps = make_uint2(packbf2(slf[0], slf[1]), packbf2(slf[2], slf[3]));
        *reinterpret_cast<uint2*>(&attb[base]) = pb;
        *reinterpret_cast<uint2*>(&atts[base]) = ps;
    }
}

// ===========================================================================
// Launch
// ===========================================================================
extern "C" void kernel_launch(void* const* d_in, const int* in_sizes, int n_in,
                              void* d_out, int out_size)
{
    const float* x     = (const float*)d_in[0];
    const float* w_q   = (const float*)d_in[1];
    const float* w_k   = (const float*)d_in[2];
    const float* w_v   = (const float*)d_in[3];
    const float* w_o   = (const float*)d_in[4];
    const float* b_o   = (const float*)d_in[5];
    const float* rel_h = (const float*)d_in[6];
    const float* rel_w = (const float*)d_in[7];
    float* out = (float*)d_out;

    float *pq, *pk, *pv, *plh, *plw;
    __nv_bfloat16 *pxtb, *pxts, *pattb, *patts, *pwb, *pws;
    cudaGetSymbolAddress((void**)&pq,    g_q);
    cudaGetSymbolAddress((void**)&pk,    g_k);
    cudaGetSymbolAddress((void**)&pv,    g_v);
    cudaGetSymbolAddress((void**)&pxtb,  g_xtb);
    cudaGetSymbolAddress((void**)&pxts,  g_xts);
    cudaGetSymbolAddress((void**)&pattb, g_attb);
    cudaGetSymbolAddress((void**)&patts, g_atts);
    cudaGetSymbolAddress((void**)&pwb,   g_wb);
    cudaGetSymbolAddress((void**)&pws,   g_ws);
    cudaGetSymbolAddress((void**)&plh,   g_lh);
    cudaGetSymbolAddress((void**)&plw,   g_lw);

    cudaFuncSetAttribute(gemm_mma_kernel<0>, cudaFuncAttributeMaxDynamicSharedMemorySize,
                         (int)GEMM_SMEM);
    cudaFuncSetAttribute(gemm_mma_kernel<1>, cudaFuncAttributeMaxDynamicSharedMemorySize,
                         (int)GEMM_SMEM);
    cudaFuncSetAttribute(bias_tables_kernel, cudaFuncAttributeMaxDynamicSharedMemorySize,
                         49152);
    cudaFuncSetAttribute(attn_kernel, cudaFuncAttributeMaxDynamicSharedMemorySize,
                         (int)sizeof(AttnSmem));

    transpose_split_kernel<<<dim3(32, 16, 16), 256>>>(x, pxtb, pxts);
    wsplit_kernel<<<4096, 256>>>(w_q, w_k, w_v, w_o, pwb, pws);

    const size_t WS = 512 * 512;
    dim3 gg(8, 4, 16);   // n-tiles(128), o-tiles(128), batch
    gemm_mma_kernel<0><<<gg, 256, GEMM_SMEM>>>(pxtb, pxts, pwb + 0 * WS, pws + 0 * WS, pq, nullptr);
    gemm_mma_kernel<0><<<gg, 256, GEMM_SMEM>>>(pxtb, pxts, pwb + 1 * WS, pws + 1 * WS, pk, nullptr);
    gemm_mma_kernel<0><<<gg, 256, GEMM_SMEM>>>(pxtb, pxts, pwb + 2 * WS, pws + 2 * WS, pv, nullptr);

    bias_tables_kernel<<<2048, 256, 49152>>>(pq, rel_h, rel_w, plh, plw);

    attn_kernel<<<dim3(16, 128), 128, sizeof(AttnSmem)>>>(pq, pk, pv, plh, plw, pattb, patts);

    gemm_mma_kernel<1><<<gg, 256, GEMM_SMEM>>>(pattb, patts, pwb + 3 * WS, pws + 3 * WS, out, b_o);
}

// round 8
// speedup vs baseline: 1.4507x; 1.1519x over previous
#include <cuda_runtime.h>
#include <cuda_bf16.h>
#include <math.h>
#include <stdint.h>

// Problem: B=16, C=512, NH=8, DK=64, H=W=32, N=1024
// Toolchain targets compute_103 (no 'a'): tcgen05/TMA unusable -> mma.sync path.

// ===========================================================================
// PTX helpers
// ===========================================================================
__device__ __forceinline__ uint32_t smem_u32(const void* p) {
    uint32_t a;
    asm("{ .reg .u64 t; cvta.to.shared.u64 t, %1; cvt.u32.u64 %0, t; }"
        : "=r"(a) : "l"(p));
    return a;
}
__device__ __forceinline__ void cp16(uint32_t dst, const void* src) {
    asm volatile("cp.async.cg.shared.global [%0], [%1], 16;" :: "r"(dst), "l"(src));
}
__device__ __forceinline__ void cp_commit() { asm volatile("cp.async.commit_group;"); }
template <int N>
__device__ __forceinline__ void cp_wait() {
    asm volatile("cp.async.wait_group %0;" :: "n"(N) : "memory");
}
__device__ __forceinline__ void ldsm4(uint32_t* r, uint32_t addr) {
    asm volatile("ldmatrix.sync.aligned.m8n8.x4.shared.b16 {%0,%1,%2,%3}, [%4];"
                 : "=r"(r[0]), "=r"(r[1]), "=r"(r[2]), "=r"(r[3]) : "r"(addr));
}
__device__ __forceinline__ void ldsm4t(uint32_t* r, uint32_t addr) {
    asm volatile("ldmatrix.sync.aligned.m8n8.x4.trans.shared.b16 {%0,%1,%2,%3}, [%4];"
                 : "=r"(r[0]), "=r"(r[1]), "=r"(r[2]), "=r"(r[3]) : "r"(addr));
}
__device__ __forceinline__ void mma_bf16(float* d, const uint32_t* a,
                                         uint32_t b0, uint32_t b1) {
    asm volatile(
        "mma.sync.aligned.m16n8k16.row.col.f32.bf16.bf16.f32 "
        "{%0,%1,%2,%3}, {%4,%5,%6,%7}, {%8,%9}, {%0,%1,%2,%3};"
        : "+f"(d[0]), "+f"(d[1]), "+f"(d[2]), "+f"(d[3])
        : "r"(a[0]), "r"(a[1]), "r"(a[2]), "r"(a[3]), "r"(b0), "r"(b1));
}
__device__ __forceinline__ uint32_t packbf2(float a, float b) {
    __nv_bfloat162 h = __floats2bfloat162_rn(a, b);
    return *reinterpret_cast<uint32_t*>(&h);
}
__device__ __forceinline__ float bff(float v) {
    return __bfloat162float(__float2bfloat16_rn(v));
}

// ===========================================================================
// Device scratch
// q: [b][h][d][n] fp32 (for bias tables + attention Q)
// kb/ks, vb/vs: [b][h][d][n] bf16 big/small
// xtb/xts: x transposed [b][n][c] bf16 split; attb/atts: [b][n][c] bf16 split
// wb/ws: weights [4][o][c] bf16 split (q,k,v,o); lh/lw: [b][h][n][64] fp32
// ===========================================================================
__device__ float         g_q   [16 * 8 * 64 * 1024];
__device__ __nv_bfloat16 g_kb  [16 * 8 * 64 * 1024];
__device__ __nv_bfloat16 g_ks  [16 * 8 * 64 * 1024];
__device__ __nv_bfloat16 g_vb  [16 * 8 * 64 * 1024];
__device__ __nv_bfloat16 g_vs  [16 * 8 * 64 * 1024];
__device__ __nv_bfloat16 g_xtb [16 * 1024 * 512];
__device__ __nv_bfloat16 g_xts [16 * 1024 * 512];
__device__ __nv_bfloat16 g_attb[16 * 1024 * 512];
__device__ __nv_bfloat16 g_atts[16 * 1024 * 512];
__device__ __nv_bfloat16 g_wb  [4 * 512 * 512];
__device__ __nv_bfloat16 g_ws  [4 * 512 * 512];
__device__ float         g_lh  [16 * 8 * 1024 * 64];
__device__ float         g_lw  [16 * 8 * 1024 * 64];

// ===========================================================================
// Producers
// ===========================================================================
__global__ __launch_bounds__(256)
void transpose_split_kernel(const float* __restrict__ x,
                            __nv_bfloat16* __restrict__ xtb,
                            __nv_bfloat16* __restrict__ xts)
{
    __shared__ float t[32][33];
    const int b = blockIdx.z, c0 = blockIdx.y * 32, n0 = blockIdx.x * 32;
    const int lx = threadIdx.x & 31, ly = threadIdx.x >> 5;
    const float* xb = x + ((size_t)b * 512 + c0) * 1024 + n0;
#pragma unroll
    for (int r = 0; r < 4; r++)
        t[ly * 4 + r][lx] = xb[(size_t)(ly * 4 + r) * 1024 + lx];
    __syncthreads();
    __nv_bfloat16* ob = xtb + ((size_t)b * 1024 + n0) * 512 + c0;
    __nv_bfloat16* os = xts + ((size_t)b * 1024 + n0) * 512 + c0;
#pragma unroll
    for (int r = 0; r < 4; r++) {
        float v = t[lx][ly * 4 + r];
        __nv_bfloat16 bg = __float2bfloat16_rn(v);
        ob[(size_t)(ly * 4 + r) * 512 + lx] = bg;
        os[(size_t)(ly * 4 + r) * 512 + lx] = __float2bfloat16_rn(v - __bfloat162float(bg));
    }
}

__global__ __launch_bounds__(256)
void wsplit_kernel(const float* __restrict__ w0, const float* __restrict__ w1,
                   const float* __restrict__ w2, const float* __restrict__ w3,
                   __nv_bfloat16* __restrict__ wb, __nv_bfloat16* __restrict__ ws)
{
    int i = blockIdx.x * 256 + threadIdx.x;
    int arr = i >> 18, off = i & 262143;
    const float* src = (arr == 0) ? w0 : (arr == 1) ? w1 : (arr == 2) ? w2 : w3;
    float v = src[off];
    __nv_bfloat16 bg = __float2bfloat16_rn(v);
    wb[i] = bg;
    ws[i] = __float2bfloat16_rn(v - __bfloat162float(bg));
}

// ===========================================================================
// mma.sync bf16x3 GEMM: D[n,o] = A[b][n][c] @ W[o][c], K=512.
// BM=128 BN=128 BK=32, 256 thr, warp tile 32x64, 48B smem rows.
// MODE 0: combined QKV (grid z = proj*16+b): proj0 -> fp32 q[(bh,d)][n];
//         proj1/2 -> bf16 big/small K/V in [b][h][d][n].
// MODE 1: fp32 out[b][o][n] + bias (final projection)
// ===========================================================================
static constexpr unsigned GSTAGE = 49152u;
static constexpr unsigned GEMM_SMEM = 2u * GSTAGE;

template <int MODE>
__global__ __launch_bounds__(256)
void gemm_mma_kernel(const __nv_bfloat16* __restrict__ Ab_g,
                     const __nv_bfloat16* __restrict__ As_g,
                     const __nv_bfloat16* __restrict__ Wb_g,
                     const __nv_bfloat16* __restrict__ Ws_g,
                     float* __restrict__ out, const float* __restrict__ bias,
                     __nv_bfloat16* __restrict__ kbg, __nv_bfloat16* __restrict__ ksg,
                     __nv_bfloat16* __restrict__ vbg, __nv_bfloat16* __restrict__ vsg)
{
    extern __shared__ unsigned char smraw[];
    const uint32_t sb = smem_u32(smraw);
    const int tid = threadIdx.x, w = tid >> 5, lane = tid & 31;
    const int b = blockIdx.z & 15, proj = blockIdx.z >> 4;
    const int n0 = blockIdx.x * 128, o0 = blockIdx.y * 128;
    const int wm = w & 3, wn = w >> 2;

    const __nv_bfloat16* Ag[2] = { Ab_g + ((size_t)b * 1024 + n0) * 512,
                                   As_g + ((size_t)b * 1024 + n0) * 512 };
    const size_t woff = (size_t)proj * 512 * 512 + (size_t)o0 * 512;
    const __nv_bfloat16* Bg[2] = { Wb_g + woff, Ws_g + woff };

    float acc[2][8][4];
#pragma unroll
    for (int t = 0; t < 2; t++)
#pragma unroll
        for (int j = 0; j < 8; j++)
#pragma unroll
            for (int e = 0; e < 4; e++) acc[t][j][e] = 0.f;

    auto load_chunk = [&](int c, uint32_t stage) {
#pragma unroll
        for (int l = 0; l < 8; l++) {
            int flat = tid + l * 256;
            int op   = flat >> 10;
            int term = (flat >> 9) & 1;
            int sub  = flat & 511;
            int row  = sub >> 2;
            int kb   = (sub >> 1) & 1;
            int seg  = sub & 1;
            uint32_t dst = stage + (uint32_t)op * 24576u + (uint32_t)term * 12288u
                         + (uint32_t)kb * 6144u + (uint32_t)row * 48u + (uint32_t)seg * 16u;
            const __nv_bfloat16* src = (op ? Bg[term] : Ag[term])
                                     + (size_t)row * 512 + c * 32 + kb * 16 + seg * 8;
            cp16(dst, src);
        }
    };

    const int rl  = lane & 15;
    const int byt = (lane >> 4) * 16;

    auto compute = [&](uint32_t stage) {
#pragma unroll
        for (int kb = 0; kb < 2; kb++) {
            uint32_t a_f[2][2][4];
            uint32_t b_f[2][4][4];
#pragma unroll
            for (int term = 0; term < 2; term++) {
#pragma unroll
                for (int t = 0; t < 2; t++)
                    ldsm4(a_f[term][t], stage + (uint32_t)term * 12288u + (uint32_t)kb * 6144u
                                        + (uint32_t)(wm * 32 + t * 16 + rl) * 48u + byt);
#pragma unroll
                for (int g = 0; g < 4; g++)
                    ldsm4(b_f[term][g], stage + 24576u + (uint32_t)term * 12288u + (uint32_t)kb * 6144u
                                        + (uint32_t)(wn * 64 + g * 16 + rl) * 48u + byt);
            }
#pragma unroll
            for (int t = 0; t < 2; t++)
#pragma unroll
                for (int j = 0; j < 8; j++) {
                    int g = j >> 1, jj = j & 1;
                    mma_bf16(acc[t][j], a_f[0][t], b_f[0][g][jj], b_f[0][g][jj + 2]);
                    mma_bf16(acc[t][j], a_f[0][t], b_f[1][g][jj], b_f[1][g][jj + 2]);
                    mma_bf16(acc[t][j], a_f[1][t], b_f[0][g][jj], b_f[0][g][jj + 2]);
                }
        }
    };

    load_chunk(0, sb); cp_commit();
    for (int c = 0; c < 16; c++) {
        if (c < 15) {
            load_chunk(c + 1, sb + (uint32_t)((c + 1) & 1) * GSTAGE);
            cp_commit();
            cp_wait<1>();
        } else {
            cp_wait<0>();
        }
        __syncthreads();
        compute(sb + (uint32_t)(c & 1) * GSTAGE);
        __syncthreads();
    }

    float* Ds = reinterpret_cast<float*>(smraw);    // [64][132]
    const int grp = lane >> 2, tig = lane & 3;
#pragma unroll
    for (int p = 0; p < 2; p++) {
        if (wn == p) {
#pragma unroll
            for (int t = 0; t < 2; t++)
#pragma unroll
                for (int j = 0; j < 8; j++) {
                    int oc = j * 8 + 2 * tig;
                    int mb = wm * 32 + t * 16 + grp;
                    Ds[oc * 132 + mb]           = acc[t][j][0];
                    Ds[(oc + 1) * 132 + mb]     = acc[t][j][1];
                    Ds[oc * 132 + mb + 8]       = acc[t][j][2];
                    Ds[(oc + 1) * 132 + mb + 8] = acc[t][j][3];
                }
        }
        __syncthreads();
#pragma unroll
        for (int l = 0; l < 8; l++) {
            int idx  = tid + l * 256;
            int row  = idx >> 5;
            int col4 = (idx & 31) * 4;
            float4 v = *reinterpret_cast<float4*>(&Ds[row * 132 + col4]);
            int o = o0 + p * 64 + row;
            if (MODE == 1) {
                float bo = __ldg(&bias[o]);
                v.x += bo; v.y += bo; v.z += bo; v.w += bo;
                *reinterpret_cast<float4*>(
                    &out[(size_t)(b * 512 + o) * 1024 + n0 + col4]) = v;
            } else {
                int hh = o & 7, dd = o >> 3;
                size_t gi = (size_t)((b * 8 + hh) * 64 + dd) * 1024 + n0 + col4;
                if (proj == 0) {
                    *reinterpret_cast<float4*>(&out[gi]) = v;
                } else {
                    __nv_bfloat16* ob = (proj == 1) ? kbg : vbg;
                    __nv_bfloat16* os = (proj == 1) ? ksg : vsg;
                    float bg0 = bff(v.x), bg1 = bff(v.y), bg2 = bff(v.z), bg3 = bff(v.w);
                    uint2 pb = make_uint2(packbf2(bg0, bg1), packbf2(bg2, bg3));
                    uint2 ps = make_uint2(packbf2(v.x - bg0, v.y - bg1),
                                          packbf2(v.z - bg2, v.w - bg3));
                    *reinterpret_cast<uint2*>(&ob[gi]) = pb;
                    *reinterpret_cast<uint2*>(&os[gi]) = ps;
                }
            }
        }
        __syncthreads();
    }
}

// ===========================================================================
// Rel-pos tables (register-blocked GEMM, unchanged)
// ===========================================================================
__global__ __launch_bounds__(256)
void bias_tables_kernel(const float* __restrict__ q,
                        const float* __restrict__ rel_h, const float* __restrict__ rel_w,
                        float* __restrict__ lh, float* __restrict__ lw)
{
    extern __shared__ float bsm[];
    float (*Qs2)[64] = reinterpret_cast<float (*)[64]>(bsm);
    float (*Rs)[128] = reinterpret_cast<float (*)[128]>(bsm + 4096);

    const int blk = blockIdx.x;
    const int bh  = blk >> 4;
    const int n0  = (blk & 15) * 64;
    const float* __restrict__ qb = q + (size_t)bh * 64 * 1024;
    const int tid = threadIdx.x;

#pragma unroll
    for (int l = 0; l < 16; l++) {
        int flat = tid + l * 256;
        int d = flat >> 6, i = flat & 63;
        Qs2[d][i] = qb[(size_t)d * 1024 + n0 + i];
    }
#pragma unroll
    for (int l = 0; l < 32; l++) {
        int flat = tid + l * 256;
        int d = flat >> 7, col = flat & 127;
        float v = 0.f;
        if (col < 63)                    v = rel_h[col * 64 + d];
        else if (col >= 64 && col < 127) v = rel_w[(col - 64) * 64 + d];
        Rs[d][col] = v;
    }
    __syncthreads();

    const int warp = tid >> 5, lane = tid & 31;
    const int i0 = warp * 8, c0 = lane * 4;

    float acc[8][4];
#pragma unroll
    for (int rr = 0; rr < 8; rr++)
#pragma unroll
        for (int cc = 0; cc < 4; cc++) acc[rr][cc] = 0.f;

#pragma unroll 4
    for (int d = 0; d < 64; d++) {
        float a[8];
        *reinterpret_cast<float4*>(&a[0]) = *reinterpret_cast<float4*>(&Qs2[d][i0]);
        *reinterpret_cast<float4*>(&a[4]) = *reinterpret_cast<float4*>(&Qs2[d][i0 + 4]);
        float4 bv = *reinterpret_cast<float4*>(&Rs[d][c0]);
#pragma unroll
        for (int rr = 0; rr < 8; rr++) {
            acc[rr][0] += a[rr] * bv.x;
            acc[rr][1] += a[rr] * bv.y;
            acc[rr][2] += a[rr] * bv.z;
            acc[rr][3] += a[rr] * bv.w;
        }
    }

#pragma unroll
    for (int rr = 0; rr < 8; rr++) {
        size_t base = ((size_t)bh * 1024 + n0 + i0 + rr) * 64;
#pragma unroll
        for (int cc = 0; cc < 4; cc++) {
            int col = c0 + cc;
            if (col < 63)                    lh[base + col] = acc[rr][cc];
            else if (col >= 64 && col < 127) lw[base + col - 64] = acc[rr][cc];
        }
    }
}

// ===========================================================================
// Tensor-core flash attention (FA2 layout) with rel-pos bias, bf16x3.
// Block: one (b,h) x 64-query tile, 128 threads (4 warps, m16 rows/warp).
// S = Qb.Kb + Qb.Ks + Qs.Kb (trans-ldmatrix K [d][j]); softmax in fragments;
// P repacked from accumulators; O += Pb.Vb + Pb.Vs + Ps.Vb (V [d][j] non-trans).
// Smem rows padded to 144B for conflict-free ldmatrix.
// ===========================================================================
static constexpr unsigned ATT_Q_B  = 0u;
static constexpr unsigned ATT_Q_S  = 9216u;
static constexpr unsigned ATT_K_B  = 18432u;
static constexpr unsigned ATT_V_B  = 36864u;
static constexpr unsigned ATT_LH   = 55296u;
static constexpr unsigned ATT_LW   = 71680u;
static constexpr unsigned ATT_SMEM = 88064u;

__global__ __launch_bounds__(128)
void attn_mma_kernel(const float* __restrict__ q,
                     const __nv_bfloat16* __restrict__ kbg, const __nv_bfloat16* __restrict__ ksg,
                     const __nv_bfloat16* __restrict__ vbg, const __nv_bfloat16* __restrict__ vsg,
                     const float* __restrict__ lh, const float* __restrict__ lw,
                     __nv_bfloat16* __restrict__ attb, __nv_bfloat16* __restrict__ atts)
{
    extern __shared__ unsigned char smraw[];
    const uint32_t sb = smem_u32(smraw);
    const uint32_t Qb = sb + ATT_Q_B, Qs = sb + ATT_Q_S;
    const uint32_t Kb = sb + ATT_K_B, Vb = sb + ATT_V_B;
    __nv_bfloat16* Qbp = reinterpret_cast<__nv_bfloat16*>(smraw + ATT_Q_B);
    __nv_bfloat16* Qsp = reinterpret_cast<__nv_bfloat16*>(smraw + ATT_Q_S);
    float* Lh = reinterpret_cast<float*>(smraw + ATT_LH);
    float* Lw = reinterpret_cast<float*>(smraw + ATT_LW);

    const int bh = blockIdx.y, b = bh >> 3, h = bh & 7;
    const int q0 = blockIdx.x * 64;
    const int tid = threadIdx.x, w = tid >> 5, lane = tid & 31;
    const int g = lane >> 2, t = lane & 3;
    const int rl = lane & 15, byt = (lane >> 4) * 16;

    const float* qb_g = q + (size_t)bh * 64 * 1024;

    // Q load + bf16 split (one-time)
#pragma unroll
    for (int l = 0; l < 32; l++) {
        int flat = tid + l * 128;
        int d = flat >> 6, i = flat & 63;
        float v = qb_g[(size_t)d * 1024 + q0 + i];
        __nv_bfloat16 bg = __float2bfloat16_rn(v);
        Qbp[i * 72 + d] = bg;
        Qsp[i * 72 + d] = __float2bfloat16_rn(v - __bfloat162float(bg));
    }
    // bias tables
#pragma unroll
    for (int l = 0; l < 32; l++) {
        int flat = tid + l * 128;
        int i = flat >> 6, r = flat & 63;
        size_t gidx = ((size_t)bh * 1024 + q0 + i) * 64 + r;
        Lh[i * 64 + r] = lh[gidx];
        Lw[i * 64 + r] = lw[gidx];
    }

    // per-row constants (2 rows per thread)
    const int lr0 = w * 16 + g, lr1 = lr0 + 8;
    const int nq0 = q0 + lr0, nq1 = q0 + lr1;
    const int x0 = nq0 >> 5, y0 = nq0 & 31;
    const int x1 = nq1 >> 5, y1 = nq1 & 31;

    float m0v = -1e30f, m1v = -1e30f, l0 = 0.f, l1 = 0.f;
    float o[8][4];
#pragma unroll
    for (int nd = 0; nd < 8; nd++)
#pragma unroll
        for (int e = 0; e < 4; e++) o[nd][e] = 0.f;

    __syncthreads();

    for (int kt = 0; kt < 16; kt++) {
        // K/V tiles (big+small), [d][j] rows padded to 144B, straight cp.async
#pragma unroll
        for (int l = 0; l < 16; l++) {
            int flat = tid + l * 128;
            int arr = flat >> 9, sub = flat & 511;
            int d = sub >> 3, seg = sub & 7;
            uint32_t dst = Kb + (uint32_t)arr * 9216u + (uint32_t)d * 144u + (uint32_t)seg * 16u;
            const __nv_bfloat16* base = (arr == 0) ? kbg : (arr == 1) ? ksg
                                      : (arr == 2) ? vbg : vsg;
            cp16(dst, base + ((size_t)bh * 64 + d) * 1024 + kt * 64 + seg * 8);
        }
        cp_commit();
        cp_wait<0>();
        __syncthreads();

        // ---- S = Q K^T (3 bf16 terms) ----
        float s[8][4];
#pragma unroll
        for (int nb = 0; nb < 8; nb++)
#pragma unroll
            for (int e = 0; e < 4; e++) s[nb][e] = 0.f;

#pragma unroll
        for (int kk = 0; kk < 4; kk++) {
            uint32_t aB[4], aS[4];
            ldsm4(aB, Qb + (uint32_t)(w * 16 + rl) * 144u + (uint32_t)kk * 32u + byt);
            ldsm4(aS, Qs + (uint32_t)(w * 16 + rl) * 144u + (uint32_t)kk * 32u + byt);
#pragma unroll
            for (int np = 0; np < 4; np++) {
                uint32_t kadr = (uint32_t)(kk * 16 + rl) * 144u
                              + (uint32_t)(np * 16 + (lane >> 4) * 8) * 2u;
                uint32_t bB[4], bS[4];
                ldsm4t(bB, Kb + kadr);
                ldsm4t(bS, Kb + 9216u + kadr);
                mma_bf16(s[2 * np],     aB, bB[0], bB[1]);
                mma_bf16(s[2 * np],     aB, bS[0], bS[1]);
                mma_bf16(s[2 * np],     aS, bB[0], bB[1]);
                mma_bf16(s[2 * np + 1], aB, bB[2], bB[3]);
                mma_bf16(s[2 * np + 1], aB, bS[2], bS[3]);
                mma_bf16(s[2 * np + 1], aS, bB[2], bB[3]);
            }
        }

        // ---- bias + online softmax in fragment layout ----
        const float* pLh0 = &Lh[lr0 * 64 + kt * 2 + 31 - x0];
        const float* pLh1 = &Lh[lr1 * 64 + kt * 2 + 31 - x1];
        const float lh00 = pLh0[0], lh01 = pLh0[1];
        const float lh10 = pLh1[0], lh11 = pLh1[1];
        const float* pLw0 = &Lw[lr0 * 64 + 31 - y0 + 2 * t];
        const float* pLw1 = &Lw[lr1 * 64 + 31 - y1 + 2 * t];
        float bw0[8], bw1[8];
#pragma unroll
        for (int c = 0; c < 4; c++) {
            bw0[2 * c]     = pLw0[c * 8];
            bw0[2 * c + 1] = pLw0[c * 8 + 1];
            bw1[2 * c]     = pLw1[c * 8];
            bw1[2 * c + 1] = pLw1[c * 8 + 1];
        }

        float mx0 = -1e30f, mx1 = -1e30f;
#pragma unroll
        for (int nb = 0; nb < 8; nb++) {
            float lv0 = (nb < 4) ? lh00 : lh01;
            float lv1 = (nb < 4) ? lh10 : lh11;
            int ci = (nb & 3) * 2;
            s[nb][0] = (s[nb][0] + lv0 + bw0[ci])     * 0.125f;
            s[nb][1] = (s[nb][1] + lv0 + bw0[ci + 1]) * 0.125f;
            s[nb][2] = (s[nb][2] + lv1 + bw1[ci])     * 0.125f;
            s[nb][3] = (s[nb][3] + lv1 + bw1[ci + 1]) * 0.125f;
            mx0 = fmaxf(mx0, fmaxf(s[nb][0], s[nb][1]));
            mx1 = fmaxf(mx1, fmaxf(s[nb][2], s[nb][3]));
        }
        mx0 = fmaxf(mx0, __shfl_xor_sync(0xffffffffu, mx0, 1));
        mx0 = fmaxf(mx0, __shfl_xor_sync(0xffffffffu, mx0, 2));
        mx1 = fmaxf(mx1, __shfl_xor_sync(0xffffffffu, mx1, 1));
        mx1 = fmaxf(mx1, __shfl_xor_sync(0xffffffffu, mx1, 2));

        float mn0 = fmaxf(m0v, mx0), mn1 = fmaxf(m1v, mx1);
        float al0 = __expf(m0v - mn0), al1 = __expf(m1v - mn1);
        m0v = mn0; m1v = mn1;

        float rs0 = 0.f, rs1 = 0.f;
#pragma unroll
        for (int nb = 0; nb < 8; nb++) {
            s[nb][0] = __expf(s[nb][0] - mn0);
            s[nb][1] = __expf(s[nb][1] - mn0);
            s[nb][2] = __expf(s[nb][2] - mn1);
            s[nb][3] = __expf(s[nb][3] - mn1);
            rs0 += s[nb][0] + s[nb][1];
            rs1 += s[nb][2] + s[nb][3];
        }
        rs0 += __shfl_xor_sync(0xffffffffu, rs0, 1);
        rs0 += __shfl_xor_sync(0xffffffffu, rs0, 2);
        rs1 += __shfl_xor_sync(0xffffffffu, rs1, 1);
        rs1 += __shfl_xor_sync(0xffffffffu, rs1, 2);
        l0 = l0 * al0 + rs0;
        l1 = l1 * al1 + rs1;

#pragma unroll
        for (int nd = 0; nd < 8; nd++) {
            o[nd][0] *= al0; o[nd][1] *= al0;
            o[nd][2] *= al1; o[nd][3] *= al1;
        }

        // ---- O += P V (3 bf16 terms), P repacked from accumulators ----
#pragma unroll
        for (int kk = 0; kk < 4; kk++) {
            float* p0 = s[2 * kk];
            float* p1 = s[2 * kk + 1];
            float b00 = bff(p0[0]), b01 = bff(p0[1]), b02 = bff(p0[2]), b03 = bff(p0[3]);
            float b10 = bff(p1[0]), b11 = bff(p1[1]), b12 = bff(p1[2]), b13 = bff(p1[3]);
            uint32_t pB[4] = { packbf2(b00, b01), packbf2(b02, b03),
                               packbf2(b10, b11), packbf2(b12, b13) };
            uint32_t pS[4] = { packbf2(p0[0] - b00, p0[1] - b01),
                               packbf2(p0[2] - b02, p0[3] - b03),
                               packbf2(p1[0] - b10, p1[1] - b11),
                               packbf2(p1[2] - b12, p1[3] - b13) };
#pragma unroll
            for (int nd = 0; nd < 4; nd++) {
                uint32_t vadr = (uint32_t)(nd * 16 + rl) * 144u + (uint32_t)kk * 32u + byt;
                uint32_t vB[4], vS[4];
                ldsm4(vB, Vb + vadr);
                ldsm4(vS, Vb + 9216u + vadr);
                mma_bf16(o[2 * nd],     pB, vB[0], vB[2]);
                mma_bf16(o[2 * nd],     pB, vS[0], vS[2]);
                mma_bf16(o[2 * nd],     pS, vB[0], vB[2]);
                mma_bf16(o[2 * nd + 1], pB, vB[1], vB[3]);
                mma_bf16(o[2 * nd + 1], pB, vS[1], vS[3]);
                mma_bf16(o[2 * nd + 1], pS, vB[1], vB[3]);
            }
        }
        __syncthreads();   // protect K/V smem before next tile's cp.async
    }

    // ---- epilogue: att[b][n][c] bf16 big/small, c = h*64 + d ----
    const float inv0 = 1.0f / l0, inv1 = 1.0f / l1;
    const size_t base0 = ((size_t)(b * 1024 + nq0)) * 512 + h * 64;
    const size_t base1 = ((size_t)(b * 1024 + nq1)) * 512 + h * 64;
#pragma unroll
    for (int nd = 0; nd < 8; nd++) {
        int d = nd * 8 + 2 * t;
        float v0 = o[nd][0] * inv0, v1 = o[nd][1] * inv0;
        float v2 = o[nd][2] * inv1, v3 = o[nd][3] * inv1;
        float g0 = bff(v0), g1 = bff(v1), g2 = bff(v2), g3 = bff(v3);
        *reinterpret_cast<uint32_t*>(&attb[base0 + d]) = packbf2(g0, g1);
        *reinterpret_cast<uint32_t*>(&atts[base0 + d]) = packbf2(v0 - g0, v1 - g1);
        *reinterpret_cast<uint32_t*>(&attb[base1 + d]) = packbf2(g2, g3);
        *reinterpret_cast<uint32_t*>(&atts[base1 + d]) = packbf2(v2 - g2, v3 - g3);
    }
}

// ===========================================================================
// Launch
// ===========================================================================
extern "C" void kernel_launch(void* const* d_in, const int* in_sizes, int n_in,
                              void* d_out, int out_size)
{
    const float* x     = (const float*)d_in[0];
    const float* w_q   = (const float*)d_in[1];
    const float* w_k   = (const float*)d_in[2];
    const float* w_v   = (const float*)d_in[3];
    const float* w_o   = (const float*)d_in[4];
    const float* b_o   = (const float*)d_in[5];
    const float* rel_h = (const float*)d_in[6];
    const float* rel_w = (const float*)d_in[7];
    float* out = (float*)d_out;

    float *pq, *plh, *plw;
    __nv_bfloat16 *pkb, *pks, *pvb, *pvs, *pxtb, *pxts, *pattb, *patts, *pwb, *pws;
    cudaGetSymbolAddress((void**)&pq,    g_q);
    cudaGetSymbolAddress((void**)&pkb,   g_kb);
    cudaGetSymbolAddress((void**)&pks,   g_ks);
    cudaGetSymbolAddress((void**)&pvb,   g_vb);
    cudaGetSymbolAddress((void**)&pvs,   g_vs);
    cudaGetSymbolAddress((void**)&pxtb,  g_xtb);
    cudaGetSymbolAddress((void**)&pxts,  g_xts);
    cudaGetSymbolAddress((void**)&pattb, g_attb);
    cudaGetSymbolAddress((void**)&patts, g_atts);
    cudaGetSymbolAddress((void**)&pwb,   g_wb);
    cudaGetSymbolAddress((void**)&pws,   g_ws);
    cudaGetSymbolAddress((void**)&plh,   g_lh);
    cudaGetSymbolAddress((void**)&plw,   g_lw);

    cudaFuncSetAttribute(gemm_mma_kernel<0>, cudaFuncAttributeMaxDynamicSharedMemorySize,
                         (int)GEMM_SMEM);
    cudaFuncSetAttribute(gemm_mma_kernel<1>, cudaFuncAttributeMaxDynamicSharedMemorySize,
                         (int)GEMM_SMEM);
    cudaFuncSetAttribute(bias_tables_kernel, cudaFuncAttributeMaxDynamicSharedMemorySize,
                         49152);
    cudaFuncSetAttribute(attn_mma_kernel, cudaFuncAttributeMaxDynamicSharedMemorySize,
                         (int)ATT_SMEM);

    transpose_split_kernel<<<dim3(32, 16, 16), 256>>>(x, pxtb, pxts);
    wsplit_kernel<<<4096, 256>>>(w_q, w_k, w_v, w_o, pwb, pws);

    // Combined QKV projection: z = proj*16 + b
    gemm_mma_kernel<0><<<dim3(8, 4, 48), 256, GEMM_SMEM>>>(
        pxtb, pxts, pwb, pws, pq, nullptr, pkb, pks, pvb, pvs);

    bias_tables_kernel<<<2048, 256, 49152>>>(pq, rel_h, rel_w, plh, plw);

    attn_mma_kernel<<<dim3(16, 128), 128, ATT_SMEM>>>(
        pq, pkb, pks, pvb, pvs, plh, plw, pattb, patts);

    // Final projection (w_o is at slot 3 of the split-weight array)
    const size_t WS3 = (size_t)3 * 512 * 512;
    gemm_mma_kernel<1><<<dim3(8, 4, 16), 256, GEMM_SMEM>>>(
        pattb, patts, pwb + WS3, pws + WS3, out, b_o, nullptr, nullptr, nullptr, nullptr);
}

// round 9
// speedup vs baseline: 2.5427x; 1.7528x over previous
#include <cuda_runtime.h>
#include <cuda_bf16.h>
#include <math.h>
#include <stdint.h>

// Problem: B=16, C=512, NH=8, DK=64, H=W=32, N=1024
// Toolchain targets compute_103 (no 'a'): tcgen05/TMA unusable -> mma.sync path.

// ===========================================================================
// PTX helpers
// ===========================================================================
__device__ __forceinline__ uint32_t smem_u32(const void* p) {
    uint32_t a;
    asm("{ .reg .u64 t; cvta.to.shared.u64 t, %1; cvt.u32.u64 %0, t; }"
        : "=r"(a) : "l"(p));
    return a;
}
__device__ __forceinline__ void cp16(uint32_t dst, const void* src) {
    asm volatile("cp.async.cg.shared.global [%0], [%1], 16;" :: "r"(dst), "l"(src));
}
__device__ __forceinline__ void cp_commit() { asm volatile("cp.async.commit_group;"); }
template <int N>
__device__ __forceinline__ void cp_wait() {
    asm volatile("cp.async.wait_group %0;" :: "n"(N) : "memory");
}
__device__ __forceinline__ void ldsm4(uint32_t* r, uint32_t addr) {
    asm volatile("ldmatrix.sync.aligned.m8n8.x4.shared.b16 {%0,%1,%2,%3}, [%4];"
                 : "=r"(r[0]), "=r"(r[1]), "=r"(r[2]), "=r"(r[3]) : "r"(addr));
}
__device__ __forceinline__ void ldsm4t(uint32_t* r, uint32_t addr) {
    asm volatile("ldmatrix.sync.aligned.m8n8.x4.trans.shared.b16 {%0,%1,%2,%3}, [%4];"
                 : "=r"(r[0]), "=r"(r[1]), "=r"(r[2]), "=r"(r[3]) : "r"(addr));
}
__device__ __forceinline__ void mma_bf16(float* d, const uint32_t* a,
                                         uint32_t b0, uint32_t b1) {
    asm volatile(
        "mma.sync.aligned.m16n8k16.row.col.f32.bf16.bf16.f32 "
        "{%0,%1,%2,%3}, {%4,%5,%6,%7}, {%8,%9}, {%0,%1,%2,%3};"
        : "+f"(d[0]), "+f"(d[1]), "+f"(d[2]), "+f"(d[3])
        : "r"(a[0]), "r"(a[1]), "r"(a[2]), "r"(a[3]), "r"(b0), "r"(b1));
}
__device__ __forceinline__ uint32_t packbf2(float a, float b) {
    __nv_bfloat162 h = __floats2bfloat162_rn(a, b);
    return *reinterpret_cast<uint32_t*>(&h);
}
__device__ __forceinline__ float bff(float v) {
    return __bfloat162float(__float2bfloat16_rn(v));
}

// ===========================================================================
// Device scratch
// ===========================================================================
__device__ float         g_q   [16 * 8 * 64 * 1024];
__device__ __nv_bfloat16 g_kb  [16 * 8 * 64 * 1024];
__device__ __nv_bfloat16 g_ks  [16 * 8 * 64 * 1024];
__device__ __nv_bfloat16 g_vb  [16 * 8 * 64 * 1024];
__device__ __nv_bfloat16 g_vs  [16 * 8 * 64 * 1024];
__device__ __nv_bfloat16 g_xtb [16 * 1024 * 512];
__device__ __nv_bfloat16 g_xts [16 * 1024 * 512];
__device__ __nv_bfloat16 g_attb[16 * 1024 * 512];
__device__ __nv_bfloat16 g_atts[16 * 1024 * 512];
__device__ __nv_bfloat16 g_wb  [4 * 512 * 512];
__device__ __nv_bfloat16 g_ws  [4 * 512 * 512];
// rel tables, bf16 big/small, padded to 64 rows (row 63 = 0): [r][d]
__device__ __nv_bfloat16 g_rhb [64 * 64];
__device__ __nv_bfloat16 g_rhs [64 * 64];
__device__ __nv_bfloat16 g_rwb [64 * 64];
__device__ __nv_bfloat16 g_rws [64 * 64];

// ===========================================================================
// Producers
// ===========================================================================
__global__ __launch_bounds__(256)
void transpose_split_kernel(const float* __restrict__ x,
                            __nv_bfloat16* __restrict__ xtb,
                            __nv_bfloat16* __restrict__ xts)
{
    __shared__ float t[32][33];
    const int b = blockIdx.z, c0 = blockIdx.y * 32, n0 = blockIdx.x * 32;
    const int lx = threadIdx.x & 31, ly = threadIdx.x >> 5;
    const float* xb = x + ((size_t)b * 512 + c0) * 1024 + n0;
#pragma unroll
    for (int r = 0; r < 4; r++)
        t[ly * 4 + r][lx] = xb[(size_t)(ly * 4 + r) * 1024 + lx];
    __syncthreads();
    __nv_bfloat16* ob = xtb + ((size_t)b * 1024 + n0) * 512 + c0;
    __nv_bfloat16* os = xts + ((size_t)b * 1024 + n0) * 512 + c0;
#pragma unroll
    for (int r = 0; r < 4; r++) {
        float v = t[lx][ly * 4 + r];
        __nv_bfloat16 bg = __float2bfloat16_rn(v);
        ob[(size_t)(ly * 4 + r) * 512 + lx] = bg;
        os[(size_t)(ly * 4 + r) * 512 + lx] = __float2bfloat16_rn(v - __bfloat162float(bg));
    }
}

__global__ __launch_bounds__(256)
void wsplit_kernel(const float* __restrict__ w0, const float* __restrict__ w1,
                   const float* __restrict__ w2, const float* __restrict__ w3,
                   __nv_bfloat16* __restrict__ wb, __nv_bfloat16* __restrict__ ws)
{
    int i = blockIdx.x * 256 + threadIdx.x;
    int arr = i >> 18, off = i & 262143;
    const float* src = (arr == 0) ? w0 : (arr == 1) ? w1 : (arr == 2) ? w2 : w3;
    float v = src[off];
    __nv_bfloat16 bg = __float2bfloat16_rn(v);
    wb[i] = bg;
    ws[i] = __float2bfloat16_rn(v - __bfloat162float(bg));
}

// rel tables: fp32 (63x64) -> bf16 big/small padded (64x64), row 63 zeroed
__global__ __launch_bounds__(256)
void rel_split_kernel(const float* __restrict__ rel_h, const float* __restrict__ rel_w,
                      __nv_bfloat16* __restrict__ rhb, __nv_bfloat16* __restrict__ rhs,
                      __nv_bfloat16* __restrict__ rwb, __nv_bfloat16* __restrict__ rws)
{
    int i = blockIdx.x * 256 + threadIdx.x;    // 0..8191
    int table = i >> 12, pos = i & 4095;
    int r = pos >> 6, d = pos & 63;
    float v = (r < 63) ? (table == 0 ? rel_h[r * 64 + d] : rel_w[r * 64 + d]) : 0.f;
    __nv_bfloat16 bg = __float2bfloat16_rn(v);
    __nv_bfloat16 sl = __float2bfloat16_rn(v - __bfloat162float(bg));
    if (table == 0) { rhb[pos] = bg; rhs[pos] = sl; }
    else            { rwb[pos] = bg; rws[pos] = sl; }
}

// ===========================================================================
// mma.sync bf16x3 GEMM (unchanged from R8)
// ===========================================================================
static constexpr unsigned GSTAGE = 49152u;
static constexpr unsigned GEMM_SMEM = 2u * GSTAGE;

template <int MODE>
__global__ __launch_bounds__(256)
void gemm_mma_kernel(const __nv_bfloat16* __restrict__ Ab_g,
                     const __nv_bfloat16* __restrict__ As_g,
                     const __nv_bfloat16* __restrict__ Wb_g,
                     const __nv_bfloat16* __restrict__ Ws_g,
                     float* __restrict__ out, const float* __restrict__ bias,
                     __nv_bfloat16* __restrict__ kbg, __nv_bfloat16* __restrict__ ksg,
                     __nv_bfloat16* __restrict__ vbg, __nv_bfloat16* __restrict__ vsg)
{
    extern __shared__ unsigned char smraw[];
    const uint32_t sb = smem_u32(smraw);
    const int tid = threadIdx.x, w = tid >> 5, lane = tid & 31;
    const int b = blockIdx.z & 15, proj = blockIdx.z >> 4;
    const int n0 = blockIdx.x * 128, o0 = blockIdx.y * 128;
    const int wm = w & 3, wn = w >> 2;

    const __nv_bfloat16* Ag[2] = { Ab_g + ((size_t)b * 1024 + n0) * 512,
                                   As_g + ((size_t)b * 1024 + n0) * 512 };
    const size_t woff = (size_t)proj * 512 * 512 + (size_t)o0 * 512;
    const __nv_bfloat16* Bg[2] = { Wb_g + woff, Ws_g + woff };

    float acc[2][8][4];
#pragma unroll
    for (int t = 0; t < 2; t++)
#pragma unroll
        for (int j = 0; j < 8; j++)
#pragma unroll
            for (int e = 0; e < 4; e++) acc[t][j][e] = 0.f;

    auto load_chunk = [&](int c, uint32_t stage) {
#pragma unroll
        for (int l = 0; l < 8; l++) {
            int flat = tid + l * 256;
            int op   = flat >> 10;
            int term = (flat >> 9) & 1;
            int sub  = flat & 511;
            int row  = sub >> 2;
            int kb   = (sub >> 1) & 1;
            int seg  = sub & 1;
            uint32_t dst = stage + (uint32_t)op * 24576u + (uint32_t)term * 12288u
                         + (uint32_t)kb * 6144u + (uint32_t)row * 48u + (uint32_t)seg * 16u;
            const __nv_bfloat16* src = (op ? Bg[term] : Ag[term])
                                     + (size_t)row * 512 + c * 32 + kb * 16 + seg * 8;
            cp16(dst, src);
        }
    };

    const int rl  = lane & 15;
    const int byt = (lane >> 4) * 16;

    auto compute = [&](uint32_t stage) {
#pragma unroll
        for (int kb = 0; kb < 2; kb++) {
            uint32_t a_f[2][2][4];
            uint32_t b_f[2][4][4];
#pragma unroll
            for (int term = 0; term < 2; term++) {
#pragma unroll
                for (int t = 0; t < 2; t++)
                    ldsm4(a_f[term][t], stage + (uint32_t)term * 12288u + (uint32_t)kb * 6144u
                                        + (uint32_t)(wm * 32 + t * 16 + rl) * 48u + byt);
#pragma unroll
                for (int g = 0; g < 4; g++)
                    ldsm4(b_f[term][g], stage + 24576u + (uint32_t)term * 12288u + (uint32_t)kb * 6144u
                                        + (uint32_t)(wn * 64 + g * 16 + rl) * 48u + byt);
            }
#pragma unroll
            for (int t = 0; t < 2; t++)
#pragma unroll
                for (int j = 0; j < 8; j++) {
                    int g = j >> 1, jj = j & 1;
                    mma_bf16(acc[t][j], a_f[0][t], b_f[0][g][jj], b_f[0][g][jj + 2]);
                    mma_bf16(acc[t][j], a_f[0][t], b_f[1][g][jj], b_f[1][g][jj + 2]);
                    mma_bf16(acc[t][j], a_f[1][t], b_f[0][g][jj], b_f[0][g][jj + 2]);
                }
        }
    };

    load_chunk(0, sb); cp_commit();
    for (int c = 0; c < 16; c++) {
        if (c < 15) {
            load_chunk(c + 1, sb + (uint32_t)((c + 1) & 1) * GSTAGE);
            cp_commit();
            cp_wait<1>();
        } else {
            cp_wait<0>();
        }
        __syncthreads();
        compute(sb + (uint32_t)(c & 1) * GSTAGE);
        __syncthreads();
    }

    float* Ds = reinterpret_cast<float*>(smraw);    // [64][132]
    const int grp = lane >> 2, tig = lane & 3;
#pragma unroll
    for (int p = 0; p < 2; p++) {
        if (wn == p) {
#pragma unroll
            for (int t = 0; t < 2; t++)
#pragma unroll
                for (int j = 0; j < 8; j++) {
                    int oc = j * 8 + 2 * tig;
                    int mb = wm * 32 + t * 16 + grp;
                    Ds[oc * 132 + mb]           = acc[t][j][0];
                    Ds[(oc + 1) * 132 + mb]     = acc[t][j][1];
                    Ds[oc * 132 + mb + 8]       = acc[t][j][2];
                    Ds[(oc + 1) * 132 + mb + 8] = acc[t][j][3];
                }
        }
        __syncthreads();
#pragma unroll
        for (int l = 0; l < 8; l++) {
            int idx  = tid + l * 256;
            int row  = idx >> 5;
            int col4 = (idx & 31) * 4;
            float4 v = *reinterpret_cast<float4*>(&Ds[row * 132 + col4]);
            int o = o0 + p * 64 + row;
            if (MODE == 1) {
                float bo = __ldg(&bias[o]);
                v.x += bo; v.y += bo; v.z += bo; v.w += bo;
                *reinterpret_cast<float4*>(
                    &out[(size_t)(b * 512 + o) * 1024 + n0 + col4]) = v;
            } else {
                int hh = o & 7, dd = o >> 3;
                size_t gi = (size_t)((b * 8 + hh) * 64 + dd) * 1024 + n0 + col4;
                if (proj == 0) {
                    *reinterpret_cast<float4*>(&out[gi]) = v;
                } else {
                    __nv_bfloat16* ob = (proj == 1) ? kbg : vbg;
                    __nv_bfloat16* os = (proj == 1) ? ksg : vsg;
                    float bg0 = bff(v.x), bg1 = bff(v.y), bg2 = bff(v.z), bg3 = bff(v.w);
                    uint2 pb = make_uint2(packbf2(bg0, bg1), packbf2(bg2, bg3));
                    uint2 ps = make_uint2(packbf2(v.x - bg0, v.y - bg1),
                                          packbf2(v.z - bg2, v.w - bg3));
                    *reinterpret_cast<uint2*>(&ob[gi]) = pb;
                    *reinterpret_cast<uint2*>(&os[gi]) = ps;
                }
            }
        }
        __syncthreads();
    }
}

// ===========================================================================
// Flash attention v2: Tq=128, 8 warps, double-buffered K/V, fused rel-pos
// bias tables (computed via mma at block start), base-2 softmax.
// Smem: QB/QS [128][72] bf16 (144B rows); two K/V stages of
// {KB,KS,VB,VS} 64x72 bf16 each; LH/LW fp32 [128][64].
// ===========================================================================
static constexpr unsigned AT_QB   = 0u;
static constexpr unsigned AT_QS   = 18432u;
static constexpr unsigned AT_ST0  = 36864u;
static constexpr unsigned AT_ST1  = 73728u;
static constexpr unsigned AT_LH   = 110592u;
static constexpr unsigned AT_LW   = 143360u;
static constexpr unsigned AT_SMEM = 176128u;

__global__ __launch_bounds__(256)
void attn_mma_kernel(const float* __restrict__ q,
                     const __nv_bfloat16* __restrict__ kbg, const __nv_bfloat16* __restrict__ ksg,
                     const __nv_bfloat16* __restrict__ vbg, const __nv_bfloat16* __restrict__ vsg,
                     const __nv_bfloat16* __restrict__ rhb, const __nv_bfloat16* __restrict__ rhs,
                     const __nv_bfloat16* __restrict__ rwb, const __nv_bfloat16* __restrict__ rws,
                     __nv_bfloat16* __restrict__ attb, __nv_bfloat16* __restrict__ atts)
{
    extern __shared__ unsigned char smraw[];
    const uint32_t sb = smem_u32(smraw);
    const uint32_t Qb = sb + AT_QB, Qs = sb + AT_QS;
    __nv_bfloat16* Qbp = reinterpret_cast<__nv_bfloat16*>(smraw + AT_QB);
    __nv_bfloat16* Qsp = reinterpret_cast<__nv_bfloat16*>(smraw + AT_QS);
    float* Lh = reinterpret_cast<float*>(smraw + AT_LH);
    float* Lw = reinterpret_cast<float*>(smraw + AT_LW);

    const int bh = blockIdx.y, b = bh >> 3, h = bh & 7;
    const int q0 = blockIdx.x * 128;
    const int tid = threadIdx.x, w = tid >> 5, lane = tid & 31;
    const int g = lane >> 2, t = lane & 3;
    const int rl = lane & 15, byt = (lane >> 4) * 16;

    const float* qb_g = q + (size_t)bh * 64 * 1024;

    // ---- Q load + bf16 split ----
#pragma unroll
    for (int l = 0; l < 32; l++) {
        int flat = tid + l * 256;
        int d = flat >> 7, i = flat & 127;
        float v = qb_g[(size_t)d * 1024 + q0 + i];
        __nv_bfloat16 bg = __float2bfloat16_rn(v);
        Qbp[i * 72 + d] = bg;
        Qsp[i * 72 + d] = __float2bfloat16_rn(v - __bfloat162float(bg));
    }

    // ---- rel tables into stage0: [rhb, rhs, rwb, rws] 64x144B each ----
    {
        const __nv_bfloat16* relp[4] = { rhb, rhs, rwb, rws };
#pragma unroll
        for (int l = 0; l < 8; l++) {
            int flat = tid + l * 256;
            int arr = flat >> 9, sub = flat & 511;
            int r = sub >> 3, seg = sub & 7;
            cp16(sb + AT_ST0 + (uint32_t)arr * 9216u + (uint32_t)r * 144u + (uint32_t)seg * 16u,
                 relp[arr] + r * 64 + seg * 8);
        }
    }
    cp_commit();
    cp_wait<0>();
    __syncthreads();

    // per-row constants (2 rows per thread)
    const int lr0 = w * 16 + g, lr1 = lr0 + 8;
    const int nq0 = q0 + lr0, nq1 = q0 + lr1;
    const int x0 = nq0 >> 5, y0 = nq0 & 31;
    const int x1 = nq1 >> 5, y1 = nq1 & 31;

    // ---- bias tables via mma: Lh/Lw = Q @ rel^T (bf16x3) ----
    {
        float sl[2][8][4];
#pragma unroll
        for (int tb = 0; tb < 2; tb++)
#pragma unroll
            for (int nb = 0; nb < 8; nb++)
#pragma unroll
                for (int e = 0; e < 4; e++) sl[tb][nb][e] = 0.f;

#pragma unroll
        for (int kk = 0; kk < 4; kk++) {
            uint32_t aB[4], aS[4];
            ldsm4(aB, Qb + (uint32_t)(w * 16 + rl) * 144u + (uint32_t)kk * 32u + byt);
            ldsm4(aS, Qs + (uint32_t)(w * 16 + rl) * 144u + (uint32_t)kk * 32u + byt);
#pragma unroll
            for (int tb = 0; tb < 2; tb++) {
#pragma unroll
                for (int np = 0; np < 4; np++) {
                    uint32_t radr = sb + AT_ST0 + (uint32_t)tb * 18432u
                                  + (uint32_t)(np * 16 + rl) * 144u + (uint32_t)kk * 32u + byt;
                    uint32_t rB[4], rS[4];
                    ldsm4(rB, radr);
                    ldsm4(rS, radr + 9216u);
#pragma unroll
                    for (int jj = 0; jj < 2; jj++) {
                        int nb = np * 2 + jj;
                        mma_bf16(sl[tb][nb], aB, rB[jj], rB[jj + 2]);
                        mma_bf16(sl[tb][nb], aB, rS[jj], rS[jj + 2]);
                        mma_bf16(sl[tb][nb], aS, rB[jj], rB[jj + 2]);
                    }
                }
            }
        }
#pragma unroll
        for (int nb = 0; nb < 8; nb++) {
            int c0 = nb * 8 + 2 * t;
            Lh[lr0 * 64 + c0]     = sl[0][nb][0];
            Lh[lr0 * 64 + c0 + 1] = sl[0][nb][1];
            Lh[lr1 * 64 + c0]     = sl[0][nb][2];
            Lh[lr1 * 64 + c0 + 1] = sl[0][nb][3];
            Lw[lr0 * 64 + c0]     = sl[1][nb][0];
            Lw[lr0 * 64 + c0 + 1] = sl[1][nb][1];
            Lw[lr1 * 64 + c0]     = sl[1][nb][2];
            Lw[lr1 * 64 + c0 + 1] = sl[1][nb][3];
        }
    }
    __syncthreads();   // Lh/Lw visible; stage0 free for K/V

    // ---- main flash loop, double-buffered K/V ----
    const __nv_bfloat16* kvp[4] = { kbg, ksg, vbg, vsg };
    auto load_kv = [&](int kt, uint32_t stage) {
#pragma unroll
        for (int l = 0; l < 8; l++) {
            int flat = tid + l * 256;
            int arr = flat >> 9, sub = flat & 511;
            int d = sub >> 3, seg = sub & 7;
            cp16(stage + (uint32_t)arr * 9216u + (uint32_t)d * 144u + (uint32_t)seg * 16u,
                 kvp[arr] + ((size_t)bh * 64 + d) * 1024 + kt * 64 + seg * 8);
        }
    };

    float m0v = -1e30f, m1v = -1e30f, l0 = 0.f, l1 = 0.f;
    float o[8][4];
#pragma unroll
    for (int nd = 0; nd < 8; nd++)
#pragma unroll
        for (int e = 0; e < 4; e++) o[nd][e] = 0.f;

    const float SC = 0.18033688f;    // 0.125 * log2(e)

    load_kv(0, sb + AT_ST0);
    cp_commit();

    for (int kt = 0; kt < 16; kt++) {
        const uint32_t stage = sb + AT_ST0 + (uint32_t)(kt & 1) * 36864u;
        if (kt < 15) {
            load_kv(kt + 1, sb + AT_ST0 + (uint32_t)((kt + 1) & 1) * 36864u);
            cp_commit();
            cp_wait<1>();
        } else {
            cp_wait<0>();
        }
        __syncthreads();

        const uint32_t Kb = stage, Vb = stage + 18432u;

        // ---- S = Q K^T (3 bf16 terms) ----
        float s[8][4];
#pragma unroll
        for (int nb = 0; nb < 8; nb++)
#pragma unroll
            for (int e = 0; e < 4; e++) s[nb][e] = 0.f;

#pragma unroll
        for (int kk = 0; kk < 4; kk++) {
            uint32_t aB[4], aS[4];
            ldsm4(aB, Qb + (uint32_t)(w * 16 + rl) * 144u + (uint32_t)kk * 32u + byt);
            ldsm4(aS, Qs + (uint32_t)(w * 16 + rl) * 144u + (uint32_t)kk * 32u + byt);
#pragma unroll
            for (int np = 0; np < 4; np++) {
                uint32_t kadr = (uint32_t)(kk * 16 + rl) * 144u
                              + (uint32_t)(np * 16 + (lane >> 4) * 8) * 2u;
                uint32_t bB[4], bS[4];
                ldsm4t(bB, Kb + kadr);
                ldsm4t(bS, Kb + 9216u + kadr);
                mma_bf16(s[2 * np],     aB, bB[0], bB[1]);
                mma_bf16(s[2 * np],     aB, bS[0], bS[1]);
                mma_bf16(s[2 * np],     aS, bB[0], bB[1]);
                mma_bf16(s[2 * np + 1], aB, bB[2], bB[3]);
                mma_bf16(s[2 * np + 1], aB, bS[2], bS[3]);
                mma_bf16(s[2 * np + 1], aS, bB[2], bB[3]);
            }
        }

        // ---- bias + base-2 online softmax ----
        const float* pLh0 = &Lh[lr0 * 64 + kt * 2 + 31 - x0];
        const float* pLh1 = &Lh[lr1 * 64 + kt * 2 + 31 - x1];
        const float lh00 = pLh0[0], lh01 = pLh0[1];
        const float lh10 = pLh1[0], lh11 = pLh1[1];
        const float* pLw0 = &Lw[lr0 * 64 + 31 - y0 + 2 * t];
        const float* pLw1 = &Lw[lr1 * 64 + 31 - y1 + 2 * t];
        float bw0[8], bw1[8];
#pragma unroll
        for (int c = 0; c < 4; c++) {
            bw0[2 * c]     = pLw0[c * 8];
            bw0[2 * c + 1] = pLw0[c * 8 + 1];
            bw1[2 * c]     = pLw1[c * 8];
            bw1[2 * c + 1] = pLw1[c * 8 + 1];
        }

        float mx0 = -1e30f, mx1 = -1e30f;
#pragma unroll
        for (int nb = 0; nb < 8; nb++) {
            float lv0 = (nb < 4) ? lh00 : lh01;
            float lv1 = (nb < 4) ? lh10 : lh11;
            int ci = (nb & 3) * 2;
            s[nb][0] = (s[nb][0] + lv0 + bw0[ci])     * SC;
            s[nb][1] = (s[nb][1] + lv0 + bw0[ci + 1]) * SC;
            s[nb][2] = (s[nb][2] + lv1 + bw1[ci])     * SC;
            s[nb][3] = (s[nb][3] + lv1 + bw1[ci + 1]) * SC;
            mx0 = fmaxf(mx0, fmaxf(s[nb][0], s[nb][1]));
            mx1 = fmaxf(mx1, fmaxf(s[nb][2], s[nb][3]));
        }
        mx0 = fmaxf(mx0, __shfl_xor_sync(0xffffffffu, mx0, 1));
        mx0 = fmaxf(mx0, __shfl_xor_sync(0xffffffffu, mx0, 2));
        mx1 = fmaxf(mx1, __shfl_xor_sync(0xffffffffu, mx1, 1));
        mx1 = fmaxf(mx1, __shfl_xor_sync(0xffffffffu, mx1, 2));

        float mn0 = fmaxf(m0v, mx0), mn1 = fmaxf(m1v, mx1);
        float al0 = exp2f(m0v - mn0), al1 = exp2f(m1v - mn1);
        m0v = mn0; m1v = mn1;

        float rs0 = 0.f, rs1 = 0.f;
#pragma unroll
        for (int nb = 0; nb < 8; nb++) {
            s[nb][0] = exp2f(s[nb][0] - mn0);
            s[nb][1] = exp2f(s[nb][1] - mn0);
            s[nb][2] = exp2f(s[nb][2] - mn1);
            s[nb][3] = exp2f(s[nb][3] - mn1);
            rs0 += s[nb][0] + s[nb][1];
            rs1 += s[nb][2] + s[nb][3];
        }
        rs0 += __shfl_xor_sync(0xffffffffu, rs0, 1);
        rs0 += __shfl_xor_sync(0xffffffffu, rs0, 2);
        rs1 += __shfl_xor_sync(0xffffffffu, rs1, 1);
        rs1 += __shfl_xor_sync(0xffffffffu, rs1, 2);
        l0 = l0 * al0 + rs0;
        l1 = l1 * al1 + rs1;

#pragma unroll
        for (int nd = 0; nd < 8; nd++) {
            o[nd][0] *= al0; o[nd][1] *= al0;
            o[nd][2] *= al1; o[nd][3] *= al1;
        }

        // ---- O += P V (3 bf16 terms) ----
#pragma unroll
        for (int kk = 0; kk < 4; kk++) {
            float* p0 = s[2 * kk];
            float* p1 = s[2 * kk + 1];
            float b00 = bff(p0[0]), b01 = bff(p0[1]), b02 = bff(p0[2]), b03 = bff(p0[3]);
            float b10 = bff(p1[0]), b11 = bff(p1[1]), b12 = bff(p1[2]), b13 = bff(p1[3]);
            uint32_t pB[4] = { packbf2(b00, b01), packbf2(b02, b03),
                               packbf2(b10, b11), packbf2(b12, b13) };
            uint32_t pS[4] = { packbf2(p0[0] - b00, p0[1] - b01),
                               packbf2(p0[2] - b02, p0[3] - b03),
                               packbf2(p1[0] - b10, p1[1] - b11),
                               packbf2(p1[2] - b12, p1[3] - b13) };
#pragma unroll
            for (int nd = 0; nd < 4; nd++) {
                uint32_t vadr = (uint32_t)(nd * 16 + rl) * 144u + (uint32_t)kk * 32u + byt;
                uint32_t vB[4], vS[4];
                ldsm4(vB, Vb + vadr);
                ldsm4(vS, Vb + 9216u + vadr);
                mma_bf16(o[2 * nd],     pB, vB[0], vB[2]);
                mma_bf16(o[2 * nd],     pB, vS[0], vS[2]);
                mma_bf16(o[2 * nd],     pS, vB[0], vB[2]);
                mma_bf16(o[2 * nd + 1], pB, vB[1], vB[3]);
                mma_bf16(o[2 * nd + 1], pB, vS[1], vS[3]);
                mma_bf16(o[2 * nd + 1], pS, vB[1], vB[3]);
            }
        }
        __syncthreads();
    }

    // ---- epilogue: att[b][n][c] bf16 big/small, c = h*64 + d ----
    const float inv0 = 1.0f / l0, inv1 = 1.0f / l1;
    const size_t base0 = ((size_t)(b * 1024 + nq0)) * 512 + h * 64;
    const size_t base1 = ((size_t)(b * 1024 + nq1)) * 512 + h * 64;
#pragma unroll
    for (int nd = 0; nd < 8; nd++) {
        int d = nd * 8 + 2 * t;
        float v0 = o[nd][0] * inv0, v1 = o[nd][1] * inv0;
        float v2 = o[nd][2] * inv1, v3 = o[nd][3] * inv1;
        float g0 = bff(v0), g1 = bff(v1), g2 = bff(v2), g3 = bff(v3);
        *reinterpret_cast<uint32_t*>(&attb[base0 + d]) = packbf2(g0, g1);
        *reinterpret_cast<uint32_t*>(&atts[base0 + d]) = packbf2(v0 - g0, v1 - g1);
        *reinterpret_cast<uint32_t*>(&attb[base1 + d]) = packbf2(g2, g3);
        *reinterpret_cast<uint32_t*>(&atts[base1 + d]) = packbf2(v2 - g2, v3 - g3);
    }
}

// ===========================================================================
// Launch
// ===========================================================================
extern "C" void kernel_launch(void* const* d_in, const int* in_sizes, int n_in,
                              void* d_out, int out_size)
{
    const float* x     = (const float*)d_in[0];
    const float* w_q   = (const float*)d_in[1];
    const float* w_k   = (const float*)d_in[2];
    const float* w_v   = (const float*)d_in[3];
    const float* w_o   = (const float*)d_in[4];
    const float* b_o   = (const float*)d_in[5];
    const float* rel_h = (const float*)d_in[6];
    const float* rel_w = (const float*)d_in[7];
    float* out = (float*)d_out;

    float *pq;
    __nv_bfloat16 *pkb, *pks, *pvb, *pvs, *pxtb, *pxts, *pattb, *patts, *pwb, *pws;
    __nv_bfloat16 *prhb, *prhs, *prwb, *prws;
    cudaGetSymbolAddress((void**)&pq,    g_q);
    cudaGetSymbolAddress((void**)&pkb,   g_kb);
    cudaGetSymbolAddress((void**)&pks,   g_ks);
    cudaGetSymbolAddress((void**)&pvb,   g_vb);
    cudaGetSymbolAddress((void**)&pvs,   g_vs);
    cudaGetSymbolAddress((void**)&pxtb,  g_xtb);
    cudaGetSymbolAddress((void**)&pxts,  g_xts);
    cudaGetSymbolAddress((void**)&pattb, g_attb);
    cudaGetSymbolAddress((void**)&patts, g_atts);
    cudaGetSymbolAddress((void**)&pwb,   g_wb);
    cudaGetSymbolAddress((void**)&pws,   g_ws);
    cudaGetSymbolAddress((void**)&prhb,  g_rhb);
    cudaGetSymbolAddress((void**)&prhs,  g_rhs);
    cudaGetSymbolAddress((void**)&prwb,  g_rwb);
    cudaGetSymbolAddress((void**)&prws,  g_rws);

    cudaFuncSetAttribute(gemm_mma_kernel<0>, cudaFuncAttributeMaxDynamicSharedMemorySize,
                         (int)GEMM_SMEM);
    cudaFuncSetAttribute(gemm_mma_kernel<1>, cudaFuncAttributeMaxDynamicSharedMemorySize,
                         (int)GEMM_SMEM);
    cudaFuncSetAttribute(attn_mma_kernel, cudaFuncAttributeMaxDynamicSharedMemorySize,
                         (int)AT_SMEM);

    transpose_split_kernel<<<dim3(32, 16, 16), 256>>>(x, pxtb, pxts);
    wsplit_kernel<<<4096, 256>>>(w_q, w_k, w_v, w_o, pwb, pws);
    rel_split_kernel<<<32, 256>>>(rel_h, rel_w, prhb, prhs, prwb, prws);

    // Combined QKV projection: z = proj*16 + b
    gemm_mma_kernel<0><<<dim3(8, 4, 48), 256, GEMM_SMEM>>>(
        pxtb, pxts, pwb, pws, pq, nullptr, pkb, pks, pvb, pvs);

    attn_mma_kernel<<<dim3(8, 128), 256, AT_SMEM>>>(
        pq, pkb, pks, pvb, pvs, prhb, prhs, prwb, prws, pattb, patts);

    // Final projection (w_o at slot 3)
    const size_t WS3 = (size_t)3 * 512 * 512;
    gemm_mma_kernel<1><<<dim3(8, 4, 16), 256, GEMM_SMEM>>>(
        pattb, patts, pwb + WS3, pws + WS3, out, b_o, nullptr, nullptr, nullptr, nullptr);
}

// round 10
// speedup vs baseline: 2.9496x; 1.1600x over previous
#include <cuda_runtime.h>
#include <cuda_bf16.h>
#include <math.h>
#include <stdint.h>

// Problem: B=16, C=512, NH=8, DK=64, H=W=32, N=1024
// Toolchain targets compute_103 (no 'a'): tcgen05/TMA unusable -> mma.sync path.

// ===========================================================================
// PTX helpers
// ===========================================================================
__device__ __forceinline__ uint32_t smem_u32(const void* p) {
    uint32_t a;
    asm("{ .reg .u64 t; cvta.to.shared.u64 t, %1; cvt.u32.u64 %0, t; }"
        : "=r"(a) : "l"(p));
    return a;
}
__device__ __forceinline__ void cp16(uint32_t dst, const void* src) {
    asm volatile("cp.async.cg.shared.global [%0], [%1], 16;" :: "r"(dst), "l"(src));
}
__device__ __forceinline__ void cp_commit() { asm volatile("cp.async.commit_group;"); }
template <int N>
__device__ __forceinline__ void cp_wait() {
    asm volatile("cp.async.wait_group %0;" :: "n"(N) : "memory");
}
__device__ __forceinline__ void ldsm4(uint32_t* r, uint32_t addr) {
    asm volatile("ldmatrix.sync.aligned.m8n8.x4.shared.b16 {%0,%1,%2,%3}, [%4];"
                 : "=r"(r[0]), "=r"(r[1]), "=r"(r[2]), "=r"(r[3]) : "r"(addr));
}
__device__ __forceinline__ void ldsm4t(uint32_t* r, uint32_t addr) {
    asm volatile("ldmatrix.sync.aligned.m8n8.x4.trans.shared.b16 {%0,%1,%2,%3}, [%4];"
                 : "=r"(r[0]), "=r"(r[1]), "=r"(r[2]), "=r"(r[3]) : "r"(addr));
}
__device__ __forceinline__ void mma_bf16(float* d, const uint32_t* a,
                                         uint32_t b0, uint32_t b1) {
    asm volatile(
        "mma.sync.aligned.m16n8k16.row.col.f32.bf16.bf16.f32 "
        "{%0,%1,%2,%3}, {%4,%5,%6,%7}, {%8,%9}, {%0,%1,%2,%3};"
        : "+f"(d[0]), "+f"(d[1]), "+f"(d[2]), "+f"(d[3])
        : "r"(a[0]), "r"(a[1]), "r"(a[2]), "r"(a[3]), "r"(b0), "r"(b1));
}
__device__ __forceinline__ uint32_t packbf2(float a, float b) {
    __nv_bfloat162 h = __floats2bfloat162_rn(a, b);
    return *reinterpret_cast<uint32_t*>(&h);
}
__device__ __forceinline__ float bff(float v) {
    return __bfloat162float(__float2bfloat16_rn(v));
}

// ===========================================================================
// Device scratch
// ===========================================================================
__device__ float         g_q   [16 * 8 * 64 * 1024];
__device__ __nv_bfloat16 g_kb  [16 * 8 * 64 * 1024];
__device__ __nv_bfloat16 g_ks  [16 * 8 * 64 * 1024];
__device__ __nv_bfloat16 g_vb  [16 * 8 * 64 * 1024];
__device__ __nv_bfloat16 g_vs  [16 * 8 * 64 * 1024];
__device__ __nv_bfloat16 g_xtb [16 * 1024 * 512];
__device__ __nv_bfloat16 g_xts [16 * 1024 * 512];
__device__ __nv_bfloat16 g_attb[16 * 1024 * 512];
__device__ __nv_bfloat16 g_atts[16 * 1024 * 512];
__device__ __nv_bfloat16 g_wb  [4 * 512 * 512];
__device__ __nv_bfloat16 g_ws  [4 * 512 * 512];
// rel tables, bf16 big/small, padded to 64 rows (row 63 = 0): [r][d]
__device__ __nv_bfloat16 g_rhb [64 * 64];
__device__ __nv_bfloat16 g_rhs [64 * 64];
__device__ __nv_bfloat16 g_rwb [64 * 64];
__device__ __nv_bfloat16 g_rws [64 * 64];

// ===========================================================================
// Producers
// ===========================================================================
__global__ __launch_bounds__(256)
void transpose_split_kernel(const float* __restrict__ x,
                            __nv_bfloat16* __restrict__ xtb,
                            __nv_bfloat16* __restrict__ xts)
{
    __shared__ float t[32][33];
    const int b = blockIdx.z, c0 = blockIdx.y * 32, n0 = blockIdx.x * 32;
    const int lx = threadIdx.x & 31, ly = threadIdx.x >> 5;
    const float* xb = x + ((size_t)b * 512 + c0) * 1024 + n0;
#pragma unroll
    for (int r = 0; r < 4; r++)
        t[ly * 4 + r][lx] = xb[(size_t)(ly * 4 + r) * 1024 + lx];
    __syncthreads();
    __nv_bfloat16* ob = xtb + ((size_t)b * 1024 + n0) * 512 + c0;
    __nv_bfloat16* os = xts + ((size_t)b * 1024 + n0) * 512 + c0;
#pragma unroll
    for (int r = 0; r < 4; r++) {
        float v = t[lx][ly * 4 + r];
        __nv_bfloat16 bg = __float2bfloat16_rn(v);
        ob[(size_t)(ly * 4 + r) * 512 + lx] = bg;
        os[(size_t)(ly * 4 + r) * 512 + lx] = __float2bfloat16_rn(v - __bfloat162float(bg));
    }
}

__global__ __launch_bounds__(256)
void wsplit_kernel(const float* __restrict__ w0, const float* __restrict__ w1,
                   const float* __restrict__ w2, const float* __restrict__ w3,
                   __nv_bfloat16* __restrict__ wb, __nv_bfloat16* __restrict__ ws)
{
    int i = blockIdx.x * 256 + threadIdx.x;
    int arr = i >> 18, off = i & 262143;
    const float* src = (arr == 0) ? w0 : (arr == 1) ? w1 : (arr == 2) ? w2 : w3;
    float v = src[off];
    __nv_bfloat16 bg = __float2bfloat16_rn(v);
    wb[i] = bg;
    ws[i] = __float2bfloat16_rn(v - __bfloat162float(bg));
}

__global__ __launch_bounds__(256)
void rel_split_kernel(const float* __restrict__ rel_h, const float* __restrict__ rel_w,
                      __nv_bfloat16* __restrict__ rhb, __nv_bfloat16* __restrict__ rhs,
                      __nv_bfloat16* __restrict__ rwb, __nv_bfloat16* __restrict__ rws)
{
    int i = blockIdx.x * 256 + threadIdx.x;    // 0..8191
    int table = i >> 12, pos = i & 4095;
    int r = pos >> 6, d = pos & 63;
    float v = (r < 63) ? (table == 0 ? rel_h[r * 64 + d] : rel_w[r * 64 + d]) : 0.f;
    __nv_bfloat16 bg = __float2bfloat16_rn(v);
    __nv_bfloat16 sl = __float2bfloat16_rn(v - __bfloat162float(bg));
    if (table == 0) { rhb[pos] = bg; rhs[pos] = sl; }
    else            { rwb[pos] = bg; rws[pos] = sl; }
}

// ===========================================================================
// mma.sync bf16x3 GEMM v3: 3-stage pipeline, 1 sync/chunk.
// Smem: 64B rows (32 bf16 = full BK), XOR seg swizzle seg^((row>>1)&3)
// -> conflict-free ldmatrix. Stage = {A0,A1,B0,B1} x 128row x 64B = 32KB.
// ===========================================================================
static constexpr unsigned GSTAGE = 32768u;
static constexpr unsigned GEMM_SMEM = 3u * GSTAGE;   // 98304

template <int MODE>
__global__ __launch_bounds__(256, 2)
void gemm_mma_kernel(const __nv_bfloat16* __restrict__ Ab_g,
                     const __nv_bfloat16* __restrict__ As_g,
                     const __nv_bfloat16* __restrict__ Wb_g,
                     const __nv_bfloat16* __restrict__ Ws_g,
                     float* __restrict__ out, const float* __restrict__ bias,
                     __nv_bfloat16* __restrict__ kbg, __nv_bfloat16* __restrict__ ksg,
                     __nv_bfloat16* __restrict__ vbg, __nv_bfloat16* __restrict__ vsg)
{
    extern __shared__ unsigned char smraw[];
    const uint32_t sb = smem_u32(smraw);
    const int tid = threadIdx.x, w = tid >> 5, lane = tid & 31;
    const int b = blockIdx.z & 15, proj = blockIdx.z >> 4;
    const int n0 = blockIdx.x * 128, o0 = blockIdx.y * 128;
    const int wm = w & 3, wn = w >> 2;

    const size_t woff = (size_t)proj * 512 * 512 + (size_t)o0 * 512;
    const __nv_bfloat16* srcs[4] = {
        Ab_g + ((size_t)b * 1024 + n0) * 512,
        As_g + ((size_t)b * 1024 + n0) * 512,
        Wb_g + woff, Ws_g + woff };

    float acc[2][8][4];
#pragma unroll
    for (int t = 0; t < 2; t++)
#pragma unroll
        for (int j = 0; j < 8; j++)
#pragma unroll
            for (int e = 0; e < 4; e++) acc[t][j][e] = 0.f;

    auto load_chunk = [&](int c, uint32_t stage) {
#pragma unroll
        for (int l = 0; l < 8; l++) {
            int flat = tid + l * 256;        // 0..2047
            int arr  = flat >> 9;            // A0,A1,B0,B1
            int sub  = flat & 511;
            int row  = sub >> 2;
            int seg  = sub & 3;
            uint32_t dst = stage + (uint32_t)arr * 8192u + (uint32_t)row * 64u
                         + (uint32_t)((seg ^ ((row >> 1) & 3)) * 16);
            cp16(dst, srcs[arr] + (size_t)row * 512 + c * 32 + seg * 8);
        }
    };

    const int rl   = lane & 15;
    const int half = lane >> 4;

    auto compute = [&](uint32_t stage) {
#pragma unroll
        for (int kk = 0; kk < 2; kk++) {
            uint32_t a_f[2][2][4];
            uint32_t b_f[2][4][4];
#pragma unroll
            for (int term = 0; term < 2; term++) {
#pragma unroll
                for (int t = 0; t < 2; t++) {
                    int row = wm * 32 + t * 16 + rl;
                    uint32_t seg = (uint32_t)((2 * kk + half) ^ ((row >> 1) & 3));
                    ldsm4(a_f[term][t], stage + (uint32_t)term * 8192u
                                        + (uint32_t)row * 64u + seg * 16u);
                }
#pragma unroll
                for (int g = 0; g < 4; g++) {
                    int row = wn * 64 + g * 16 + rl;
                    uint32_t seg = (uint32_t)((2 * kk + half) ^ ((row >> 1) & 3));
                    ldsm4(b_f[term][g], stage + 16384u + (uint32_t)term * 8192u
                                        + (uint32_t)row * 64u + seg * 16u);
                }
            }
#pragma unroll
            for (int t = 0; t < 2; t++)
#pragma unroll
                for (int j = 0; j < 8; j++) {
                    int g = j >> 1, jj = j & 1;
                    mma_bf16(acc[t][j], a_f[0][t], b_f[0][g][jj], b_f[0][g][jj + 2]);
                    mma_bf16(acc[t][j], a_f[0][t], b_f[1][g][jj], b_f[1][g][jj + 2]);
                    mma_bf16(acc[t][j], a_f[1][t], b_f[0][g][jj], b_f[0][g][jj + 2]);
                }
        }
    };

    load_chunk(0, sb); cp_commit();
    load_chunk(1, sb + GSTAGE); cp_commit();
    for (int c = 0; c < 16; c++) {
        if (c < 15) cp_wait<1>(); else cp_wait<0>();
        __syncthreads();
        if (c + 2 < 16) {
            load_chunk(c + 2, sb + (uint32_t)((c + 2) % 3) * GSTAGE);
            cp_commit();
        }
        compute(sb + (uint32_t)(c % 3) * GSTAGE);
    }
    __syncthreads();

    float* Ds = reinterpret_cast<float*>(smraw);    // [64][132]
    const int grp = lane >> 2, tig = lane & 3;
#pragma unroll
    for (int p = 0; p < 2; p++) {
        if (wn == p) {
#pragma unroll
            for (int t = 0; t < 2; t++)
#pragma unroll
                for (int j = 0; j < 8; j++) {
                    int oc = j * 8 + 2 * tig;
                    int mb = wm * 32 + t * 16 + grp;
                    Ds[oc * 132 + mb]           = acc[t][j][0];
                    Ds[(oc + 1) * 132 + mb]     = acc[t][j][1];
                    Ds[oc * 132 + mb + 8]       = acc[t][j][2];
                    Ds[(oc + 1) * 132 + mb + 8] = acc[t][j][3];
                }
        }
        __syncthreads();
#pragma unroll
        for (int l = 0; l < 8; l++) {
            int idx  = tid + l * 256;
            int row  = idx >> 5;
            int col4 = (idx & 31) * 4;
            float4 v = *reinterpret_cast<float4*>(&Ds[row * 132 + col4]);
            int o = o0 + p * 64 + row;
            if (MODE == 1) {
                float bo = __ldg(&bias[o]);
                v.x += bo; v.y += bo; v.z += bo; v.w += bo;
                *reinterpret_cast<float4*>(
                    &out[(size_t)(b * 512 + o) * 1024 + n0 + col4]) = v;
            } else {
                int hh = o & 7, dd = o >> 3;
                size_t gi = (size_t)((b * 8 + hh) * 64 + dd) * 1024 + n0 + col4;
                if (proj == 0) {
                    *reinterpret_cast<float4*>(&out[gi]) = v;
                } else {
                    __nv_bfloat16* ob = (proj == 1) ? kbg : vbg;
                    __nv_bfloat16* os = (proj == 1) ? ksg : vsg;
                    float bg0 = bff(v.x), bg1 = bff(v.y), bg2 = bff(v.z), bg3 = bff(v.w);
                    uint2 pb = make_uint2(packbf2(bg0, bg1), packbf2(bg2, bg3));
                    uint2 ps = make_uint2(packbf2(v.x - bg0, v.y - bg1),
                                          packbf2(v.z - bg2, v.w - bg3));
                    *reinterpret_cast<uint2*>(&ob[gi]) = pb;
                    *reinterpret_cast<uint2*>(&os[gi]) = ps;
                }
            }
        }
        __syncthreads();
    }
}

// ===========================================================================
// Flash attention v3: Tq=128, 8 warps, 3-stage K/V pipeline (1 sync/tile),
// Q fragments hoisted to registers, fused mma bias tables, base-2 softmax.
// Smem: QB/QS [128][72]bf16; 3 KV stages of {KB,KS,VB,VS} 64x144B; LH/LW fp32.
// ===========================================================================
static constexpr unsigned AT_QB    = 0u;
static constexpr unsigned AT_QS    = 18432u;
static constexpr unsigned AT_ST0   = 36864u;
static constexpr unsigned AT_STSZ  = 36864u;
static constexpr unsigned AT_LH    = AT_ST0 + 3u * AT_STSZ;   // 147456
static constexpr unsigned AT_LW    = AT_LH + 32768u;          // 180224
static constexpr unsigned AT_SMEM  = AT_LW + 32768u;          // 212992

__global__ __launch_bounds__(256)
void attn_mma_kernel(const float* __restrict__ q,
                     const __nv_bfloat16* __restrict__ kbg, const __nv_bfloat16* __restrict__ ksg,
                     const __nv_bfloat16* __restrict__ vbg, const __nv_bfloat16* __restrict__ vsg,
                     const __nv_bfloat16* __restrict__ rhb, const __nv_bfloat16* __restrict__ rhs,
                     const __nv_bfloat16* __restrict__ rwb, const __nv_bfloat16* __restrict__ rws,
                     __nv_bfloat16* __restrict__ attb, __nv_bfloat16* __restrict__ atts)
{
    extern __shared__ unsigned char smraw[];
    const uint32_t sb = smem_u32(smraw);
    const uint32_t Qb = sb + AT_QB, Qs = sb + AT_QS;
    __nv_bfloat16* Qbp = reinterpret_cast<__nv_bfloat16*>(smraw + AT_QB);
    __nv_bfloat16* Qsp = reinterpret_cast<__nv_bfloat16*>(smraw + AT_QS);
    float* Lh = reinterpret_cast<float*>(smraw + AT_LH);
    float* Lw = reinterpret_cast<float*>(smraw + AT_LW);

    const int bh = blockIdx.y, b = bh >> 3, h = bh & 7;
    const int q0 = blockIdx.x * 128;
    const int tid = threadIdx.x, w = tid >> 5, lane = tid & 31;
    const int g = lane >> 2, t = lane & 3;
    const int rl = lane & 15, byt = (lane >> 4) * 16;

    const float* qb_g = q + (size_t)bh * 64 * 1024;

    // ---- Q load + bf16 split ----
#pragma unroll
    for (int l = 0; l < 32; l++) {
        int flat = tid + l * 256;
        int d = flat >> 7, i = flat & 127;
        float v = qb_g[(size_t)d * 1024 + q0 + i];
        __nv_bfloat16 bg = __float2bfloat16_rn(v);
        Qbp[i * 72 + d] = bg;
        Qsp[i * 72 + d] = __float2bfloat16_rn(v - __bfloat162float(bg));
    }

    // ---- rel tables into stage0 ----
    {
        const __nv_bfloat16* relp[4] = { rhb, rhs, rwb, rws };
#pragma unroll
        for (int l = 0; l < 8; l++) {
            int flat = tid + l * 256;
            int arr = flat >> 9, sub = flat & 511;
            int r = sub >> 3, seg = sub & 7;
            cp16(sb + AT_ST0 + (uint32_t)arr * 9216u + (uint32_t)r * 144u + (uint32_t)seg * 16u,
                 relp[arr] + r * 64 + seg * 8);
        }
    }
    cp_commit();
    cp_wait<0>();
    __syncthreads();

    // ---- hoisted Q fragments (used by bias mma AND all 16 S tiles) ----
    uint32_t qB[4][4], qS[4][4];
#pragma unroll
    for (int kk = 0; kk < 4; kk++) {
        ldsm4(qB[kk], Qb + (uint32_t)(w * 16 + rl) * 144u + (uint32_t)kk * 32u + byt);
        ldsm4(qS[kk], Qs + (uint32_t)(w * 16 + rl) * 144u + (uint32_t)kk * 32u + byt);
    }

    // per-row constants (2 rows per thread)
    const int lr0 = w * 16 + g, lr1 = lr0 + 8;
    const int nq0 = q0 + lr0, nq1 = q0 + lr1;
    const int x0 = nq0 >> 5, y0 = nq0 & 31;
    const int x1 = nq1 >> 5, y1 = nq1 & 31;

    // ---- bias tables via mma: Lh/Lw = Q @ rel^T (bf16x3) ----
    {
        float sl[2][8][4];
#pragma unroll
        for (int tb = 0; tb < 2; tb++)
#pragma unroll
            for (int nb = 0; nb < 8; nb++)
#pragma unroll
                for (int e = 0; e < 4; e++) sl[tb][nb][e] = 0.f;

#pragma unroll
        for (int kk = 0; kk < 4; kk++) {
#pragma unroll
            for (int tb = 0; tb < 2; tb++) {
#pragma unroll
                for (int np = 0; np < 4; np++) {
                    uint32_t radr = sb + AT_ST0 + (uint32_t)tb * 18432u
                                  + (uint32_t)(np * 16 + rl) * 144u + (uint32_t)kk * 32u + byt;
                    uint32_t rB[4], rS[4];
                    ldsm4(rB, radr);
                    ldsm4(rS, radr + 9216u);
#pragma unroll
                    for (int jj = 0; jj < 2; jj++) {
                        int nb = np * 2 + jj;
                        mma_bf16(sl[tb][nb], qB[kk], rB[jj], rB[jj + 2]);
                        mma_bf16(sl[tb][nb], qB[kk], rS[jj], rS[jj + 2]);
                        mma_bf16(sl[tb][nb], qS[kk], rB[jj], rB[jj + 2]);
                    }
                }
            }
        }
#pragma unroll
        for (int nb = 0; nb < 8; nb++) {
            int c0 = nb * 8 + 2 * t;
            Lh[lr0 * 64 + c0]     = sl[0][nb][0];
            Lh[lr0 * 64 + c0 + 1] = sl[0][nb][1];
            Lh[lr1 * 64 + c0]     = sl[0][nb][2];
            Lh[lr1 * 64 + c0 + 1] = sl[0][nb][3];
            Lw[lr0 * 64 + c0]     = sl[1][nb][0];
            Lw[lr0 * 64 + c0 + 1] = sl[1][nb][1];
            Lw[lr1 * 64 + c0]     = sl[1][nb][2];
            Lw[lr1 * 64 + c0 + 1] = sl[1][nb][3];
        }
    }
    __syncthreads();   // Lh/Lw visible; stage0 free for K/V

    // ---- main flash loop, 3-stage K/V pipeline ----
    const __nv_bfloat16* kvp[4] = { kbg, ksg, vbg, vsg };
    auto load_kv = [&](int kt, uint32_t stage) {
#pragma unroll
        for (int l = 0; l < 8; l++) {
            int flat = tid + l * 256;
            int arr = flat >> 9, sub = flat & 511;
            int d = sub >> 3, seg = sub & 7;
            cp16(stage + (uint32_t)arr * 9216u + (uint32_t)d * 144u + (uint32_t)seg * 16u,
                 kvp[arr] + ((size_t)bh * 64 + d) * 1024 + kt * 64 + seg * 8);
        }
    };

    float m0v = -1e30f, m1v = -1e30f, l0 = 0.f, l1 = 0.f;
    float o[8][4];
#pragma unroll
    for (int nd = 0; nd < 8; nd++)
#pragma unroll
        for (int e = 0; e < 4; e++) o[nd][e] = 0.f;

    const float SC = 0.18033688f;    // 0.125 * log2(e)

    load_kv(0, sb + AT_ST0); cp_commit();
    load_kv(1, sb + AT_ST0 + AT_STSZ); cp_commit();

    for (int kt = 0; kt < 16; kt++) {
        if (kt < 15) cp_wait<1>(); else cp_wait<0>();
        __syncthreads();
        if (kt + 2 < 16) {
            load_kv(kt + 2, sb + AT_ST0 + (uint32_t)((kt + 2) % 3) * AT_STSZ);
            cp_commit();
        }
        const uint32_t stage = sb + AT_ST0 + (uint32_t)(kt % 3) * AT_STSZ;
        const uint32_t Kb = stage, Vb = stage + 18432u;

        // ---- S = Q K^T (3 bf16 terms) ----
        float s[8][4];
#pragma unroll
        for (int nb = 0; nb < 8; nb++)
#pragma unroll
            for (int e = 0; e < 4; e++) s[nb][e] = 0.f;

#pragma unroll
        for (int kk = 0; kk < 4; kk++) {
#pragma unroll
            for (int np = 0; np < 4; np++) {
                uint32_t kadr = (uint32_t)(kk * 16 + rl) * 144u
                              + (uint32_t)(np * 16 + (lane >> 4) * 8) * 2u;
                uint32_t bB[4], bS[4];
                ldsm4t(bB, Kb + kadr);
                ldsm4t(bS, Kb + 9216u + kadr);
                mma_bf16(s[2 * np],     qB[kk], bB[0], bB[1]);
                mma_bf16(s[2 * np],     qB[kk], bS[0], bS[1]);
                mma_bf16(s[2 * np],     qS[kk], bB[0], bB[1]);
                mma_bf16(s[2 * np + 1], qB[kk], bB[2], bB[3]);
                mma_bf16(s[2 * np + 1], qB[kk], bS[2], bS[3]);
                mma_bf16(s[2 * np + 1], qS[kk], bB[2], bB[3]);
            }
        }

        // ---- bias + base-2 online softmax ----
        const float* pLh0 = &Lh[lr0 * 64 + kt * 2 + 31 - x0];
        const float* pLh1 = &Lh[lr1 * 64 + kt * 2 + 31 - x1];
        const float lh00 = pLh0[0], lh01 = pLh0[1];
        const float lh10 = pLh1[0], lh11 = pLh1[1];
        const float* pLw0 = &Lw[lr0 * 64 + 31 - y0 + 2 * t];
        const float* pLw1 = &Lw[lr1 * 64 + 31 - y1 + 2 * t];
        float bw0[8], bw1[8];
#pragma unroll
        for (int c = 0; c < 4; c++) {
            bw0[2 * c]     = pLw0[c * 8];
            bw0[2 * c + 1] = pLw0[c * 8 + 1];
            bw1[2 * c]     = pLw1[c * 8];
            bw1[2 * c + 1] = pLw1[c * 8 + 1];
        }

        float mx0 = -1e30f, mx1 = -1e30f;
#pragma unroll
        for (int nb = 0; nb < 8; nb++) {
            float lv0 = (nb < 4) ? lh00 : lh01;
            float lv1 = (nb < 4) ? lh10 : lh11;
            int ci = (nb & 3) * 2;
            s[nb][0] = (s[nb][0] + lv0 + bw0[ci])     * SC;
            s[nb][1] = (s[nb][1] + lv0 + bw0[ci + 1]) * SC;
            s[nb][2] = (s[nb][2] + lv1 + bw1[ci])     * SC;
            s[nb][3] = (s[nb][3] + lv1 + bw1[ci + 1]) * SC;
            mx0 = fmaxf(mx0, fmaxf(s[nb][0], s[nb][1]));
            mx1 = fmaxf(mx1, fmaxf(s[nb][2], s[nb][3]));
        }
        mx0 = fmaxf(mx0, __shfl_xor_sync(0xffffffffu, mx0, 1));
        mx0 = fmaxf(mx0, __shfl_xor_sync(0xffffffffu, mx0, 2));
        mx1 = fmaxf(mx1, __shfl_xor_sync(0xffffffffu, mx1, 1));
        mx1 = fmaxf(mx1, __shfl_xor_sync(0xffffffffu, mx1, 2));

        float mn0 = fmaxf(m0v, mx0), mn1 = fmaxf(m1v, mx1);
        float al0 = exp2f(m0v - mn0), al1 = exp2f(m1v - mn1);
        m0v = mn0; m1v = mn1;

        float rs0 = 0.f, rs1 = 0.f;
#pragma unroll
        for (int nb = 0; nb < 8; nb++) {
            s[nb][0] = exp2f(s[nb][0] - mn0);
            s[nb][1] = exp2f(s[nb][1] - mn0);
            s[nb][2] = exp2f(s[nb][2] - mn1);
            s[nb][3] = exp2f(s[nb][3] - mn1);
            rs0 += s[nb][0] + s[nb][1];
            rs1 += s[nb][2] + s[nb][3];
        }
        rs0 += __shfl_xor_sync(0xffffffffu, rs0, 1);
        rs0 += __shfl_xor_sync(0xffffffffu, rs0, 2);
        rs1 += __shfl_xor_sync(0xffffffffu, rs1, 1);
        rs1 += __shfl_xor_sync(0xffffffffu, rs1, 2);
        l0 = l0 * al0 + rs0;
        l1 = l1 * al1 + rs1;

#pragma unroll
        for (int nd = 0; nd < 8; nd++) {
            o[nd][0] *= al0; o[nd][1] *= al0;
            o[nd][2] *= al1; o[nd][3] *= al1;
        }

        // ---- O += P V (3 bf16 terms) ----
#pragma unroll
        for (int kk = 0; kk < 4; kk++) {
            float* p0 = s[2 * kk];
            float* p1 = s[2 * kk + 1];
            float b00 = bff(p0[0]), b01 = bff(p0[1]), b02 = bff(p0[2]), b03 = bff(p0[3]);
            float b10 = bff(p1[0]), b11 = bff(p1[1]), b12 = bff(p1[2]), b13 = bff(p1[3]);
            uint32_t pB[4] = { packbf2(b00, b01), packbf2(b02, b03),
                               packbf2(b10, b11), packbf2(b12, b13) };
            uint32_t pS[4] = { packbf2(p0[0] - b00, p0[1] - b01),
                               packbf2(p0[2] - b02, p0[3] - b03),
                               packbf2(p1[0] - b10, p1[1] - b11),
                               packbf2(p1[2] - b12, p1[3] - b13) };
#pragma unroll
            for (int nd = 0; nd < 4; nd++) {
                uint32_t vadr = (uint32_t)(nd * 16 + rl) * 144u + (uint32_t)kk * 32u + byt;
                uint32_t vB[4], vS[4];
                ldsm4(vB, Vb + vadr);
                ldsm4(vS, Vb + 9216u + vadr);
                mma_bf16(o[2 * nd],     pB, vB[0], vB[2]);
                mma_bf16(o[2 * nd],     pB, vS[0], vS[2]);
                mma_bf16(o[2 * nd],     pS, vB[0], vB[2]);
                mma_bf16(o[2 * nd + 1], pB, vB[1], vB[3]);
                mma_bf16(o[2 * nd + 1], pB, vS[1], vS[3]);
                mma_bf16(o[2 * nd + 1], pS, vB[1], vB[3]);
            }
        }
    }

    // ---- epilogue: att[b][n][c] bf16 big/small, c = h*64 + d ----
    const float inv0 = 1.0f / l0, inv1 = 1.0f / l1;
    const size_t base0 = ((size_t)(b * 1024 + nq0)) * 512 + h * 64;
    const size_t base1 = ((size_t)(b * 1024 + nq1)) * 512 + h * 64;
#pragma unroll
    for (int nd = 0; nd < 8; nd++) {
        int d = nd * 8 + 2 * t;
        float v0 = o[nd][0] * inv0, v1 = o[nd][1] * inv0;
        float v2 = o[nd][2] * inv1, v3 = o[nd][3] * inv1;
        float g0 = bff(v0), g1 = bff(v1), g2 = bff(v2), g3 = bff(v3);
        *reinterpret_cast<uint32_t*>(&attb[base0 + d]) = packbf2(g0, g1);
        *reinterpret_cast<uint32_t*>(&atts[base0 + d]) = packbf2(v0 - g0, v1 - g1);
        *reinterpret_cast<uint32_t*>(&attb[base1 + d]) = packbf2(g2, g3);
        *reinterpret_cast<uint32_t*>(&atts[base1 + d]) = packbf2(v2 - g2, v3 - g3);
    }
}

// ===========================================================================
// Launch
// ===========================================================================
extern "C" void kernel_launch(void* const* d_in, const int* in_sizes, int n_in,
                              void* d_out, int out_size)
{
    const float* x     = (const float*)d_in[0];
    const float* w_q   = (const float*)d_in[1];
    const float* w_k   = (const float*)d_in[2];
    const float* w_v   = (const float*)d_in[3];
    const float* w_o   = (const float*)d_in[4];
    const float* b_o   = (const float*)d_in[5];
    const float* rel_h = (const float*)d_in[6];
    const float* rel_w = (const float*)d_in[7];
    float* out = (float*)d_out;

    float *pq;
    __nv_bfloat16 *pkb, *pks, *pvb, *pvs, *pxtb, *pxts, *pattb, *patts, *pwb, *pws;
    __nv_bfloat16 *prhb, *prhs, *prwb, *prws;
    cudaGetSymbolAddress((void**)&pq,    g_q);
    cudaGetSymbolAddress((void**)&pkb,   g_kb);
    cudaGetSymbolAddress((void**)&pks,   g_ks);
    cudaGetSymbolAddress((void**)&pvb,   g_vb);
    cudaGetSymbolAddress((void**)&pvs,   g_vs);
    cudaGetSymbolAddress((void**)&pxtb,  g_xtb);
    cudaGetSymbolAddress((void**)&pxts,  g_xts);
    cudaGetSymbolAddress((void**)&pattb, g_attb);
    cudaGetSymbolAddress((void**)&patts, g_atts);
    cudaGetSymbolAddress((void**)&pwb,   g_wb);
    cudaGetSymbolAddress((void**)&pws,   g_ws);
    cudaGetSymbolAddress((void**)&prhb,  g_rhb);
    cudaGetSymbolAddress((void**)&prhs,  g_rhs);
    cudaGetSymbolAddress((void**)&prwb,  g_rwb);
    cudaGetSymbolAddress((void**)&prws,  g_rws);

    cudaFuncSetAttribute(gemm_mma_kernel<0>, cudaFuncAttributeMaxDynamicSharedMemorySize,
                         (int)GEMM_SMEM);
    cudaFuncSetAttribute(gemm_mma_kernel<1>, cudaFuncAttributeMaxDynamicSharedMemorySize,
                         (int)GEMM_SMEM);
    cudaFuncSetAttribute(attn_mma_kernel, cudaFuncAttributeMaxDynamicSharedMemorySize,
                         (int)AT_SMEM);

    transpose_split_kernel<<<dim3(32, 16, 16), 256>>>(x, pxtb, pxts);
    wsplit_kernel<<<4096, 256>>>(w_q, w_k, w_v, w_o, pwb, pws);
    rel_split_kernel<<<32, 256>>>(rel_h, rel_w, prhb, prhs, prwb, prws);

    // Combined QKV projection: z = proj*16 + b
    gemm_mma_kernel<0><<<dim3(8, 4, 48), 256, GEMM_SMEM>>>(
        pxtb, pxts, pwb, pws, pq, nullptr, pkb, pks, pvb, pvs);

    attn_mma_kernel<<<dim3(8, 128), 256, AT_SMEM>>>(
        pq, pkb, pks, pvb, pvs, prhb, prhs, prwb, prws, pattb, patts);

    // Final projection (w_o at slot 3)
    const size_t WS3 = (size_t)3 * 512 * 512;
    gemm_mma_kernel<1><<<dim3(8, 4, 16), 256, GEMM_SMEM>>>(
        pattb, patts, pwb + WS3, pws + WS3, out, b_o, nullptr, nullptr, nullptr, nullptr);
}

// round 11
// speedup vs baseline: 3.4678x; 1.1757x over previous
#include <cuda_runtime.h>
#include <cuda_bf16.h>
#include <cuda_fp16.h>
#include <math.h>
#include <stdint.h>

// Problem: B=16, C=512, NH=8, DK=64, H=W=32, N=1024
// Toolchain targets compute_103 (no 'a'): tcgen05/TMA unusable -> mma.sync path.

// ===========================================================================
// PTX helpers
// ===========================================================================
__device__ __forceinline__ uint32_t smem_u32(const void* p) {
    uint32_t a;
    asm("{ .reg .u64 t; cvta.to.shared.u64 t, %1; cvt.u32.u64 %0, t; }"
        : "=r"(a) : "l"(p));
    return a;
}
__device__ __forceinline__ void cp16(uint32_t dst, const void* src) {
    asm volatile("cp.async.cg.shared.global [%0], [%1], 16;" :: "r"(dst), "l"(src));
}
__device__ __forceinline__ void cp_commit() { asm volatile("cp.async.commit_group;"); }
template <int N>
__device__ __forceinline__ void cp_wait() {
    asm volatile("cp.async.wait_group %0;" :: "n"(N) : "memory");
}
__device__ __forceinline__ void ldsm4(uint32_t* r, uint32_t addr) {
    asm volatile("ldmatrix.sync.aligned.m8n8.x4.shared.b16 {%0,%1,%2,%3}, [%4];"
                 : "=r"(r[0]), "=r"(r[1]), "=r"(r[2]), "=r"(r[3]) : "r"(addr));
}
__device__ __forceinline__ void ldsm4t(uint32_t* r, uint32_t addr) {
    asm volatile("ldmatrix.sync.aligned.m8n8.x4.trans.shared.b16 {%0,%1,%2,%3}, [%4];"
                 : "=r"(r[0]), "=r"(r[1]), "=r"(r[2]), "=r"(r[3]) : "r"(addr));
}
__device__ __forceinline__ void mma_bf16(float* d, const uint32_t* a,
                                         uint32_t b0, uint32_t b1) {
    asm volatile(
        "mma.sync.aligned.m16n8k16.row.col.f32.bf16.bf16.f32 "
        "{%0,%1,%2,%3}, {%4,%5,%6,%7}, {%8,%9}, {%0,%1,%2,%3};"
        : "+f"(d[0]), "+f"(d[1]), "+f"(d[2]), "+f"(d[3])
        : "r"(a[0]), "r"(a[1]), "r"(a[2]), "r"(a[3]), "r"(b0), "r"(b1));
}
__device__ __forceinline__ void mma_f16(float* d, const uint32_t* a,
                                        uint32_t b0, uint32_t b1) {
    asm volatile(
        "mma.sync.aligned.m16n8k16.row.col.f32.f16.f16.f32 "
        "{%0,%1,%2,%3}, {%4,%5,%6,%7}, {%8,%9}, {%0,%1,%2,%3};"
        : "+f"(d[0]), "+f"(d[1]), "+f"(d[2]), "+f"(d[3])
        : "r"(a[0]), "r"(a[1]), "r"(a[2]), "r"(a[3]), "r"(b0), "r"(b1));
}
__device__ __forceinline__ uint32_t packbf2(float a, float b) {
    __nv_bfloat162 h = __floats2bfloat162_rn(a, b);
    return *reinterpret_cast<uint32_t*>(&h);
}
__device__ __forceinline__ uint32_t packh2(float a, float b) {
    __half2 h = __floats2half2_rn(a, b);
    return *reinterpret_cast<uint32_t*>(&h);
}
__device__ __forceinline__ float bff(float v) {
    return __bfloat162float(__float2bfloat16_rn(v));
}
__device__ __forceinline__ float hff(float v) {
    return __half2float(__float2half_rn(v));
}

// ===========================================================================
// Device scratch
// ===========================================================================
__device__ float         g_q   [16 * 8 * 64 * 1024];
__device__ __nv_bfloat16 g_kb  [16 * 8 * 64 * 1024];
__device__ __nv_bfloat16 g_ks  [16 * 8 * 64 * 1024];
__device__ __half        g_vb  [16 * 8 * 64 * 1024];   // V now fp16 big/small
__device__ __half        g_vs  [16 * 8 * 64 * 1024];
__device__ __nv_bfloat16 g_xtb [16 * 1024 * 512];
__device__ __nv_bfloat16 g_xts [16 * 1024 * 512];
__device__ __nv_bfloat16 g_attb[16 * 1024 * 512];
__device__ __nv_bfloat16 g_atts[16 * 1024 * 512];
__device__ __nv_bfloat16 g_wb  [4 * 512 * 512];
__device__ __nv_bfloat16 g_ws  [4 * 512 * 512];
// rel tables, bf16 big/small, padded to 64 rows (row 63 = 0): [r][d]
__device__ __nv_bfloat16 g_rhb [64 * 64];
__device__ __nv_bfloat16 g_rhs [64 * 64];
__device__ __nv_bfloat16 g_rwb [64 * 64];
__device__ __nv_bfloat16 g_rws [64 * 64];

// ===========================================================================
// Producers
// ===========================================================================
__global__ __launch_bounds__(256)
void transpose_split_kernel(const float* __restrict__ x,
                            __nv_bfloat16* __restrict__ xtb,
                            __nv_bfloat16* __restrict__ xts)
{
    __shared__ float t[32][33];
    const int b = blockIdx.z, c0 = blockIdx.y * 32, n0 = blockIdx.x * 32;
    const int lx = threadIdx.x & 31, ly = threadIdx.x >> 5;
    const float* xb = x + ((size_t)b * 512 + c0) * 1024 + n0;
#pragma unroll
    for (int r = 0; r < 4; r++)
        t[ly * 4 + r][lx] = xb[(size_t)(ly * 4 + r) * 1024 + lx];
    __syncthreads();
    __nv_bfloat16* ob = xtb + ((size_t)b * 1024 + n0) * 512 + c0;
    __nv_bfloat16* os = xts + ((size_t)b * 1024 + n0) * 512 + c0;
#pragma unroll
    for (int r = 0; r < 4; r++) {
        float v = t[lx][ly * 4 + r];
        __nv_bfloat16 bg = __float2bfloat16_rn(v);
        ob[(size_t)(ly * 4 + r) * 512 + lx] = bg;
        os[(size_t)(ly * 4 + r) * 512 + lx] = __float2bfloat16_rn(v - __bfloat162float(bg));
    }
}

__global__ __launch_bounds__(256)
void wsplit_kernel(const float* __restrict__ w0, const float* __restrict__ w1,
                   const float* __restrict__ w2, const float* __restrict__ w3,
                   __nv_bfloat16* __restrict__ wb, __nv_bfloat16* __restrict__ ws)
{
    int i = blockIdx.x * 256 + threadIdx.x;
    int arr = i >> 18, off = i & 262143;
    const float* src = (arr == 0) ? w0 : (arr == 1) ? w1 : (arr == 2) ? w2 : w3;
    float v = src[off];
    __nv_bfloat16 bg = __float2bfloat16_rn(v);
    wb[i] = bg;
    ws[i] = __float2bfloat16_rn(v - __bfloat162float(bg));
}

__global__ __launch_bounds__(256)
void rel_split_kernel(const float* __restrict__ rel_h, const float* __restrict__ rel_w,
                      __nv_bfloat16* __restrict__ rhb, __nv_bfloat16* __restrict__ rhs,
                      __nv_bfloat16* __restrict__ rwb, __nv_bfloat16* __restrict__ rws)
{
    int i = blockIdx.x * 256 + threadIdx.x;    // 0..8191
    int table = i >> 12, pos = i & 4095;
    int r = pos >> 6, d = pos & 63;
    float v = (r < 63) ? (table == 0 ? rel_h[r * 64 + d] : rel_w[r * 64 + d]) : 0.f;
    __nv_bfloat16 bg = __float2bfloat16_rn(v);
    __nv_bfloat16 sl = __float2bfloat16_rn(v - __bfloat162float(bg));
    if (table == 0) { rhb[pos] = bg; rhs[pos] = sl; }
    else            { rwb[pos] = bg; rws[pos] = sl; }
}

// ===========================================================================
// mma.sync bf16x3 GEMM v3: 3-stage pipeline, 1 sync/chunk. (unchanged except
// proj==2 epilogue now emits fp16 big/small V)
// ===========================================================================
static constexpr unsigned GSTAGE = 32768u;
static constexpr unsigned GEMM_SMEM = 3u * GSTAGE;   // 98304

template <int MODE>
__global__ __launch_bounds__(256, 2)
void gemm_mma_kernel(const __nv_bfloat16* __restrict__ Ab_g,
                     const __nv_bfloat16* __restrict__ As_g,
                     const __nv_bfloat16* __restrict__ Wb_g,
                     const __nv_bfloat16* __restrict__ Ws_g,
                     float* __restrict__ out, const float* __restrict__ bias,
                     __nv_bfloat16* __restrict__ kbg, __nv_bfloat16* __restrict__ ksg,
                     __half* __restrict__ vbg, __half* __restrict__ vsg)
{
    extern __shared__ unsigned char smraw[];
    const uint32_t sb = smem_u32(smraw);
    const int tid = threadIdx.x, w = tid >> 5, lane = tid & 31;
    const int b = blockIdx.z & 15, proj = blockIdx.z >> 4;
    const int n0 = blockIdx.x * 128, o0 = blockIdx.y * 128;
    const int wm = w & 3, wn = w >> 2;

    const size_t woff = (size_t)proj * 512 * 512 + (size_t)o0 * 512;
    const __nv_bfloat16* srcs[4] = {
        Ab_g + ((size_t)b * 1024 + n0) * 512,
        As_g + ((size_t)b * 1024 + n0) * 512,
        Wb_g + woff, Ws_g + woff };

    float acc[2][8][4];
#pragma unroll
    for (int t = 0; t < 2; t++)
#pragma unroll
        for (int j = 0; j < 8; j++)
#pragma unroll
            for (int e = 0; e < 4; e++) acc[t][j][e] = 0.f;

    auto load_chunk = [&](int c, uint32_t stage) {
#pragma unroll
        for (int l = 0; l < 8; l++) {
            int flat = tid + l * 256;        // 0..2047
            int arr  = flat >> 9;            // A0,A1,B0,B1
            int sub  = flat & 511;
            int row  = sub >> 2;
            int seg  = sub & 3;
            uint32_t dst = stage + (uint32_t)arr * 8192u + (uint32_t)row * 64u
                         + (uint32_t)((seg ^ ((row >> 1) & 3)) * 16);
            cp16(dst, srcs[arr] + (size_t)row * 512 + c * 32 + seg * 8);
        }
    };

    const int rl   = lane & 15;
    const int half = lane >> 4;

    auto compute = [&](uint32_t stage) {
#pragma unroll
        for (int kk = 0; kk < 2; kk++) {
            uint32_t a_f[2][2][4];
            uint32_t b_f[2][4][4];
#pragma unroll
            for (int term = 0; term < 2; term++) {
#pragma unroll
                for (int t = 0; t < 2; t++) {
                    int row = wm * 32 + t * 16 + rl;
                    uint32_t seg = (uint32_t)((2 * kk + half) ^ ((row >> 1) & 3));
                    ldsm4(a_f[term][t], stage + (uint32_t)term * 8192u
                                        + (uint32_t)row * 64u + seg * 16u);
                }
#pragma unroll
                for (int g = 0; g < 4; g++) {
                    int row = wn * 64 + g * 16 + rl;
                    uint32_t seg = (uint32_t)((2 * kk + half) ^ ((row >> 1) & 3));
                    ldsm4(b_f[term][g], stage + 16384u + (uint32_t)term * 8192u
                                        + (uint32_t)row * 64u + seg * 16u);
                }
            }
#pragma unroll
            for (int t = 0; t < 2; t++)
#pragma unroll
                for (int j = 0; j < 8; j++) {
                    int g = j >> 1, jj = j & 1;
                    mma_bf16(acc[t][j], a_f[0][t], b_f[0][g][jj], b_f[0][g][jj + 2]);
                    mma_bf16(acc[t][j], a_f[0][t], b_f[1][g][jj], b_f[1][g][jj + 2]);
                    mma_bf16(acc[t][j], a_f[1][t], b_f[0][g][jj], b_f[0][g][jj + 2]);
                }
        }
    };

    load_chunk(0, sb); cp_commit();
    load_chunk(1, sb + GSTAGE); cp_commit();
    for (int c = 0; c < 16; c++) {
        if (c < 15) cp_wait<1>(); else cp_wait<0>();
        __syncthreads();
        if (c + 2 < 16) {
            load_chunk(c + 2, sb + (uint32_t)((c + 2) % 3) * GSTAGE);
            cp_commit();
        }
        compute(sb + (uint32_t)(c % 3) * GSTAGE);
    }
    __syncthreads();

    float* Ds = reinterpret_cast<float*>(smraw);    // [64][132]
    const int grp = lane >> 2, tig = lane & 3;
#pragma unroll
    for (int p = 0; p < 2; p++) {
        if (wn == p) {
#pragma unroll
            for (int t = 0; t < 2; t++)
#pragma unroll
                for (int j = 0; j < 8; j++) {
                    int oc = j * 8 + 2 * tig;
                    int mb = wm * 32 + t * 16 + grp;
                    Ds[oc * 132 + mb]           = acc[t][j][0];
                    Ds[(oc + 1) * 132 + mb]     = acc[t][j][1];
                    Ds[oc * 132 + mb + 8]       = acc[t][j][2];
                    Ds[(oc + 1) * 132 + mb + 8] = acc[t][j][3];
                }
        }
        __syncthreads();
#pragma unroll
        for (int l = 0; l < 8; l++) {
            int idx  = tid + l * 256;
            int row  = idx >> 5;
            int col4 = (idx & 31) * 4;
            float4 v = *reinterpret_cast<float4*>(&Ds[row * 132 + col4]);
            int o = o0 + p * 64 + row;
            if (MODE == 1) {
                float bo = __ldg(&bias[o]);
                v.x += bo; v.y += bo; v.z += bo; v.w += bo;
                *reinterpret_cast<float4*>(
                    &out[(size_t)(b * 512 + o) * 1024 + n0 + col4]) = v;
            } else {
                int hh = o & 7, dd = o >> 3;
                size_t gi = (size_t)((b * 8 + hh) * 64 + dd) * 1024 + n0 + col4;
                if (proj == 0) {
                    *reinterpret_cast<float4*>(&out[gi]) = v;
                } else if (proj == 1) {
                    float bg0 = bff(v.x), bg1 = bff(v.y), bg2 = bff(v.z), bg3 = bff(v.w);
                    uint2 pb = make_uint2(packbf2(bg0, bg1), packbf2(bg2, bg3));
                    uint2 ps = make_uint2(packbf2(v.x - bg0, v.y - bg1),
                                          packbf2(v.z - bg2, v.w - bg3));
                    *reinterpret_cast<uint2*>(&kbg[gi]) = pb;
                    *reinterpret_cast<uint2*>(&ksg[gi]) = ps;
                } else {
                    float bg0 = hff(v.x), bg1 = hff(v.y), bg2 = hff(v.z), bg3 = hff(v.w);
                    uint2 pb = make_uint2(packh2(bg0, bg1), packh2(bg2, bg3));
                    uint2 ps = make_uint2(packh2(v.x - bg0, v.y - bg1),
                                          packh2(v.z - bg2, v.w - bg3));
                    *reinterpret_cast<uint2*>(&vbg[gi]) = pb;
                    *reinterpret_cast<uint2*>(&vsg[gi]) = ps;
                }
            }
        }
        __syncthreads();
    }
}

// ===========================================================================
// Flash attention v4: Tq=128, 8 warps, 3-stage K/V pipeline, hoisted Q frags,
// fused mma bias tables (stored pre-scaled: val*SC - 5), STATIC-MAX base-2
// softmax (offset -10, cancels in p/l), PV in fp16 (P single, V big/small).
// ===========================================================================
static constexpr unsigned AT_QB    = 0u;
static constexpr unsigned AT_QS    = 18432u;
static constexpr unsigned AT_ST0   = 36864u;
static constexpr unsigned AT_STSZ  = 36864u;
static constexpr unsigned AT_LH    = AT_ST0 + 3u * AT_STSZ;   // 147456
static constexpr unsigned AT_LW    = AT_LH + 32768u;          // 180224
static constexpr unsigned AT_SMEM  = AT_LW + 32768u;          // 212992

__global__ __launch_bounds__(256)
void attn_mma_kernel(const float* __restrict__ q,
                     const __nv_bfloat16* __restrict__ kbg, const __nv_bfloat16* __restrict__ ksg,
                     const __half* __restrict__ vbg, const __half* __restrict__ vsg,
                     const __nv_bfloat16* __restrict__ rhb, const __nv_bfloat16* __restrict__ rhs,
                     const __nv_bfloat16* __restrict__ rwb, const __nv_bfloat16* __restrict__ rws,
                     __nv_bfloat16* __restrict__ attb, __nv_bfloat16* __restrict__ atts)
{
    extern __shared__ unsigned char smraw[];
    const uint32_t sb = smem_u32(smraw);
    const uint32_t Qb = sb + AT_QB, Qs = sb + AT_QS;
    __nv_bfloat16* Qbp = reinterpret_cast<__nv_bfloat16*>(smraw + AT_QB);
    __nv_bfloat16* Qsp = reinterpret_cast<__nv_bfloat16*>(smraw + AT_QS);
    float* Lh = reinterpret_cast<float*>(smraw + AT_LH);
    float* Lw = reinterpret_cast<float*>(smraw + AT_LW);

    const int bh = blockIdx.y, b = bh >> 3, h = bh & 7;
    const int q0 = blockIdx.x * 128;
    const int tid = threadIdx.x, w = tid >> 5, lane = tid & 31;
    const int g = lane >> 2, t = lane & 3;
    const int rl = lane & 15, byt = (lane >> 4) * 16;

    const float SC = 0.18033688f;    // 0.125 * log2(e)

    const float* qb_g = q + (size_t)bh * 64 * 1024;

    // ---- Q load + bf16 split ----
#pragma unroll
    for (int l = 0; l < 32; l++) {
        int flat = tid + l * 256;
        int d = flat >> 7, i = flat & 127;
        float v = qb_g[(size_t)d * 1024 + q0 + i];
        __nv_bfloat16 bg = __float2bfloat16_rn(v);
        Qbp[i * 72 + d] = bg;
        Qsp[i * 72 + d] = __float2bfloat16_rn(v - __bfloat162float(bg));
    }

    // ---- rel tables into stage0 ----
    {
        const __nv_bfloat16* relp[4] = { rhb, rhs, rwb, rws };
#pragma unroll
        for (int l = 0; l < 8; l++) {
            int flat = tid + l * 256;
            int arr = flat >> 9, sub = flat & 511;
            int r = sub >> 3, seg = sub & 7;
            cp16(sb + AT_ST0 + (uint32_t)arr * 9216u + (uint32_t)r * 144u + (uint32_t)seg * 16u,
                 relp[arr] + r * 64 + seg * 8);
        }
    }
    cp_commit();
    cp_wait<0>();
    __syncthreads();

    // ---- hoisted Q fragments ----
    uint32_t qB[4][4], qS[4][4];
#pragma unroll
    for (int kk = 0; kk < 4; kk++) {
        ldsm4(qB[kk], Qb + (uint32_t)(w * 16 + rl) * 144u + (uint32_t)kk * 32u + byt);
        ldsm4(qS[kk], Qs + (uint32_t)(w * 16 + rl) * 144u + (uint32_t)kk * 32u + byt);
    }

    // per-row constants (2 rows per thread)
    const int lr0 = w * 16 + g, lr1 = lr0 + 8;
    const int nq0 = q0 + lr0, nq1 = q0 + lr1;
    const int x0 = nq0 >> 5, y0 = nq0 & 31;
    const int x1 = nq1 >> 5, y1 = nq1 & 31;

    // ---- bias tables via mma: store pre-scaled  val*SC - 5  ----
    {
        float sl[2][8][4];
#pragma unroll
        for (int tb = 0; tb < 2; tb++)
#pragma unroll
            for (int nb = 0; nb < 8; nb++)
#pragma unroll
                for (int e = 0; e < 4; e++) sl[tb][nb][e] = 0.f;

#pragma unroll
        for (int kk = 0; kk < 4; kk++) {
#pragma unroll
            for (int tb = 0; tb < 2; tb++) {
#pragma unroll
                for (int np = 0; np < 4; np++) {
                    uint32_t radr = sb + AT_ST0 + (uint32_t)tb * 18432u
                                  + (uint32_t)(np * 16 + rl) * 144u + (uint32_t)kk * 32u + byt;
                    uint32_t rB[4], rS[4];
                    ldsm4(rB, radr);
                    ldsm4(rS, radr + 9216u);
#pragma unroll
                    for (int jj = 0; jj < 2; jj++) {
                        int nb = np * 2 + jj;
                        mma_bf16(sl[tb][nb], qB[kk], rB[jj], rB[jj + 2]);
                        mma_bf16(sl[tb][nb], qB[kk], rS[jj], rS[jj + 2]);
                        mma_bf16(sl[tb][nb], qS[kk], rB[jj], rB[jj + 2]);
                    }
                }
            }
        }
#pragma unroll
        for (int nb = 0; nb < 8; nb++) {
            int c0 = nb * 8 + 2 * t;
            Lh[lr0 * 64 + c0]     = sl[0][nb][0] * SC - 5.f;
            Lh[lr0 * 64 + c0 + 1] = sl[0][nb][1] * SC - 5.f;
            Lh[lr1 * 64 + c0]     = sl[0][nb][2] * SC - 5.f;
            Lh[lr1 * 64 + c0 + 1] = sl[0][nb][3] * SC - 5.f;
            Lw[lr0 * 64 + c0]     = sl[1][nb][0] * SC - 5.f;
            Lw[lr0 * 64 + c0 + 1] = sl[1][nb][1] * SC - 5.f;
            Lw[lr1 * 64 + c0]     = sl[1][nb][2] * SC - 5.f;
            Lw[lr1 * 64 + c0 + 1] = sl[1][nb][3] * SC - 5.f;
        }
    }
    __syncthreads();   // Lh/Lw visible; stage0 free for K/V

    // ---- main flash loop, 3-stage K/V pipeline ----
    const __nv_bfloat16* kvp[4] = { kbg, ksg,
                                    reinterpret_cast<const __nv_bfloat16*>(vbg),
                                    reinterpret_cast<const __nv_bfloat16*>(vsg) };
    auto load_kv = [&](int kt, uint32_t stage) {
#pragma unroll
        for (int l = 0; l < 8; l++) {
            int flat = tid + l * 256;
            int arr = flat >> 9, sub = flat & 511;
            int d = sub >> 3, seg = sub & 7;
            cp16(stage + (uint32_t)arr * 9216u + (uint32_t)d * 144u + (uint32_t)seg * 16u,
                 kvp[arr] + ((size_t)bh * 64 + d) * 1024 + kt * 64 + seg * 8);
        }
    };

    float l0 = 0.f, l1 = 0.f;
    float o[8][4];
#pragma unroll
    for (int nd = 0; nd < 8; nd++)
#pragma unroll
        for (int e = 0; e < 4; e++) o[nd][e] = 0.f;

    load_kv(0, sb + AT_ST0); cp_commit();
    load_kv(1, sb + AT_ST0 + AT_STSZ); cp_commit();

    for (int kt = 0; kt < 16; kt++) {
        if (kt < 15) cp_wait<1>(); else cp_wait<0>();
        __syncthreads();
        if (kt + 2 < 16) {
            load_kv(kt + 2, sb + AT_ST0 + (uint32_t)((kt + 2) % 3) * AT_STSZ);
            cp_commit();
        }
        const uint32_t stage = sb + AT_ST0 + (uint32_t)(kt % 3) * AT_STSZ;
        const uint32_t Kb = stage, Vb = stage + 18432u;

        // ---- S = Q K^T (3 bf16 terms) ----
        float s[8][4];
#pragma unroll
        for (int nb = 0; nb < 8; nb++)
#pragma unroll
            for (int e = 0; e < 4; e++) s[nb][e] = 0.f;

#pragma unroll
        for (int kk = 0; kk < 4; kk++) {
#pragma unroll
            for (int np = 0; np < 4; np++) {
                uint32_t kadr = (uint32_t)(kk * 16 + rl) * 144u
                              + (uint32_t)(np * 16 + (lane >> 4) * 8) * 2u;
                uint32_t bB[4], bS[4];
                ldsm4t(bB, Kb + kadr);
                ldsm4t(bS, Kb + 9216u + kadr);
                mma_bf16(s[2 * np],     qB[kk], bB[0], bB[1]);
                mma_bf16(s[2 * np],     qB[kk], bS[0], bS[1]);
                mma_bf16(s[2 * np],     qS[kk], bB[0], bB[1]);
                mma_bf16(s[2 * np + 1], qB[kk], bB[2], bB[3]);
                mma_bf16(s[2 * np + 1], qB[kk], bS[2], bS[3]);
                mma_bf16(s[2 * np + 1], qS[kk], bB[2], bB[3]);
            }
        }

        // ---- static-max base-2 softmax: p = exp2(s*SC + biasScaled) ----
        const float* pLh0 = &Lh[lr0 * 64 + kt * 2 + 31 - x0];
        const float* pLh1 = &Lh[lr1 * 64 + kt * 2 + 31 - x1];
        const float lh00 = pLh0[0], lh01 = pLh0[1];
        const float lh10 = pLh1[0], lh11 = pLh1[1];
        const float* pLw0 = &Lw[lr0 * 64 + 31 - y0 + 2 * t];
        const float* pLw1 = &Lw[lr1 * 64 + 31 - y1 + 2 * t];
        float bw0[8], bw1[8];
#pragma unroll
        for (int c = 0; c < 4; c++) {
            bw0[2 * c]     = pLw0[c * 8];
            bw0[2 * c + 1] = pLw0[c * 8 + 1];
            bw1[2 * c]     = pLw1[c * 8];
            bw1[2 * c + 1] = pLw1[c * 8 + 1];
        }

        float rs0 = 0.f, rs1 = 0.f;
#pragma unroll
        for (int nb = 0; nb < 8; nb++) {
            float lv0 = (nb < 4) ? lh00 : lh01;
            float lv1 = (nb < 4) ? lh10 : lh11;
            int ci = (nb & 3) * 2;
            s[nb][0] = exp2f(fmaf(s[nb][0], SC, lv0 + bw0[ci]));
            s[nb][1] = exp2f(fmaf(s[nb][1], SC, lv0 + bw0[ci + 1]));
            s[nb][2] = exp2f(fmaf(s[nb][2], SC, lv1 + bw1[ci]));
            s[nb][3] = exp2f(fmaf(s[nb][3], SC, lv1 + bw1[ci + 1]));
            rs0 += s[nb][0] + s[nb][1];
            rs1 += s[nb][2] + s[nb][3];
        }
        l0 += rs0;
        l1 += rs1;

        // ---- O += P V : fp16, P single-term, V big/small ----
#pragma unroll
        for (int kk = 0; kk < 4; kk++) {
            float* p0 = s[2 * kk];
            float* p1 = s[2 * kk + 1];
            uint32_t pF[4] = { packh2(p0[0], p0[1]), packh2(p0[2], p0[3]),
                               packh2(p1[0], p1[1]), packh2(p1[2], p1[3]) };
#pragma unroll
            for (int nd = 0; nd < 4; nd++) {
                uint32_t vadr = (uint32_t)(nd * 16 + rl) * 144u + (uint32_t)kk * 32u + byt;
                uint32_t vB[4], vS[4];
                ldsm4(vB, Vb + vadr);
                ldsm4(vS, Vb + 9216u + vadr);
                mma_f16(o[2 * nd],     pF, vB[0], vB[2]);
                mma_f16(o[2 * nd],     pF, vS[0], vS[2]);
                mma_f16(o[2 * nd + 1], pF, vB[1], vB[3]);
                mma_f16(o[2 * nd + 1], pF, vS[1], vS[3]);
            }
        }
    }

    // ---- final l reduction across the quad (columns disjoint per thread) ----
    l0 += __shfl_xor_sync(0xffffffffu, l0, 1);
    l0 += __shfl_xor_sync(0xffffffffu, l0, 2);
    l1 += __shfl_xor_sync(0xffffffffu, l1, 1);
    l1 += __shfl_xor_sync(0xffffffffu, l1, 2);

    // ---- epilogue: att[b][n][c] bf16 big/small, c = h*64 + d ----
    const float inv0 = 1.0f / l0, inv1 = 1.0f / l1;
    const size_t base0 = ((size_t)(b * 1024 + nq0)) * 512 + h * 64;
    const size_t base1 = ((size_t)(b * 1024 + nq1)) * 512 + h * 64;
#pragma unroll
    for (int nd = 0; nd < 8; nd++) {
        int d = nd * 8 + 2 * t;
        float v0 = o[nd][0] * inv0, v1 = o[nd][1] * inv0;
        float v2 = o[nd][2] * inv1, v3 = o[nd][3] * inv1;
        float g0 = bff(v0), g1 = bff(v1), g2 = bff(v2), g3 = bff(v3);
        *reinterpret_cast<uint32_t*>(&attb[base0 + d]) = packbf2(g0, g1);
        *reinterpret_cast<uint32_t*>(&atts[base0 + d]) = packbf2(v0 - g0, v1 - g1);
        *reinterpret_cast<uint32_t*>(&attb[base1 + d]) = packbf2(g2, g3);
        *reinterpret_cast<uint32_t*>(&atts[base1 + d]) = packbf2(v2 - g2, v3 - g3);
    }
}

// ===========================================================================
// Launch
// ===========================================================================
extern "C" void kernel_launch(void* const* d_in, const int* in_sizes, int n_in,
                              void* d_out, int out_size)
{
    const float* x     = (const float*)d_in[0];
    const float* w_q   = (const float*)d_in[1];
    const float* w_k   = (const float*)d_in[2];
    const float* w_v   = (const float*)d_in[3];
    const float* w_o   = (const float*)d_in[4];
    const float* b_o   = (const float*)d_in[5];
    const float* rel_h = (const float*)d_in[6];
    const float* rel_w = (const float*)d_in[7];
    float* out = (float*)d_out;

    float *pq;
    __nv_bfloat16 *pkb, *pks, *pxtb, *pxts, *pattb, *patts, *pwb, *pws;
    __nv_bfloat16 *prhb, *prhs, *prwb, *prws;
    __half *pvb, *pvs;
    cudaGetSymbolAddress((void**)&pq,    g_q);
    cudaGetSymbolAddress((void**)&pkb,   g_kb);
    cudaGetSymbolAddress((void**)&pks,   g_ks);
    cudaGetSymbolAddress((void**)&pvb,   g_vb);
    cudaGetSymbolAddress((void**)&pvs,   g_vs);
    cudaGetSymbolAddress((void**)&pxtb,  g_xtb);
    cudaGetSymbolAddress((void**)&pxts,  g_xts);
    cudaGetSymbolAddress((void**)&pattb, g_attb);
    cudaGetSymbolAddress((void**)&patts, g_atts);
    cudaGetSymbolAddress((void**)&pwb,   g_wb);
    cudaGetSymbolAddress((void**)&pws,   g_ws);
    cudaGetSymbolAddress((void**)&prhb,  g_rhb);
    cudaGetSymbolAddress((void**)&prhs,  g_rhs);
    cudaGetSymbolAddress((void**)&prwb,  g_rwb);
    cudaGetSymbolAddress((void**)&prws,  g_rws);

    cudaFuncSetAttribute(gemm_mma_kernel<0>, cudaFuncAttributeMaxDynamicSharedMemorySize,
                         (int)GEMM_SMEM);
    cudaFuncSetAttribute(gemm_mma_kernel<1>, cudaFuncAttributeMaxDynamicSharedMemorySize,
                         (int)GEMM_SMEM);
    cudaFuncSetAttribute(attn_mma_kernel, cudaFuncAttributeMaxDynamicSharedMemorySize,
                         (int)AT_SMEM);

    transpose_split_kernel<<<dim3(32, 16, 16), 256>>>(x, pxtb, pxts);
    wsplit_kernel<<<4096, 256>>>(w_q, w_k, w_v, w_o, pwb, pws);
    rel_split_kernel<<<32, 256>>>(rel_h, rel_w, prhb, prhs, prwb, prws);

    // Combined QKV projection: z = proj*16 + b
    gemm_mma_kernel<0><<<dim3(8, 4, 48), 256, GEMM_SMEM>>>(
        pxtb, pxts, pwb, pws, pq, nullptr, pkb, pks, pvb, pvs);

    attn_mma_kernel<<<dim3(8, 128), 256, AT_SMEM>>>(
        pq, pkb, pks, pvb, pvs, prhb, prhs, prwb, prws, pattb, patts);

    // Final projection (w_o at slot 3)
    const size_t WS3 = (size_t)3 * 512 * 512;
    gemm_mma_kernel<1><<<dim3(8, 4, 16), 256, GEMM_SMEM>>>(
        pattb, patts, pwb + WS3, pws + WS3, out, b_o, nullptr, nullptr, nullptr, nullptr);
}

// round 15
// speedup vs baseline: 3.8669x; 1.1151x over previous
#include <cuda_runtime.h>
#include <cuda_bf16.h>
#include <cuda_fp16.h>
#include <math.h>
#include <stdint.h>

// Problem: B=16, C=512, NH=8, DK=64, H=W=32, N=1024
// Toolchain targets compute_103 (no 'a'): tcgen05/TMA unusable -> mma.sync path.

// ===========================================================================
// PTX helpers
// ===========================================================================
__device__ __forceinline__ uint32_t smem_u32(const void* p) {
    uint32_t a;
    asm("{ .reg .u64 t; cvta.to.shared.u64 t, %1; cvt.u32.u64 %0, t; }"
        : "=r"(a) : "l"(p));
    return a;
}
__device__ __forceinline__ void cp16(uint32_t dst, const void* src) {
    asm volatile("cp.async.cg.shared.global [%0], [%1], 16;" :: "r"(dst), "l"(src));
}
__device__ __forceinline__ void cp_commit() { asm volatile("cp.async.commit_group;"); }
template <int N>
__device__ __forceinline__ void cp_wait() {
    asm volatile("cp.async.wait_group %0;" :: "n"(N) : "memory");
}
__device__ __forceinline__ void ldsm4(uint32_t* r, uint32_t addr) {
    asm volatile("ldmatrix.sync.aligned.m8n8.x4.shared.b16 {%0,%1,%2,%3}, [%4];"
                 : "=r"(r[0]), "=r"(r[1]), "=r"(r[2]), "=r"(r[3]) : "r"(addr));
}
__device__ __forceinline__ void ldsm4t(uint32_t* r, uint32_t addr) {
    asm volatile("ldmatrix.sync.aligned.m8n8.x4.trans.shared.b16 {%0,%1,%2,%3}, [%4];"
                 : "=r"(r[0]), "=r"(r[1]), "=r"(r[2]), "=r"(r[3]) : "r"(addr));
}
__device__ __forceinline__ void mma_bf16(float* d, const uint32_t* a,
                                         uint32_t b0, uint32_t b1) {
    asm volatile(
        "mma.sync.aligned.m16n8k16.row.col.f32.bf16.bf16.f32 "
        "{%0,%1,%2,%3}, {%4,%5,%6,%7}, {%8,%9}, {%0,%1,%2,%3};"
        : "+f"(d[0]), "+f"(d[1]), "+f"(d[2]), "+f"(d[3])
        : "r"(a[0]), "r"(a[1]), "r"(a[2]), "r"(a[3]), "r"(b0), "r"(b1));
}
__device__ __forceinline__ void mma_f16(float* d, const uint32_t* a,
                                        uint32_t b0, uint32_t b1) {
    asm volatile(
        "mma.sync.aligned.m16n8k16.row.col.f32.f16.f16.f32 "
        "{%0,%1,%2,%3}, {%4,%5,%6,%7}, {%8,%9}, {%0,%1,%2,%3};"
        : "+f"(d[0]), "+f"(d[1]), "+f"(d[2]), "+f"(d[3])
        : "r"(a[0]), "r"(a[1]), "r"(a[2]), "r"(a[3]), "r"(b0), "r"(b1));
}
__device__ __forceinline__ uint32_t packbf2(float a, float b) {
    __nv_bfloat162 h = __floats2bfloat162_rn(a, b);
    return *reinterpret_cast<uint32_t*>(&h);
}
__device__ __forceinline__ uint32_t packh2(float a, float b) {
    __half2 h = __floats2half2_rn(a, b);
    return *reinterpret_cast<uint32_t*>(&h);
}
__device__ __forceinline__ float bff(float v) {
    return __bfloat162float(__float2bfloat16_rn(v));
}
__device__ __forceinline__ float hff(float v) {
    return __half2float(__float2half_rn(v));
}

// ===========================================================================
// Device scratch
// q, k: fp16 single [b][h][d][n]; v: fp16 big/small [b][h][d][n]
// ===========================================================================
__device__ __half        g_qf  [16 * 8 * 64 * 1024];
__device__ __half        g_kf  [16 * 8 * 64 * 1024];
__device__ __half        g_vb  [16 * 8 * 64 * 1024];
__device__ __half        g_vs  [16 * 8 * 64 * 1024];
__device__ __nv_bfloat16 g_xtb [16 * 1024 * 512];
__device__ __nv_bfloat16 g_xts [16 * 1024 * 512];
__device__ __nv_bfloat16 g_attb[16 * 1024 * 512];
__device__ __nv_bfloat16 g_atts[16 * 1024 * 512];
__device__ __nv_bfloat16 g_wb  [4 * 512 * 512];
__device__ __nv_bfloat16 g_ws  [4 * 512 * 512];
// rel tables, fp16 single, padded to 64 rows (row 63 = 0): [r][d]
__device__ __half        g_rhf [64 * 64];
__device__ __half        g_rwf [64 * 64];

// ===========================================================================
// Producers
// ===========================================================================
__global__ __launch_bounds__(256)
void transpose_split_kernel(const float* __restrict__ x,
                            __nv_bfloat16* __restrict__ xtb,
                            __nv_bfloat16* __restrict__ xts)
{
    __shared__ float t[32][33];
    const int b = blockIdx.z, c0 = blockIdx.y * 32, n0 = blockIdx.x * 32;
    const int lx = threadIdx.x & 31, ly = threadIdx.x >> 5;
    const float* xb = x + ((size_t)b * 512 + c0) * 1024 + n0;
#pragma unroll
    for (int r = 0; r < 4; r++)
        t[ly * 4 + r][lx] = xb[(size_t)(ly * 4 + r) * 1024 + lx];
    __syncthreads();
    __nv_bfloat16* ob = xtb + ((size_t)b * 1024 + n0) * 512 + c0;
    __nv_bfloat16* os = xts + ((size_t)b * 1024 + n0) * 512 + c0;
#pragma unroll
    for (int r = 0; r < 4; r++) {
        float v = t[lx][ly * 4 + r];
        __nv_bfloat16 bg = __float2bfloat16_rn(v);
        ob[(size_t)(ly * 4 + r) * 512 + lx] = bg;
        os[(size_t)(ly * 4 + r) * 512 + lx] = __float2bfloat16_rn(v - __bfloat162float(bg));
    }
}

__global__ __launch_bounds__(256)
void wsplit_kernel(const float* __restrict__ w0, const float* __restrict__ w1,
                   const float* __restrict__ w2, const float* __restrict__ w3,
                   __nv_bfloat16* __restrict__ wb, __nv_bfloat16* __restrict__ ws)
{
    int i = blockIdx.x * 256 + threadIdx.x;
    int arr = i >> 18, off = i & 262143;
    const float* src = (arr == 0) ? w0 : (arr == 1) ? w1 : (arr == 2) ? w2 : w3;
    float v = src[off];
    __nv_bfloat16 bg = __float2bfloat16_rn(v);
    wb[i] = bg;
    ws[i] = __float2bfloat16_rn(v - __bfloat162float(bg));
}

// rel tables: fp32 (63x64) -> fp16 single, padded to 64 rows (row 63 = 0)
__global__ __launch_bounds__(256)
void rel_split_kernel(const float* __restrict__ rel_h, const float* __restrict__ rel_w,
                      __half* __restrict__ rhf, __half* __restrict__ rwf)
{
    int i = blockIdx.x * 256 + threadIdx.x;    // 0..8191
    int table = i >> 12, pos = i & 4095;
    int r = pos >> 6, d = pos & 63;
    float v = (r < 63) ? (table == 0 ? rel_h[r * 64 + d] : rel_w[r * 64 + d]) : 0.f;
    if (table == 0) rhf[pos] = __float2half_rn(v);
    else            rwf[pos] = __float2half_rn(v);
}

// ===========================================================================
// mma.sync bf16x3 GEMM v3: 3-stage pipeline, 1 sync/chunk.
// MODE 0 epilogues: proj0 -> fp16 Q; proj1 -> fp16 K; proj2 -> fp16 V big/small
// MODE 1: fp32 out + bias
// ===========================================================================
static constexpr unsigned GSTAGE = 32768u;
static constexpr unsigned GEMM_SMEM = 3u * GSTAGE;   // 98304

template <int MODE>
__global__ __launch_bounds__(256, 2)
void gemm_mma_kernel(const __nv_bfloat16* __restrict__ Ab_g,
                     const __nv_bfloat16* __restrict__ As_g,
                     const __nv_bfloat16* __restrict__ Wb_g,
                     const __nv_bfloat16* __restrict__ Ws_g,
                     float* __restrict__ out, const float* __restrict__ bias,
                     __half* __restrict__ qfg, __half* __restrict__ kfg,
                     __half* __restrict__ vbg, __half* __restrict__ vsg)
{
    extern __shared__ unsigned char smraw[];
    const uint32_t sb = smem_u32(smraw);
    const int tid = threadIdx.x, w = tid >> 5, lane = tid & 31;
    const int b = blockIdx.z & 15, proj = blockIdx.z >> 4;
    const int n0 = blockIdx.x * 128, o0 = blockIdx.y * 128;
    const int wm = w & 3, wn = w >> 2;

    const size_t woff = (size_t)proj * 512 * 512 + (size_t)o0 * 512;
    const __nv_bfloat16* srcs[4] = {
        Ab_g + ((size_t)b * 1024 + n0) * 512,
        As_g + ((size_t)b * 1024 + n0) * 512,
        Wb_g + woff, Ws_g + woff };

    float acc[2][8][4];
#pragma unroll
    for (int t = 0; t < 2; t++)
#pragma unroll
        for (int j = 0; j < 8; j++)
#pragma unroll
            for (int e = 0; e < 4; e++) acc[t][j][e] = 0.f;

    auto load_chunk = [&](int c, uint32_t stage) {
#pragma unroll
        for (int l = 0; l < 8; l++) {
            int flat = tid + l * 256;        // 0..2047
            int arr  = flat >> 9;            // A0,A1,B0,B1
            int sub  = flat & 511;
            int row  = sub >> 2;
            int seg  = sub & 3;
            uint32_t dst = stage + (uint32_t)arr * 8192u + (uint32_t)row * 64u
                         + (uint32_t)((seg ^ ((row >> 1) & 3)) * 16);
            cp16(dst, srcs[arr] + (size_t)row * 512 + c * 32 + seg * 8);
        }
    };

    const int rl   = lane & 15;
    const int half = lane >> 4;

    auto compute = [&](uint32_t stage) {
#pragma unroll
        for (int kk = 0; kk < 2; kk++) {
            uint32_t a_f[2][2][4];
            uint32_t b_f[2][4][4];
#pragma unroll
            for (int term = 0; term < 2; term++) {
#pragma unroll
                for (int t = 0; t < 2; t++) {
                    int row = wm * 32 + t * 16 + rl;
                    uint32_t seg = (uint32_t)((2 * kk + half) ^ ((row >> 1) & 3));
                    ldsm4(a_f[term][t], stage + (uint32_t)term * 8192u
                                        + (uint32_t)row * 64u + seg * 16u);
                }
#pragma unroll
                for (int g = 0; g < 4; g++) {
                    int row = wn * 64 + g * 16 + rl;
                    uint32_t seg = (uint32_t)((2 * kk + half) ^ ((row >> 1) & 3));
                    ldsm4(b_f[term][g], stage + 16384u + (uint32_t)term * 8192u
                                        + (uint32_t)row * 64u + seg * 16u);
                }
            }
#pragma unroll
            for (int t = 0; t < 2; t++)
#pragma unroll
                for (int j = 0; j < 8; j++) {
                    int g = j >> 1, jj = j & 1;
                    mma_bf16(acc[t][j], a_f[0][t], b_f[0][g][jj], b_f[0][g][jj + 2]);
                    mma_bf16(acc[t][j], a_f[0][t], b_f[1][g][jj], b_f[1][g][jj + 2]);
                    mma_bf16(acc[t][j], a_f[1][t], b_f[0][g][jj], b_f[0][g][jj + 2]);
                }
        }
    };

    load_chunk(0, sb); cp_commit();
    load_chunk(1, sb + GSTAGE); cp_commit();
    for (int c = 0; c < 16; c++) {
        if (c < 15) cp_wait<1>(); else cp_wait<0>();
        __syncthreads();
        if (c + 2 < 16) {
            load_chunk(c + 2, sb + (uint32_t)((c + 2) % 3) * GSTAGE);
            cp_commit();
        }
        compute(sb + (uint32_t)(c % 3) * GSTAGE);
    }
    __syncthreads();

    float* Ds = reinterpret_cast<float*>(smraw);    // [64][132]
    const int grp = lane >> 2, tig = lane & 3;
#pragma unroll
    for (int p = 0; p < 2; p++) {
        if (wn == p) {
#pragma unroll
            for (int t = 0; t < 2; t++)
#pragma unroll
                for (int j = 0; j < 8; j++) {
                    int oc = j * 8 + 2 * tig;
                    int mb = wm * 32 + t * 16 + grp;
                    Ds[oc * 132 + mb]           = acc[t][j][0];
                    Ds[(oc + 1) * 132 + mb]     = acc[t][j][1];
                    Ds[oc * 132 + mb + 8]       = acc[t][j][2];
                    Ds[(oc + 1) * 132 + mb + 8] = acc[t][j][3];
                }
        }
        __syncthreads();
#pragma unroll
        for (int l = 0; l < 8; l++) {
            int idx  = tid + l * 256;
            int row  = idx >> 5;
            int col4 = (idx & 31) * 4;
            float4 v = *reinterpret_cast<float4*>(&Ds[row * 132 + col4]);
            int o = o0 + p * 64 + row;
            if (MODE == 1) {
                float bo = __ldg(&bias[o]);
                v.x += bo; v.y += bo; v.z += bo; v.w += bo;
                *reinterpret_cast<float4*>(
                    &out[(size_t)(b * 512 + o) * 1024 + n0 + col4]) = v;
            } else {
                int hh = o & 7, dd = o >> 3;
                size_t gi = (size_t)((b * 8 + hh) * 64 + dd) * 1024 + n0 + col4;
                if (proj == 0) {
                    uint2 ph = make_uint2(packh2(v.x, v.y), packh2(v.z, v.w));
                    *reinterpret_cast<uint2*>(&qfg[gi]) = ph;
                } else if (proj == 1) {
                    uint2 ph = make_uint2(packh2(v.x, v.y), packh2(v.z, v.w));
                    *reinterpret_cast<uint2*>(&kfg[gi]) = ph;
                } else {
                    float bg0 = hff(v.x), bg1 = hff(v.y), bg2 = hff(v.z), bg3 = hff(v.w);
                    uint2 pb = make_uint2(packh2(bg0, bg1), packh2(bg2, bg3));
                    uint2 ps = make_uint2(packh2(v.x - bg0, v.y - bg1),
                                          packh2(v.z - bg2, v.w - bg3));
                    *reinterpret_cast<uint2*>(&vbg[gi]) = pb;
                    *reinterpret_cast<uint2*>(&vsg[gi]) = ps;
                }
            }
        }
        __syncthreads();
    }
}

// ===========================================================================
// Flash attention v5: Tq=128, 8 warps, 4-stage K/V pipeline, fp16 single-term
// S and bias (Q,K fp16), PV fp16 (P single, V big/small), static-max base-2
// softmax, fused mma bias tables.
// Smem: Qf [128][72]h; 4 KV stages {Kf,Vb,Vs} 64x144B each; LH/LW fp32.
// ===========================================================================
static constexpr unsigned AT_QF    = 0u;
static constexpr unsigned AT_ST0   = 18432u;
static constexpr unsigned AT_STSZ  = 27648u;
static constexpr unsigned AT_LH    = AT_ST0 + 4u * AT_STSZ;   // 129024
static constexpr unsigned AT_LW    = AT_LH + 32768u;          // 161792
static constexpr unsigned AT_SMEM  = AT_LW + 32768u;          // 194560

__global__ __launch_bounds__(256)
void attn_mma_kernel(const __half* __restrict__ qfg,
                     const __half* __restrict__ kfg,
                     const __half* __restrict__ vbg, const __half* __restrict__ vsg,
                     const __half* __restrict__ rhf, const __half* __restrict__ rwf,
                     __nv_bfloat16* __restrict__ attb, __nv_bfloat16* __restrict__ atts)
{
    extern __shared__ unsigned char smraw[];
    const uint32_t sb = smem_u32(smraw);
    const uint32_t Qf = sb + AT_QF;
    __half* Qfp = reinterpret_cast<__half*>(smraw + AT_QF);
    float* Lh = reinterpret_cast<float*>(smraw + AT_LH);
    float* Lw = reinterpret_cast<float*>(smraw + AT_LW);

    const int bh = blockIdx.y, b = bh >> 3, h = bh & 7;
    const int q0 = blockIdx.x * 128;
    const int tid = threadIdx.x, w = tid >> 5, lane = tid & 31;
    const int g = lane >> 2, t = lane & 3;
    const int rl = lane & 15, byt = (lane >> 4) * 16;

    const float SC = 0.18033688f;    // 0.125 * log2(e)

    const __half* qb_g = qfg + (size_t)bh * 64 * 1024;

    // ---- Q into smem [i][d], 144B rows ----
#pragma unroll
    for (int l = 0; l < 32; l++) {
        int flat = tid + l * 256;
        int d = flat >> 7, i = flat & 127;
        Qfp[i * 72 + d] = qb_g[(size_t)d * 1024 + q0 + i];
    }

    // ---- rel tables into stage0: [rhf, rwf] 64x144B each ----
#pragma unroll
    for (int l = 0; l < 4; l++) {
        int flat = tid + l * 256;            // 0..1023
        int arr = flat >> 9, sub = flat & 511;
        int r = sub >> 3, seg = sub & 7;
        cp16(sb + AT_ST0 + (uint32_t)arr * 9216u + (uint32_t)r * 144u + (uint32_t)seg * 16u,
             (arr == 0 ? rhf : rwf) + r * 64 + seg * 8);
    }
    cp_commit();
    cp_wait<0>();
    __syncthreads();

    // ---- hoisted Q fragments ----
    uint32_t qF[4][4];
#pragma unroll
    for (int kk = 0; kk < 4; kk++)
        ldsm4(qF[kk], Qf + (uint32_t)(w * 16 + rl) * 144u + (uint32_t)kk * 32u + byt);

    // per-row constants (2 rows per thread)
    const int lr0 = w * 16 + g, lr1 = lr0 + 8;
    const int nq0 = q0 + lr0, nq1 = q0 + lr1;
    const int x0 = nq0 >> 5, y0 = nq0 & 31;
    const int x1 = nq1 >> 5, y1 = nq1 & 31;

    // ---- bias tables via mma (fp16 single-term); store pre-scaled *SC - 5 ----
    {
        float sl[2][8][4];
#pragma unroll
        for (int tb = 0; tb < 2; tb++)
#pragma unroll
            for (int nb = 0; nb < 8; nb++)
#pragma unroll
                for (int e = 0; e < 4; e++) sl[tb][nb][e] = 0.f;

#pragma unroll
        for (int kk = 0; kk < 4; kk++) {
#pragma unroll
            for (int tb = 0; tb < 2; tb++) {
#pragma unroll
                for (int np = 0; np < 4; np++) {
                    uint32_t radr = sb + AT_ST0 + (uint32_t)tb * 9216u
                                  + (uint32_t)(np * 16 + rl) * 144u + (uint32_t)kk * 32u + byt;
                    uint32_t rF[4];
                    ldsm4(rF, radr);
                    mma_f16(sl[tb][np * 2],     qF[kk], rF[0], rF[2]);
                    mma_f16(sl[tb][np * 2 + 1], qF[kk], rF[1], rF[3]);
                }
            }
        }
#pragma unroll
        for (int nb = 0; nb < 8; nb++) {
            int c0 = nb * 8 + 2 * t;
            Lh[lr0 * 64 + c0]     = sl[0][nb][0] * SC - 5.f;
            Lh[lr0 * 64 + c0 + 1] = sl[0][nb][1] * SC - 5.f;
            Lh[lr1 * 64 + c0]     = sl[0][nb][2] * SC - 5.f;
            Lh[lr1 * 64 + c0 + 1] = sl[0][nb][3] * SC - 5.f;
            Lw[lr0 * 64 + c0]     = sl[1][nb][0] * SC - 5.f;
            Lw[lr0 * 64 + c0 + 1] = sl[1][nb][1] * SC - 5.f;
            Lw[lr1 * 64 + c0]     = sl[1][nb][2] * SC - 5.f;
            Lw[lr1 * 64 + c0 + 1] = sl[1][nb][3] * SC - 5.f;
        }
    }
    __syncthreads();   // Lh/Lw visible; stage0 free for K/V

    // ---- main flash loop, 4-stage K/V pipeline ----
    const __half* kvp[3] = { kfg, vbg, vsg };
    auto load_kv = [&](int kt, uint32_t stage) {
#pragma unroll
        for (int l = 0; l < 6; l++) {
            int flat = tid + l * 256;            // 0..1535
            int arr = flat / 512, sub = flat & 511;
            int d = sub >> 3, seg = sub & 7;
            cp16(stage + (uint32_t)arr * 9216u + (uint32_t)d * 144u + (uint32_t)seg * 16u,
                 kvp[arr] + ((size_t)bh * 64 + d) * 1024 + kt * 64 + seg * 8);
        }
    };

    float l0 = 0.f, l1 = 0.f;
    float o[8][4];
#pragma unroll
    for (int nd = 0; nd < 8; nd++)
#pragma unroll
        for (int e = 0; e < 4; e++) o[nd][e] = 0.f;

    load_kv(0, sb + AT_ST0); cp_commit();
    load_kv(1, sb + AT_ST0 + AT_STSZ); cp_commit();
    load_kv(2, sb + AT_ST0 + 2u * AT_STSZ); cp_commit();

    for (int kt = 0; kt < 16; kt++) {
        if (kt <= 13)      cp_wait<2>();
        else if (kt == 14) cp_wait<1>();
        else               cp_wait<0>();
        __syncthreads();
        if (kt + 3 < 16) {
            load_kv(kt + 3, sb + AT_ST0 + (uint32_t)((kt + 3) & 3) * AT_STSZ);
            cp_commit();
        }
        const uint32_t stage = sb + AT_ST0 + (uint32_t)(kt & 3) * AT_STSZ;
        const uint32_t Kb = stage, Vb = stage + 9216u, Vs = stage + 18432u;

        // ---- S = Q K^T (fp16 single-term) ----
        float s[8][4];
#pragma unroll
        for (int nb = 0; nb < 8; nb++)
#pragma unroll
            for (int e = 0; e < 4; e++) s[nb][e] = 0.f;

#pragma unroll
        for (int kk = 0; kk < 4; kk++) {
#pragma unroll
            for (int np = 0; np < 4; np++) {
                uint32_t kadr = (uint32_t)(kk * 16 + rl) * 144u
                              + (uint32_t)(np * 16 + (lane >> 4) * 8) * 2u;
                uint32_t kF[4];
                ldsm4t(kF, Kb + kadr);
                mma_f16(s[2 * np],     qF[kk], kF[0], kF[1]);
                mma_f16(s[2 * np + 1], qF[kk], kF[2], kF[3]);
            }
        }

        // ---- static-max base-2 softmax: p = exp2(s*SC + biasScaled) ----
        const float* pLh0 = &Lh[lr0 * 64 + kt * 2 + 31 - x0];
        const float* pLh1 = &Lh[lr1 * 64 + kt * 2 + 31 - x1];
        const float lh00 = pLh0[0], lh01 = pLh0[1];
        const float lh10 = pLh1[0], lh11 = pLh1[1];
        const float* pLw0 = &Lw[lr0 * 64 + 31 - y0 + 2 * t];
        const float* pLw1 = &Lw[lr1 * 64 + 31 - y1 + 2 * t];
        float bw0[8], bw1[8];
#pragma unroll
        for (int c = 0; c < 4; c++) {
            bw0[2 * c]     = pLw0[c * 8];
            bw0[2 * c + 1] = pLw0[c * 8 + 1];
            bw1[2 * c]     = pLw1[c * 8];
            bw1[2 * c + 1] = pLw1[c * 8 + 1];
        }

        float rs0 = 0.f, rs1 = 0.f;
#pragma unroll
        for (int nb = 0; nb < 8; nb++) {
            float lv0 = (nb < 4) ? lh00 : lh01;
            float lv1 = (nb < 4) ? lh10 : lh11;
            int ci = (nb & 3) * 2;
            s[nb][0] = exp2f(fmaf(s[nb][0], SC, lv0 + bw0[ci]));
            s[nb][1] = exp2f(fmaf(s[nb][1], SC, lv0 + bw0[ci + 1]));
            s[nb][2] = exp2f(fmaf(s[nb][2], SC, lv1 + bw1[ci]));
            s[nb][3] = exp2f(fmaf(s[nb][3], SC, lv1 + bw1[ci + 1]));
            rs0 += s[nb][0] + s[nb][1];
            rs1 += s[nb][2] + s[nb][3];
        }
        l0 += rs0;
        l1 += rs1;

        // ---- O += P V : fp16, P single-term, V big/small ----
#pragma unroll
        for (int kk = 0; kk < 4; kk++) {
            float* p0 = s[2 * kk];
            float* p1 = s[2 * kk + 1];
            uint32_t pF[4] = { packh2(p0[0], p0[1]), packh2(p0[2], p0[3]),
                               packh2(p1[0], p1[1]), packh2(p1[2], p1[3]) };
#pragma unroll
            for (int nd = 0; nd < 4; nd++) {
                uint32_t vadr = (uint32_t)(nd * 16 + rl) * 144u + (uint32_t)kk * 32u + byt;
                uint32_t vB[4], vS[4];
                ldsm4(vB, Vb + vadr);
                ldsm4(vS, Vs + vadr);
                mma_f16(o[2 * nd],     pF, vB[0], vB[2]);
                mma_f16(o[2 * nd],     pF, vS[0], vS[2]);
                mma_f16(o[2 * nd + 1], pF, vB[1], vB[3]);
                mma_f16(o[2 * nd + 1], pF, vS[1], vS[3]);
            }
        }
    }

    // ---- final l reduction across the quad ----
    l0 += __shfl_xor_sync(0xffffffffu, l0, 1);
    l0 += __shfl_xor_sync(0xffffffffu, l0, 2);
    l1 += __shfl_xor_sync(0xffffffffu, l1, 1);
    l1 += __shfl_xor_sync(0xffffffffu, l1, 2);

    // ---- epilogue: att[b][n][c] bf16 big/small, c = h*64 + d ----
    const float inv0 = 1.0f / l0, inv1 = 1.0f / l1;
    const size_t base0 = ((size_t)(b * 1024 + nq0)) * 512 + h * 64;
    const size_t base1 = ((size_t)(b * 1024 + nq1)) * 512 + h * 64;
#pragma unroll
    for (int nd = 0; nd < 8; nd++) {
        int d = nd * 8 + 2 * t;
        float v0 = o[nd][0] * inv0, v1 = o[nd][1] * inv0;
        float v2 = o[nd][2] * inv1, v3 = o[nd][3] * inv1;
        float g0 = bff(v0), g1 = bff(v1), g2 = bff(v2), g3 = bff(v3);
        *reinterpret_cast<uint32_t*>(&attb[base0 + d]) = packbf2(g0, g1);
        *reinterpret_cast<uint32_t*>(&atts[base0 + d]) = packbf2(v0 - g0, v1 - g1);
        *reinterpret_cast<uint32_t*>(&attb[base1 + d]) = packbf2(g2, g3);
        *reinterpret_cast<uint32_t*>(&atts[base1 + d]) = packbf2(v2 - g2, v3 - g3);
    }
}

// ===========================================================================
// Launch
// ===========================================================================
extern "C" void kernel_launch(void* const* d_in, const int* in_sizes, int n_in,
                              void* d_out, int out_size)
{
    const float* x     = (const float*)d_in[0];
    const float* w_q   = (const float*)d_in[1];
    const float* w_k   = (const float*)d_in[2];
    const float* w_v   = (const float*)d_in[3];
    const float* w_o   = (const float*)d_in[4];
    const float* b_o   = (const float*)d_in[5];
    const float* rel_h = (const float*)d_in[6];
    const float* rel_w = (const float*)d_in[7];
    float* out = (float*)d_out;

    __nv_bfloat16 *pxtb, *pxts, *pattb, *patts, *pwb, *pws;
    __half *pqf, *pkf, *pvb, *pvs, *prhf, *prwf;
    cudaGetSymbolAddress((void**)&pqf,   g_qf);
    cudaGetSymbolAddress((void**)&pkf,   g_kf);
    cudaGetSymbolAddress((void**)&pvb,   g_vb);
    cudaGetSymbolAddress((void**)&pvs,   g_vs);
    cudaGetSymbolAddress((void**)&pxtb,  g_xtb);
    cudaGetSymbolAddress((void**)&pxts,  g_xts);
    cudaGetSymbolAddress((void**)&pattb, g_attb);
    cudaGetSymbolAddress((void**)&patts, g_atts);
    cudaGetSymbolAddress((void**)&pwb,   g_wb);
    cudaGetSymbolAddress((void**)&pws,   g_ws);
    cudaGetSymbolAddress((void**)&prhf,  g_rhf);
    cudaGetSymbolAddress((void**)&prwf,  g_rwf);

    cudaFuncSetAttribute(gemm_mma_kernel<0>, cudaFuncAttributeMaxDynamicSharedMemorySize,
                         (int)GEMM_SMEM);
    cudaFuncSetAttribute(gemm_mma_kernel<1>, cudaFuncAttributeMaxDynamicSharedMemorySize,
                         (int)GEMM_SMEM);
    cudaFuncSetAttribute(attn_mma_kernel, cudaFuncAttributeMaxDynamicSharedMemorySize,
                         (int)AT_SMEM);

    transpose_split_kernel<<<dim3(32, 16, 16), 256>>>(x, pxtb, pxts);
    wsplit_kernel<<<4096, 256>>>(w_q, w_k, w_v, w_o, pwb, pws);
    rel_split_kernel<<<32, 256>>>(rel_h, rel_w, prhf, prwf);

    // Combined QKV projection: z = proj*16 + b
    gemm_mma_kernel<0><<<dim3(8, 4, 48), 256, GEMM_SMEM>>>(
        pxtb, pxts, pwb, pws, nullptr, nullptr, pqf, pkf, pvb, pvs);

    attn_mma_kernel<<<dim3(8, 128), 256, AT_SMEM>>>(
        pqf, pkf, pvb, pvs, prhf, prwf, pattb, patts);

    // Final projection (w_o at slot 3)
    const size_t WS3 = (size_t)3 * 512 * 512;
    gemm_mma_kernel<1><<<dim3(8, 4, 16), 256, GEMM_SMEM>>>(
        pattb, patts, pwb + WS3, pws + WS3, out, b_o, nullptr, nullptr, nullptr, nullptr);
}

// round 16
// speedup vs baseline: 7.0915x; 1.8339x over previous
#include <cuda_runtime.h>
#include <cuda_bf16.h>
#include <cuda_fp16.h>
#include <math.h>
#include <stdint.h>

// Problem: B=16, C=512, NH=8, DK=64, H=W=32, N=1024
// Toolchain targets compute_103 (no 'a'): tcgen05/TMA unusable -> mma.sync path.
// Precision: fp16 single-term everywhere, fp32 accumulate. Predicted ~5.5e-4.

// ===========================================================================
// PTX helpers
// ===========================================================================
__device__ __forceinline__ uint32_t smem_u32(const void* p) {
    uint32_t a;
    asm("{ .reg .u64 t; cvta.to.shared.u64 t, %1; cvt.u32.u64 %0, t; }"
        : "=r"(a) : "l"(p));
    return a;
}
__device__ __forceinline__ void cp16(uint32_t dst, const void* src) {
    asm volatile("cp.async.cg.shared.global [%0], [%1], 16;" :: "r"(dst), "l"(src));
}
__device__ __forceinline__ void cp_commit() { asm volatile("cp.async.commit_group;"); }
template <int N>
__device__ __forceinline__ void cp_wait() {
    asm volatile("cp.async.wait_group %0;" :: "n"(N) : "memory");
}
__device__ __forceinline__ void ldsm4(uint32_t* r, uint32_t addr) {
    asm volatile("ldmatrix.sync.aligned.m8n8.x4.shared.b16 {%0,%1,%2,%3}, [%4];"
                 : "=r"(r[0]), "=r"(r[1]), "=r"(r[2]), "=r"(r[3]) : "r"(addr));
}
__device__ __forceinline__ void ldsm4t(uint32_t* r, uint32_t addr) {
    asm volatile("ldmatrix.sync.aligned.m8n8.x4.trans.shared.b16 {%0,%1,%2,%3}, [%4];"
                 : "=r"(r[0]), "=r"(r[1]), "=r"(r[2]), "=r"(r[3]) : "r"(addr));
}
__device__ __forceinline__ void mma_f16(float* d, const uint32_t* a,
                                        uint32_t b0, uint32_t b1) {
    asm volatile(
        "mma.sync.aligned.m16n8k16.row.col.f32.f16.f16.f32 "
        "{%0,%1,%2,%3}, {%4,%5,%6,%7}, {%8,%9}, {%0,%1,%2,%3};"
        : "+f"(d[0]), "+f"(d[1]), "+f"(d[2]), "+f"(d[3])
        : "r"(a[0]), "r"(a[1]), "r"(a[2]), "r"(a[3]), "r"(b0), "r"(b1));
}
__device__ __forceinline__ uint32_t packh2(float a, float b) {
    __half2 h = __floats2half2_rn(a, b);
    return *reinterpret_cast<uint32_t*>(&h);
}

// ===========================================================================
// Device scratch (all fp16 single)
// ===========================================================================
__device__ __half g_qf  [16 * 8 * 64 * 1024];
__device__ __half g_kf  [16 * 8 * 64 * 1024];
__device__ __half g_vf  [16 * 8 * 64 * 1024];
__device__ __half g_xtf [16 * 1024 * 512];
__device__ __half g_attf[16 * 1024 * 512];
__device__ __half g_wf  [4 * 512 * 512];
__device__ __half g_rhf [64 * 64];
__device__ __half g_rwf [64 * 64];

// ===========================================================================
// Producers
// ===========================================================================
__global__ __launch_bounds__(256)
void transpose_kernel(const float* __restrict__ x, __half* __restrict__ xtf)
{
    __shared__ float t[32][33];
    const int b = blockIdx.z, c0 = blockIdx.y * 32, n0 = blockIdx.x * 32;
    const int lx = threadIdx.x & 31, ly = threadIdx.x >> 5;
    const float* xb = x + ((size_t)b * 512 + c0) * 1024 + n0;
#pragma unroll
    for (int r = 0; r < 4; r++)
        t[ly * 4 + r][lx] = xb[(size_t)(ly * 4 + r) * 1024 + lx];
    __syncthreads();
    __half* ob = xtf + ((size_t)b * 1024 + n0) * 512 + c0;
#pragma unroll
    for (int r = 0; r < 4; r++)
        ob[(size_t)(ly * 4 + r) * 512 + lx] = __float2half_rn(t[lx][ly * 4 + r]);
}

__global__ __launch_bounds__(256)
void wconv_kernel(const float* __restrict__ w0, const float* __restrict__ w1,
                  const float* __restrict__ w2, const float* __restrict__ w3,
                  __half* __restrict__ wf)
{
    int i = blockIdx.x * 256 + threadIdx.x;
    int arr = i >> 18, off = i & 262143;
    const float* src = (arr == 0) ? w0 : (arr == 1) ? w1 : (arr == 2) ? w2 : w3;
    wf[i] = __float2half_rn(src[off]);
}

__global__ __launch_bounds__(256)
void rel_conv_kernel(const float* __restrict__ rel_h, const float* __restrict__ rel_w,
                     __half* __restrict__ rhf, __half* __restrict__ rwf)
{
    int i = blockIdx.x * 256 + threadIdx.x;    // 0..8191
    int table = i >> 12, pos = i & 4095;
    int r = pos >> 6, d = pos & 63;
    float v = (r < 63) ? (table == 0 ? rel_h[r * 64 + d] : rel_w[r * 64 + d]) : 0.f;
    if (table == 0) rhf[pos] = __float2half_rn(v);
    else            rwf[pos] = __float2half_rn(v);
}

// ===========================================================================
// fp16 single-term GEMM, 3-stage pipeline, 64B rows + XOR seg swizzle.
// Stage = {A,B} x 128row x 64B = 16KB.
// MODE 0 (proj = blockIdx.z>>4): fp16 q/k/v scatter.  MODE 1: fp32 out + bias.
// ===========================================================================
static constexpr unsigned GSTAGE = 16384u;
static constexpr unsigned GEMM_SMEM = 3u * GSTAGE;   // 49152

template <int MODE>
__global__ __launch_bounds__(256, 2)
void gemm_mma_kernel(const __half* __restrict__ A_g,
                     const __half* __restrict__ W_g,
                     float* __restrict__ out, const float* __restrict__ bias,
                     __half* __restrict__ qfg, __half* __restrict__ kfg,
                     __half* __restrict__ vfg)
{
    extern __shared__ unsigned char smraw[];
    const uint32_t sb = smem_u32(smraw);
    const int tid = threadIdx.x, w = tid >> 5, lane = tid & 31;
    const int b = blockIdx.z & 15, proj = blockIdx.z >> 4;
    const int n0 = blockIdx.x * 128, o0 = blockIdx.y * 128;
    const int wm = w & 3, wn = w >> 2;

    const __half* srcs[2] = {
        A_g + ((size_t)b * 1024 + n0) * 512,
        W_g + (size_t)proj * 512 * 512 + (size_t)o0 * 512 };

    float acc[2][8][4];
#pragma unroll
    for (int t = 0; t < 2; t++)
#pragma unroll
        for (int j = 0; j < 8; j++)
#pragma unroll
            for (int e = 0; e < 4; e++) acc[t][j][e] = 0.f;

    auto load_chunk = [&](int c, uint32_t stage) {
#pragma unroll
        for (int l = 0; l < 4; l++) {
            int flat = tid + l * 256;        // 0..1023
            int arr  = flat >> 9;            // 0=A, 1=B
            int sub  = flat & 511;
            int row  = sub >> 2;
            int seg  = sub & 3;
            uint32_t dst = stage + (uint32_t)arr * 8192u + (uint32_t)row * 64u
                         + (uint32_t)((seg ^ ((row >> 1) & 3)) * 16);
            cp16(dst, srcs[arr] + (size_t)row * 512 + c * 32 + seg * 8);
        }
    };

    const int rl   = lane & 15;
    const int half = lane >> 4;

    auto compute = [&](uint32_t stage) {
#pragma unroll
        for (int kk = 0; kk < 2; kk++) {
            uint32_t a_f[2][4];
            uint32_t b_f[4][4];
#pragma unroll
            for (int t = 0; t < 2; t++) {
                int row = wm * 32 + t * 16 + rl;
                uint32_t seg = (uint32_t)((2 * kk + half) ^ ((row >> 1) & 3));
                ldsm4(a_f[t], stage + (uint32_t)row * 64u + seg * 16u);
            }
#pragma unroll
            for (int g = 0; g < 4; g++) {
                int row = wn * 64 + g * 16 + rl;
                uint32_t seg = (uint32_t)((2 * kk + half) ^ ((row >> 1) & 3));
                ldsm4(b_f[g], stage + 8192u + (uint32_t)row * 64u + seg * 16u);
            }
#pragma unroll
            for (int t = 0; t < 2; t++)
#pragma unroll
                for (int j = 0; j < 8; j++) {
                    int g = j >> 1, jj = j & 1;
                    mma_f16(acc[t][j], a_f[t], b_f[g][jj], b_f[g][jj + 2]);
                }
        }
    };

    load_chunk(0, sb); cp_commit();
    load_chunk(1, sb + GSTAGE); cp_commit();
    for (int c = 0; c < 16; c++) {
        if (c < 15) cp_wait<1>(); else cp_wait<0>();
        __syncthreads();
        if (c + 2 < 16) {
            load_chunk(c + 2, sb + (uint32_t)((c + 2) % 3) * GSTAGE);
            cp_commit();
        }
        compute(sb + (uint32_t)(c % 3) * GSTAGE);
    }
    __syncthreads();

    float* Ds = reinterpret_cast<float*>(smraw);    // [64][132]
    const int grp = lane >> 2, tig = lane & 3;
#pragma unroll
    for (int p = 0; p < 2; p++) {
        if (wn == p) {
#pragma unroll
            for (int t = 0; t < 2; t++)
#pragma unroll
                for (int j = 0; j < 8; j++) {
                    int oc = j * 8 + 2 * tig;
                    int mb = wm * 32 + t * 16 + grp;
                    Ds[oc * 132 + mb]           = acc[t][j][0];
                    Ds[(oc + 1) * 132 + mb]     = acc[t][j][1];
                    Ds[oc * 132 + mb + 8]       = acc[t][j][2];
                    Ds[(oc + 1) * 132 + mb + 8] = acc[t][j][3];
                }
        }
        __syncthreads();
#pragma unroll
        for (int l = 0; l < 8; l++) {
            int idx  = tid + l * 256;
            int row  = idx >> 5;
            int col4 = (idx & 31) * 4;
            float4 v = *reinterpret_cast<float4*>(&Ds[row * 132 + col4]);
            int o = o0 + p * 64 + row;
            if (MODE == 1) {
                float bo = __ldg(&bias[o]);
                v.x += bo; v.y += bo; v.z += bo; v.w += bo;
                *reinterpret_cast<float4*>(
                    &out[(size_t)(b * 512 + o) * 1024 + n0 + col4]) = v;
            } else {
                int hh = o & 7, dd = o >> 3;
                size_t gi = (size_t)((b * 8 + hh) * 64 + dd) * 1024 + n0 + col4;
                __half* dst = (proj == 0) ? qfg : (proj == 1) ? kfg : vfg;
                uint2 ph = make_uint2(packh2(v.x, v.y), packh2(v.z, v.w));
                *reinterpret_cast<uint2*>(&dst[gi]) = ph;
            }
        }
        __syncthreads();
    }
}

// ===========================================================================
// Flash attention v6: Tq=128, 8 warps, 4-stage {K,V} fp16 pipeline, fp16
// single-term S / bias / PV, static-max base-2 softmax, fused mma bias tables.
// ===========================================================================
static constexpr unsigned AT_QF    = 0u;
static constexpr unsigned AT_ST0   = 18432u;
static constexpr unsigned AT_STSZ  = 18432u;
static constexpr unsigned AT_LH    = AT_ST0 + 4u * AT_STSZ;   // 92160
static constexpr unsigned AT_LW    = AT_LH + 32768u;          // 124928
static constexpr unsigned AT_SMEM  = AT_LW + 32768u;          // 157696

__global__ __launch_bounds__(256)
void attn_mma_kernel(const __half* __restrict__ qfg,
                     const __half* __restrict__ kfg,
                     const __half* __restrict__ vfg,
                     const __half* __restrict__ rhf, const __half* __restrict__ rwf,
                     __half* __restrict__ attf)
{
    extern __shared__ unsigned char smraw[];
    const uint32_t sb = smem_u32(smraw);
    const uint32_t Qf = sb + AT_QF;
    __half* Qfp = reinterpret_cast<__half*>(smraw + AT_QF);
    float* Lh = reinterpret_cast<float*>(smraw + AT_LH);
    float* Lw = reinterpret_cast<float*>(smraw + AT_LW);

    const int bh = blockIdx.y, b = bh >> 3, h = bh & 7;
    const int q0 = blockIdx.x * 128;
    const int tid = threadIdx.x, w = tid >> 5, lane = tid & 31;
    const int g = lane >> 2, t = lane & 3;
    const int rl = lane & 15, byt = (lane >> 4) * 16;

    const float SC = 0.18033688f;    // 0.125 * log2(e)

    const __half* qb_g = qfg + (size_t)bh * 64 * 1024;

#pragma unroll
    for (int l = 0; l < 32; l++) {
        int flat = tid + l * 256;
        int d = flat >> 7, i = flat & 127;
        Qfp[i * 72 + d] = qb_g[(size_t)d * 1024 + q0 + i];
    }

#pragma unroll
    for (int l = 0; l < 4; l++) {
        int flat = tid + l * 256;            // 0..1023
        int arr = flat >> 9, sub = flat & 511;
        int r = sub >> 3, seg = sub & 7;
        cp16(sb + AT_ST0 + (uint32_t)arr * 9216u + (uint32_t)r * 144u + (uint32_t)seg * 16u,
             (arr == 0 ? rhf : rwf) + r * 64 + seg * 8);
    }
    cp_commit();
    cp_wait<0>();
    __syncthreads();

    uint32_t qF[4][4];
#pragma unroll
    for (int kk = 0; kk < 4; kk++)
        ldsm4(qF[kk], Qf + (uint32_t)(w * 16 + rl) * 144u + (uint32_t)kk * 32u + byt);

    const int lr0 = w * 16 + g, lr1 = lr0 + 8;
    const int nq0 = q0 + lr0, nq1 = q0 + lr1;
    const int x0 = nq0 >> 5, y0 = nq0 & 31;
    const int x1 = nq1 >> 5, y1 = nq1 & 31;

    // ---- bias tables via mma; stored pre-scaled *SC - 5 ----
    {
        float sl[2][8][4];
#pragma unroll
        for (int tb = 0; tb < 2; tb++)
#pragma unroll
            for (int nb = 0; nb < 8; nb++)
#pragma unroll
                for (int e = 0; e < 4; e++) sl[tb][nb][e] = 0.f;

#pragma unroll
        for (int kk = 0; kk < 4; kk++) {
#pragma unroll
            for (int tb = 0; tb < 2; tb++) {
#pragma unroll
                for (int np = 0; np < 4; np++) {
                    uint32_t radr = sb + AT_ST0 + (uint32_t)tb * 9216u
                                  + (uint32_t)(np * 16 + rl) * 144u + (uint32_t)kk * 32u + byt;
                    uint32_t rF[4];
                    ldsm4(rF, radr);
                    mma_f16(sl[tb][np * 2],     qF[kk], rF[0], rF[2]);
                    mma_f16(sl[tb][np * 2 + 1], qF[kk], rF[1], rF[3]);
                }
            }
        }
#pragma unroll
        for (int nb = 0; nb < 8; nb++) {
            int c0 = nb * 8 + 2 * t;
            Lh[lr0 * 64 + c0]     = sl[0][nb][0] * SC - 5.f;
            Lh[lr0 * 64 + c0 + 1] = sl[0][nb][1] * SC - 5.f;
            Lh[lr1 * 64 + c0]     = sl[0][nb][2] * SC - 5.f;
            Lh[lr1 * 64 + c0 + 1] = sl[0][nb][3] * SC - 5.f;
            Lw[lr0 * 64 + c0]     = sl[1][nb][0] * SC - 5.f;
            Lw[lr0 * 64 + c0 + 1] = sl[1][nb][1] * SC - 5.f;
            Lw[lr1 * 64 + c0]     = sl[1][nb][2] * SC - 5.f;
            Lw[lr1 * 64 + c0 + 1] = sl[1][nb][3] * SC - 5.f;
        }
    }
    __syncthreads();

    auto load_kv = [&](int kt, uint32_t stage) {
#pragma unroll
        for (int l = 0; l < 4; l++) {
            int flat = tid + l * 256;            // 0..1023
            int arr = flat >> 9, sub = flat & 511;
            int d = sub >> 3, seg = sub & 7;
            cp16(stage + (uint32_t)arr * 9216u + (uint32_t)d * 144u + (uint32_t)seg * 16u,
                 (arr == 0 ? kfg : vfg) + ((size_t)bh * 64 + d) * 1024 + kt * 64 + seg * 8);
        }
    };

    float l0 = 0.f, l1 = 0.f;
    float o[8][4];
#pragma unroll
    for (int nd = 0; nd < 8; nd++)
#pragma unroll
        for (int e = 0; e < 4; e++) o[nd][e] = 0.f;

    load_kv(0, sb + AT_ST0); cp_commit();
    load_kv(1, sb + AT_ST0 + AT_STSZ); cp_commit();
    load_kv(2, sb + AT_ST0 + 2u * AT_STSZ); cp_commit();

    for (int kt = 0; kt < 16; kt++) {
        if (kt <= 13)      cp_wait<2>();
        else if (kt == 14) cp_wait<1>();
        else               cp_wait<0>();
        __syncthreads();
        if (kt + 3 < 16) {
            load_kv(kt + 3, sb + AT_ST0 + (uint32_t)((kt + 3) & 3) * AT_STSZ);
            cp_commit();
        }
        const uint32_t stage = sb + AT_ST0 + (uint32_t)(kt & 3) * AT_STSZ;
        const uint32_t Kb = stage, Vb = stage + 9216u;

        float s[8][4];
#pragma unroll
        for (int nb = 0; nb < 8; nb++)
#pragma unroll
            for (int e = 0; e < 4; e++) s[nb][e] = 0.f;

#pragma unroll
        for (int kk = 0; kk < 4; kk++) {
#pragma unroll
            for (int np = 0; np < 4; np++) {
                uint32_t kadr = (uint32_t)(kk * 16 + rl) * 144u
                              + (uint32_t)(np * 16 + (lane >> 4) * 8) * 2u;
                uint32_t kF[4];
                ldsm4t(kF, Kb + kadr);
                mma_f16(s[2 * np],     qF[kk], kF[0], kF[1]);
                mma_f16(s[2 * np + 1], qF[kk], kF[2], kF[3]);
            }
        }

        const float* pLh0 = &Lh[lr0 * 64 + kt * 2 + 31 - x0];
        const float* pLh1 = &Lh[lr1 * 64 + kt * 2 + 31 - x1];
        const float lh00 = pLh0[0], lh01 = pLh0[1];
        const float lh10 = pLh1[0], lh11 = pLh1[1];
        const float* pLw0 = &Lw[lr0 * 64 + 31 - y0 + 2 * t];
        const float* pLw1 = &Lw[lr1 * 64 + 31 - y1 + 2 * t];
        float bw0[8], bw1[8];
#pragma unroll
        for (int c = 0; c < 4; c++) {
            bw0[2 * c]     = pLw0[c * 8];
            bw0[2 * c + 1] = pLw0[c * 8 + 1];
            bw1[2 * c]     = pLw1[c * 8];
            bw1[2 * c + 1] = pLw1[c * 8 + 1];
        }

        float rs0 = 0.f, rs1 = 0.f;
#pragma unroll
        for (int nb = 0; nb < 8; nb++) {
            float lv0 = (nb < 4) ? lh00 : lh01;
            float lv1 = (nb < 4) ? lh10 : lh11;
            int ci = (nb & 3) * 2;
            s[nb][0] = exp2f(fmaf(s[nb][0], SC, lv0 + bw0[ci]));
            s[nb][1] = exp2f(fmaf(s[nb][1], SC, lv0 + bw0[ci + 1]));
            s[nb][2] = exp2f(fmaf(s[nb][2], SC, lv1 + bw1[ci]));
            s[nb][3] = exp2f(fmaf(s[nb][3], SC, lv1 + bw1[ci + 1]));
            rs0 += s[nb][0] + s[nb][1];
            rs1 += s[nb][2] + s[nb][3];
        }
        l0 += rs0;
        l1 += rs1;

#pragma unroll
        for (int kk = 0; kk < 4; kk++) {
            float* p0 = s[2 * kk];
            float* p1 = s[2 * kk + 1];
            uint32_t pF[4] = { packh2(p0[0], p0[1]), packh2(p0[2], p0[3]),
                               packh2(p1[0], p1[1]), packh2(p1[2], p1[3]) };
#pragma unroll
            for (int nd = 0; nd < 4; nd++) {
                uint32_t vadr = (uint32_t)(nd * 16 + rl) * 144u + (uint32_t)kk * 32u + byt;
                uint32_t vF[4];
                ldsm4(vF, Vb + vadr);
                mma_f16(o[2 * nd],     pF, vF[0], vF[2]);
                mma_f16(o[2 * nd + 1], pF, vF[1], vF[3]);
            }
        }
    }

    l0 += __shfl_xor_sync(0xffffffffu, l0, 1);
    l0 += __shfl_xor_sync(0xffffffffu, l0, 2);
    l1 += __shfl_xor_sync(0xffffffffu, l1, 1);
    l1 += __shfl_xor_sync(0xffffffffu, l1, 2);

    const float inv0 = 1.0f / l0, inv1 = 1.0f / l1;
    const size_t base0 = ((size_t)(b * 1024 + nq0)) * 512 + h * 64;
    const size_t base1 = ((size_t)(b * 1024 + nq1)) * 512 + h * 64;
#pragma unroll
    for (int nd = 0; nd < 8; nd++) {
        int d = nd * 8 + 2 * t;
        *reinterpret_cast<uint32_t*>(&attf[base0 + d]) =
            packh2(o[nd][0] * inv0, o[nd][1] * inv0);
        *reinterpret_cast<uint32_t*>(&attf[base1 + d]) =
            packh2(o[nd][2] * inv1, o[nd][3] * inv1);
    }
}

// ===========================================================================
// Launch
// ===========================================================================
extern "C" void kernel_launch(void* const* d_in, const int* in_sizes, int n_in,
                              void* d_out, int out_size)
{
    const float* x     = (const float*)d_in[0];
    const float* w_q   = (const float*)d_in[1];
    const float* w_k   = (const float*)d_in[2];
    const float* w_v   = (const float*)d_in[3];
    const float* w_o   = (const float*)d_in[4];
    const float* b_o   = (const float*)d_in[5];
    const float* rel_h = (const float*)d_in[6];
    const float* rel_w = (const float*)d_in[7];
    float* out = (float*)d_out;

    __half *pqf, *pkf, *pvf, *pxtf, *pattf, *pwf, *prhf, *prwf;
    cudaGetSymbolAddress((void**)&pqf,   g_qf);
    cudaGetSymbolAddress((void**)&pkf,   g_kf);
    cudaGetSymbolAddress((void**)&pvf,   g_vf);
    cudaGetSymbolAddress((void**)&pxtf,  g_xtf);
    cudaGetSymbolAddress((void**)&pattf, g_attf);
    cudaGetSymbolAddress((void**)&pwf,   g_wf);
    cudaGetSymbolAddress((void**)&prhf,  g_rhf);
    cudaGetSymbolAddress((void**)&prwf,  g_rwf);

    cudaFuncSetAttribute(gemm_mma_kernel<0>, cudaFuncAttributeMaxDynamicSharedMemorySize,
                         (int)GEMM_SMEM);
    cudaFuncSetAttribute(gemm_mma_kernel<1>, cudaFuncAttributeMaxDynamicSharedMemorySize,
                         (int)GEMM_SMEM);
    cudaFuncSetAttribute(attn_mma_kernel, cudaFuncAttributeMaxDynamicSharedMemorySize,
                         (int)AT_SMEM);

    transpose_kernel<<<dim3(32, 16, 16), 256>>>(x, pxtf);
    wconv_kernel<<<4096, 256>>>(w_q, w_k, w_v, w_o, pwf);
    rel_conv_kernel<<<32, 256>>>(rel_h, rel_w, prhf, prwf);

    // Combined QKV projection: z = proj*16 + b  (proj 0,1,2 over g_wf slots)
    gemm_mma_kernel<0><<<dim3(8, 4, 48), 256, GEMM_SMEM>>>(
        pxtf, pwf, nullptr, nullptr, pqf, pkf, pvf);

    attn_mma_kernel<<<dim3(8, 128), 256, AT_SMEM>>>(
        pqf, pkf, pvf, prhf, prwf, pattf);

    // Final projection: z = 16 (proj=0), weight base passed as slot 3 directly
    gemm_mma_kernel<1><<<dim3(8, 4, 16), 256, GEMM_SMEM>>>(
        pattf, pwf + (size_t)3 * 512 * 512, out, b_o, nullptr, nullptr, nullptr);
}